// round 1
// baseline (speedup 1.0000x reference)
#include <cuda_runtime.h>

#define NB 8
#define NH 8
#define NT 1024
#define CD 256
#define KD 16
#define HD 32
#define HQ 512
#define ATT_SCALE 0.25f
#define EPS 0.001f

// Scratch (static device globals; no allocations allowed)
__device__ float g_Q[NB*NH*NT*KD];     // q * ATT_SCALE, [b][h][n][16]
__device__ float g_Kd[NB*NH*NT*KD];    // [b][h][n][16]
__device__ float g_V[NB*NT*CD];        // NHWC, c = h*32+d
__device__ float g_rmax[NB*NH*NT];
__device__ float g_rinv[NB*NH*NT];
__device__ float g_mid[NB*NT*CD];      // attn out (scrambled layout) + pe

// ---------------------------------------------------------------------------
// Kernel 1: QKV GEMM [8192x256]x[256x512], BN folded, routed into Q/K/V
// ---------------------------------------------------------------------------
__global__ __launch_bounds__(256) void qkv_kernel(
    const float* __restrict__ X, const float* __restrict__ W,
    const float* __restrict__ gamma, const float* __restrict__ beta,
    const float* __restrict__ mean, const float* __restrict__ var)
{
    __shared__ float As[16][68];
    __shared__ float Bs[16][68];
    const int tid = threadIdx.x;
    const int tx = tid & 15, ty = tid >> 4;
    const int row0 = blockIdx.x * 64;
    const int col0 = blockIdx.y * 64;
    const int arow = tid >> 2, ak4 = (tid & 3) << 2;
    const int bk = tid >> 4, bc4 = (tid & 15) << 2;

    float acc[4][4];
    #pragma unroll
    for (int i = 0; i < 4; i++)
        #pragma unroll
        for (int j = 0; j < 4; j++) acc[i][j] = 0.f;

    for (int k0 = 0; k0 < CD; k0 += 16) {
        float4 a = *(const float4*)(X + (row0 + arow) * CD + k0 + ak4);
        As[ak4+0][arow] = a.x; As[ak4+1][arow] = a.y;
        As[ak4+2][arow] = a.z; As[ak4+3][arow] = a.w;
        *(float4*)(&Bs[bk][bc4]) = *(const float4*)(W + (k0 + bk) * HQ + col0 + bc4);
        __syncthreads();
        #pragma unroll
        for (int kk = 0; kk < 16; kk++) {
            float4 av = *(float4*)(&As[kk][ty << 2]);
            float4 bv = *(float4*)(&Bs[kk][tx << 2]);
            float ar[4] = {av.x, av.y, av.z, av.w};
            float br[4] = {bv.x, bv.y, bv.z, bv.w};
            #pragma unroll
            for (int i = 0; i < 4; i++)
                #pragma unroll
                for (int j = 0; j < 4; j++) acc[i][j] += ar[i] * br[j];
        }
        __syncthreads();
    }

    #pragma unroll
    for (int j = 0; j < 4; j++) {
        int co = col0 + (tx << 2) + j;
        float sc = gamma[co] * rsqrtf(var[co] + EPS);
        float bi = beta[co] - mean[co] * sc;
        int h = co >> 6, rr = co & 63;
        #pragma unroll
        for (int i = 0; i < 4; i++) {
            int gr = row0 + (ty << 2) + i;
            int b = gr >> 10, n = gr & 1023;
            float v = acc[i][j] * sc + bi;
            if (rr < KD)           g_Q [((b*NH + h)*NT + n)*KD + rr]       = v * ATT_SCALE;
            else if (rr < 2*KD)    g_Kd[((b*NH + h)*NT + n)*KD + rr - KD]  = v;
            else                   g_V [(b*NT + n)*CD + h*HD + rr - 2*KD]  = v;
        }
    }
}

// ---------------------------------------------------------------------------
// Kernel 2: per-row softmax stats (max, 1/sum of exp) for S = QK^T
// Block: (b,h) x 64 rows; 256 thr = 16 row-groups (4 rows each) x 16 lanes
// ---------------------------------------------------------------------------
__global__ __launch_bounds__(256) void rowstats_kernel()
{
    __shared__ float ks[128][20];
    const int bh = blockIdx.y;
    const int tid = threadIdx.x;
    const int lane = tid & 15, rg = tid >> 4;
    const int nb = blockIdx.x * 64 + rg * 4;

    float q[4][16];
    #pragma unroll
    for (int r = 0; r < 4; r++)
        #pragma unroll
        for (int j4 = 0; j4 < 4; j4++) {
            float4 t = *(const float4*)(g_Q + (bh*NT + nb + r)*KD + j4*4);
            q[r][j4*4+0] = t.x; q[r][j4*4+1] = t.y;
            q[r][j4*4+2] = t.z; q[r][j4*4+3] = t.w;
        }

    float mx[4], sm[4];
    #pragma unroll
    for (int r = 0; r < 4; r++) { mx[r] = -1e30f; sm[r] = 0.f; }

    for (int mc = 0; mc < NT; mc += 128) {
        for (int l = tid; l < 512; l += 256) {
            int m = l >> 2, j4 = (l & 3) << 2;
            *(float4*)(&ks[m][j4]) = *(const float4*)(g_Kd + (bh*NT + mc + m)*KD + j4);
        }
        __syncthreads();
        #pragma unroll
        for (int i2 = 0; i2 < 8; i2++) {
            int m = lane + (i2 << 4);
            float kv[16];
            #pragma unroll
            for (int j4 = 0; j4 < 4; j4++) {
                float4 t = *(float4*)(&ks[m][j4*4]);
                kv[j4*4+0] = t.x; kv[j4*4+1] = t.y; kv[j4*4+2] = t.z; kv[j4*4+3] = t.w;
            }
            #pragma unroll
            for (int r = 0; r < 4; r++) {
                float s = 0.f;
                #pragma unroll
                for (int jj = 0; jj < 16; jj++) s += q[r][jj] * kv[jj];
                if (s > mx[r]) { sm[r] = sm[r] * __expf(mx[r] - s) + 1.0f; mx[r] = s; }
                else           { sm[r] += __expf(s - mx[r]); }
            }
        }
        __syncthreads();
    }

    #pragma unroll
    for (int off = 8; off; off >>= 1) {
        #pragma unroll
        for (int r = 0; r < 4; r++) {
            float om = __shfl_xor_sync(0xffffffffu, mx[r], off);
            float os = __shfl_xor_sync(0xffffffffu, sm[r], off);
            float nm = fmaxf(mx[r], om);
            sm[r] = sm[r] * __expf(mx[r] - nm) + os * __expf(om - nm);
            mx[r] = nm;
        }
    }
    if (lane == 0) {
        #pragma unroll
        for (int r = 0; r < 4; r++) {
            int n = nb + r;
            g_rmax[bh*NT + n] = mx[r];
            g_rinv[bh*NT + n] = 1.0f / sm[r];
        }
    }
}

// ---------------------------------------------------------------------------
// Kernel 3: O[m,d] = sum_n P[n,m] * v[n,d], written in the scrambled layout.
// Block: (b,h) x 128 m-values. 256 thr = 32 m-groups (4 m) x 8 d-groups (4 d).
// K for owned m's lives in registers. P staged through smem per 64-n chunk.
// ---------------------------------------------------------------------------
__global__ __launch_bounds__(256) void pv_kernel()
{
    __shared__ float qs[64][20];
    __shared__ float vs[64][32];
    __shared__ float ps[64][136];
    __shared__ float mxs[64];
    __shared__ float ris[64];

    const int bh = blockIdx.y;
    const int b = bh >> 3, h = bh & 7;
    const int m0 = blockIdx.x * 128;
    const int tid = threadIdx.x;
    const int mg = tid >> 3;   // 0..31 -> owns m = m0 + 4*mg + mm
    const int dg = tid & 7;    // 0..7  -> owns d = 4*dg + dd

    float kreg[4][16];
    #pragma unroll
    for (int mm = 0; mm < 4; mm++) {
        int m = m0 + (mg << 2) + mm;
        #pragma unroll
        for (int j4 = 0; j4 < 4; j4++) {
            float4 t = *(const float4*)(g_Kd + (bh*NT + m)*KD + j4*4);
            kreg[mm][j4*4+0] = t.x; kreg[mm][j4*4+1] = t.y;
            kreg[mm][j4*4+2] = t.z; kreg[mm][j4*4+3] = t.w;
        }
    }

    float acc[4][4];   // [mm][dd]
    #pragma unroll
    for (int i = 0; i < 4; i++)
        #pragma unroll
        for (int j = 0; j < 4; j++) acc[i][j] = 0.f;

    for (int nc = 0; nc < NT; nc += 64) {
        {   // load Q chunk: 64x16 = 256 float4
            int n = tid >> 2, j4 = (tid & 3) << 2;
            *(float4*)(&qs[n][j4]) = *(const float4*)(g_Q + (bh*NT + nc + n)*KD + j4);
        }
        for (int l = tid; l < 512; l += 256) {   // V chunk: 64x32
            int n = l >> 3, j4 = (l & 7) << 2;
            *(float4*)(&vs[n][j4]) = *(const float4*)(g_V + (b*NT + nc + n)*CD + h*HD + j4);
        }
        if (tid < 64) {
            mxs[tid] = g_rmax[bh*NT + nc + tid];
            ris[tid] = g_rinv[bh*NT + nc + tid];
        }
        __syncthreads();

        // Phase A: p[n][m] for this thread's 4 m's, 8 n's
        #pragma unroll
        for (int i2 = 0; i2 < 8; i2++) {
            int n = dg + (i2 << 3);
            float qv[16];
            #pragma unroll
            for (int j4 = 0; j4 < 4; j4++) {
                float4 t = *(float4*)(&qs[n][j4*4]);
                qv[j4*4+0] = t.x; qv[j4*4+1] = t.y; qv[j4*4+2] = t.z; qv[j4*4+3] = t.w;
            }
            float m_ = mxs[n], ri = ris[n];
            float p[4];
            #pragma unroll
            for (int mm = 0; mm < 4; mm++) {
                float s = 0.f;
                #pragma unroll
                for (int jj = 0; jj < 16; jj++) s += qv[jj] * kreg[mm][jj];
                p[mm] = __expf(s - m_) * ri;
            }
            *(float4*)(&ps[n][mg << 2]) = make_float4(p[0], p[1], p[2], p[3]);
        }
        __syncthreads();

        // Phase B: acc[mm][dd] += p[n][mm] * v[n][dd]
        #pragma unroll 4
        for (int n = 0; n < 64; n++) {
            float4 pv = *(float4*)(&ps[n][mg << 2]);
            float4 vv = *(float4*)(&vs[n][dg << 2]);
            float pr[4] = {pv.x, pv.y, pv.z, pv.w};
            float vr[4] = {vv.x, vv.y, vv.z, vv.w};
            #pragma unroll
            for (int mm = 0; mm < 4; mm++)
                #pragma unroll
                for (int dd = 0; dd < 4; dd++) acc[mm][dd] += pr[mm] * vr[dd];
        }
        __syncthreads();
    }

    // Scrambled write: mid[b][hs=d][ws=4h+(m>>8)][c=m&255]
    const int w = (h << 2) + (m0 >> 8);
    const int cbase = (m0 & 255) + (mg << 2);
    #pragma unroll
    for (int dd = 0; dd < 4; dd++) {
        int d = (dg << 2) + dd;
        float4 o = make_float4(acc[0][dd], acc[1][dd], acc[2][dd], acc[3][dd]);
        *(float4*)(&g_mid[((b*32 + d)*32 + w)*CD + cbase]) = o;
    }
}

// ---------------------------------------------------------------------------
// Kernel 4: depthwise 3x3 PE conv on V (NHWC) + BN, added into g_mid
// ---------------------------------------------------------------------------
__global__ __launch_bounds__(256) void pe_kernel(
    const float* __restrict__ pw, const float* __restrict__ gamma,
    const float* __restrict__ beta, const float* __restrict__ mean,
    const float* __restrict__ var)
{
    const int c = threadIdx.x;
    const int bij = blockIdx.x;
    const int j = bij & 31, i = (bij >> 5) & 31, b = bij >> 10;
    float accv = 0.f;
    #pragma unroll
    for (int kh = 0; kh < 3; kh++) {
        int ii = i + kh - 1;
        if (ii < 0 || ii > 31) continue;
        #pragma unroll
        for (int kw = 0; kw < 3; kw++) {
            int jj = j + kw - 1;
            if (jj < 0 || jj > 31) continue;
            accv += g_V[(b*NT + ii*32 + jj)*CD + c] * pw[(kh*3 + kw)*CD + c];
        }
    }
    float sc = gamma[c] * rsqrtf(var[c] + EPS);
    float bi = beta[c] - mean[c] * sc;
    g_mid[bij*CD + c] += accv * sc + bi;
}

// ---------------------------------------------------------------------------
// Kernel 5: Proj GEMM [8192x256]x[256x256] + BN -> d_out
// ---------------------------------------------------------------------------
__global__ __launch_bounds__(256) void proj_kernel(
    const float* __restrict__ W, const float* __restrict__ gamma,
    const float* __restrict__ beta, const float* __restrict__ mean,
    const float* __restrict__ var, float* __restrict__ out)
{
    __shared__ float As[16][68];
    __shared__ float Bs[16][68];
    const int tid = threadIdx.x;
    const int tx = tid & 15, ty = tid >> 4;
    const int row0 = blockIdx.x * 64;
    const int col0 = blockIdx.y * 64;
    const int arow = tid >> 2, ak4 = (tid & 3) << 2;
    const int bk = tid >> 4, bc4 = (tid & 15) << 2;

    float acc[4][4];
    #pragma unroll
    for (int i = 0; i < 4; i++)
        #pragma unroll
        for (int j = 0; j < 4; j++) acc[i][j] = 0.f;

    for (int k0 = 0; k0 < CD; k0 += 16) {
        float4 a = *(const float4*)(g_mid + (row0 + arow) * CD + k0 + ak4);
        As[ak4+0][arow] = a.x; As[ak4+1][arow] = a.y;
        As[ak4+2][arow] = a.z; As[ak4+3][arow] = a.w;
        *(float4*)(&Bs[bk][bc4]) = *(const float4*)(W + (k0 + bk) * CD + col0 + bc4);
        __syncthreads();
        #pragma unroll
        for (int kk = 0; kk < 16; kk++) {
            float4 av = *(float4*)(&As[kk][ty << 2]);
            float4 bv = *(float4*)(&Bs[kk][tx << 2]);
            float ar[4] = {av.x, av.y, av.z, av.w};
            float br[4] = {bv.x, bv.y, bv.z, bv.w};
            #pragma unroll
            for (int i = 0; i < 4; i++)
                #pragma unroll
                for (int j = 0; j < 4; j++) acc[i][j] += ar[i] * br[j];
        }
        __syncthreads();
    }

    #pragma unroll
    for (int j = 0; j < 4; j++) {
        int co = col0 + (tx << 2) + j;
        float sc = gamma[co] * rsqrtf(var[co] + EPS);
        float bi = beta[co] - mean[co] * sc;
        #pragma unroll
        for (int i = 0; i < 4; i++) {
            int gr = row0 + (ty << 2) + i;
            out[gr*CD + co] = acc[i][j] * sc + bi;
        }
    }
}

// ---------------------------------------------------------------------------
extern "C" void kernel_launch(void* const* d_in, const int* in_sizes, int n_in,
                              void* d_out, int out_size)
{
    const float* inputs   = (const float*)d_in[0];
    const float* qkv_w    = (const float*)d_in[1];
    const float* qkv_g    = (const float*)d_in[2];
    const float* qkv_b    = (const float*)d_in[3];
    const float* qkv_m    = (const float*)d_in[4];
    const float* qkv_v    = (const float*)d_in[5];
    const float* pe_w     = (const float*)d_in[6];
    const float* pe_g     = (const float*)d_in[7];
    const float* pe_b     = (const float*)d_in[8];
    const float* pe_m     = (const float*)d_in[9];
    const float* pe_v     = (const float*)d_in[10];
    const float* proj_w   = (const float*)d_in[11];
    const float* proj_g   = (const float*)d_in[12];
    const float* proj_b   = (const float*)d_in[13];
    const float* proj_m   = (const float*)d_in[14];
    const float* proj_v   = (const float*)d_in[15];
    float* out = (float*)d_out;

    qkv_kernel<<<dim3(128, 8), 256>>>(inputs, qkv_w, qkv_g, qkv_b, qkv_m, qkv_v);
    rowstats_kernel<<<dim3(16, 64), 256>>>();
    pv_kernel<<<dim3(8, 64), 256>>>();
    pe_kernel<<<8192, 256>>>(pe_w, pe_g, pe_b, pe_m, pe_v);
    proj_kernel<<<dim3(128, 4), 256>>>(proj_w, proj_g, proj_b, proj_m, proj_v, out);
}

// round 2
// speedup vs baseline: 1.0829x; 1.0829x over previous
#include <cuda_runtime.h>

#define NB 8
#define NH 8
#define NT 1024
#define CD 256
#define KD 16
#define HD 32
#define HQ 512
#define ATT_SCALE 0.25f
#define EPS 0.001f

typedef unsigned long long u64;

// fma.rn.f32x2: 2 independent fp32 FMAs per instruction (Blackwell packed fp32).
__device__ __forceinline__ u64 pk2(float lo, float hi) {
    u64 r; asm("mov.b64 %0,{%1,%2};" : "=l"(r) : "f"(lo), "f"(hi)); return r;
}
__device__ __forceinline__ float2 upk2(u64 v) {
    float2 f; asm("mov.b64 {%0,%1},%2;" : "=f"(f.x), "=f"(f.y) : "l"(v)); return f;
}
__device__ __forceinline__ u64 ffma2(u64 a, u64 b, u64 c) {
    u64 d; asm("fma.rn.f32x2 %0,%1,%2,%3;" : "=l"(d) : "l"(a), "l"(b), "l"(c)); return d;
}

// Scratch (static device globals; no allocations allowed)
__device__ float g_Q[NB*NH*NT*KD];     // q * ATT_SCALE, [b][h][n][16]
__device__ float g_Kd[NB*NH*NT*KD];    // [b][h][n][16]
__device__ float g_V[NB*NT*CD];        // NHWC, c = h*32+d
__device__ float g_rmax[NB*NH*NT];
__device__ float g_rinv[NB*NH*NT];
__device__ float g_mid[NB*NT*CD];      // attn out (scrambled layout) + pe

// ---------------------------------------------------------------------------
// Kernel 1: QKV GEMM [8192x256]x[256x512], BN folded, routed into Q/K/V
// ---------------------------------------------------------------------------
__global__ __launch_bounds__(256) void qkv_kernel(
    const float* __restrict__ X, const float* __restrict__ W,
    const float* __restrict__ gamma, const float* __restrict__ beta,
    const float* __restrict__ mean, const float* __restrict__ var)
{
    __shared__ float As[16][68];
    __shared__ float Bs[16][68];
    const int tid = threadIdx.x;
    const int tx = tid & 15, ty = tid >> 4;
    const int row0 = blockIdx.x * 64;
    const int col0 = blockIdx.y * 64;
    const int arow = tid >> 2, ak4 = (tid & 3) << 2;
    const int bk = tid >> 4, bc4 = (tid & 15) << 2;

    u64 acc2[4][2];
    #pragma unroll
    for (int i = 0; i < 4; i++) { acc2[i][0] = 0ull; acc2[i][1] = 0ull; }

    for (int k0 = 0; k0 < CD; k0 += 16) {
        float4 a = *(const float4*)(X + (row0 + arow) * CD + k0 + ak4);
        As[ak4+0][arow] = a.x; As[ak4+1][arow] = a.y;
        As[ak4+2][arow] = a.z; As[ak4+3][arow] = a.w;
        *(float4*)(&Bs[bk][bc4]) = *(const float4*)(W + (k0 + bk) * HQ + col0 + bc4);
        __syncthreads();
        #pragma unroll
        for (int kk = 0; kk < 16; kk++) {
            float4 av = *(float4*)(&As[kk][ty << 2]);
            float4 bv = *(float4*)(&Bs[kk][tx << 2]);
            u64 b01 = pk2(bv.x, bv.y), b23 = pk2(bv.z, bv.w);
            float ar[4] = {av.x, av.y, av.z, av.w};
            #pragma unroll
            for (int i = 0; i < 4; i++) {
                u64 ai = pk2(ar[i], ar[i]);
                acc2[i][0] = ffma2(ai, b01, acc2[i][0]);
                acc2[i][1] = ffma2(ai, b23, acc2[i][1]);
            }
        }
        __syncthreads();
    }

    float acc[4][4];
    #pragma unroll
    for (int i = 0; i < 4; i++) {
        float2 c0 = upk2(acc2[i][0]), c1 = upk2(acc2[i][1]);
        acc[i][0] = c0.x; acc[i][1] = c0.y; acc[i][2] = c1.x; acc[i][3] = c1.y;
    }

    #pragma unroll
    for (int j = 0; j < 4; j++) {
        int co = col0 + (tx << 2) + j;
        float sc = gamma[co] * rsqrtf(var[co] + EPS);
        float bi = beta[co] - mean[co] * sc;
        int h = co >> 6, rr = co & 63;
        #pragma unroll
        for (int i = 0; i < 4; i++) {
            int gr = row0 + (ty << 2) + i;
            int b = gr >> 10, n = gr & 1023;
            float v = acc[i][j] * sc + bi;
            if (rr < KD)           g_Q [((b*NH + h)*NT + n)*KD + rr]       = v * ATT_SCALE;
            else if (rr < 2*KD)    g_Kd[((b*NH + h)*NT + n)*KD + rr - KD]  = v;
            else                   g_V [(b*NT + n)*CD + h*HD + rr - 2*KD]  = v;
        }
    }
}

// ---------------------------------------------------------------------------
// Kernel 2: per-row softmax stats (max, 1/sum of exp) for S = QK^T
// ---------------------------------------------------------------------------
__global__ __launch_bounds__(256) void rowstats_kernel()
{
    __shared__ float ks[128][20];
    const int bh = blockIdx.y;
    const int tid = threadIdx.x;
    const int lane = tid & 15, rg = tid >> 4;
    const int nb = blockIdx.x * 64 + rg * 4;

    u64 q2[4][8];
    #pragma unroll
    for (int r = 0; r < 4; r++)
        #pragma unroll
        for (int j4 = 0; j4 < 4; j4++) {
            float4 t = *(const float4*)(g_Q + (bh*NT + nb + r)*KD + j4*4);
            q2[r][j4*2]   = pk2(t.x, t.y);
            q2[r][j4*2+1] = pk2(t.z, t.w);
        }

    float mx[4], sm[4];
    #pragma unroll
    for (int r = 0; r < 4; r++) { mx[r] = -1e30f; sm[r] = 0.f; }

    for (int mc = 0; mc < NT; mc += 128) {
        for (int l = tid; l < 512; l += 256) {
            int m = l >> 2, j4 = (l & 3) << 2;
            *(float4*)(&ks[m][j4]) = *(const float4*)(g_Kd + (bh*NT + mc + m)*KD + j4);
        }
        __syncthreads();
        #pragma unroll
        for (int i2 = 0; i2 < 8; i2++) {
            int m = lane + (i2 << 4);
            u64 kv2[8];
            #pragma unroll
            for (int j4 = 0; j4 < 4; j4++) {
                float4 t = *(float4*)(&ks[m][j4*4]);
                kv2[j4*2]   = pk2(t.x, t.y);
                kv2[j4*2+1] = pk2(t.z, t.w);
            }
            #pragma unroll
            for (int r = 0; r < 4; r++) {
                u64 s2 = 0ull;
                #pragma unroll
                for (int jj = 0; jj < 8; jj++) s2 = ffma2(q2[r][jj], kv2[jj], s2);
                float2 sf = upk2(s2);
                float s = sf.x + sf.y;
                if (s > mx[r]) { sm[r] = sm[r] * __expf(mx[r] - s) + 1.0f; mx[r] = s; }
                else           { sm[r] += __expf(s - mx[r]); }
            }
        }
        __syncthreads();
    }

    #pragma unroll
    for (int off = 8; off; off >>= 1) {
        #pragma unroll
        for (int r = 0; r < 4; r++) {
            float om = __shfl_xor_sync(0xffffffffu, mx[r], off);
            float os = __shfl_xor_sync(0xffffffffu, sm[r], off);
            float nm = fmaxf(mx[r], om);
            sm[r] = sm[r] * __expf(mx[r] - nm) + os * __expf(om - nm);
            mx[r] = nm;
        }
    }
    if (lane == 0) {
        #pragma unroll
        for (int r = 0; r < 4; r++) {
            int n = nb + r;
            g_rmax[bh*NT + n] = mx[r];
            g_rinv[bh*NT + n] = 1.0f / sm[r];
        }
    }
}

// ---------------------------------------------------------------------------
// Kernel 3: O[m,d] = sum_n P[n,m] * v[n,d], scrambled-layout output.
// ---------------------------------------------------------------------------
__global__ __launch_bounds__(256) void pv_kernel()
{
    __shared__ float qs[64][20];
    __shared__ float vs[64][32];
    __shared__ float ps[64][136];
    __shared__ float mxs[64];
    __shared__ float ris[64];

    const int bh = blockIdx.y;
    const int b = bh >> 3, h = bh & 7;
    const int m0 = blockIdx.x * 128;
    const int tid = threadIdx.x;
    const int mg = tid >> 3;   // owns m = m0 + 4*mg + mm
    const int dg = tid & 7;    // owns d = 4*dg + dd

    u64 kreg2[4][8];
    #pragma unroll
    for (int mm = 0; mm < 4; mm++) {
        int m = m0 + (mg << 2) + mm;
        #pragma unroll
        for (int j4 = 0; j4 < 4; j4++) {
            float4 t = *(const float4*)(g_Kd + (bh*NT + m)*KD + j4*4);
            kreg2[mm][j4*2]   = pk2(t.x, t.y);
            kreg2[mm][j4*2+1] = pk2(t.z, t.w);
        }
    }

    u64 acc2[4][2];   // [mm][d-pair]
    #pragma unroll
    for (int i = 0; i < 4; i++) { acc2[i][0] = 0ull; acc2[i][1] = 0ull; }

    for (int nc = 0; nc < NT; nc += 64) {
        {
            int n = tid >> 2, j4 = (tid & 3) << 2;
            *(float4*)(&qs[n][j4]) = *(const float4*)(g_Q + (bh*NT + nc + n)*KD + j4);
        }
        for (int l = tid; l < 512; l += 256) {
            int n = l >> 3, j4 = (l & 7) << 2;
            *(float4*)(&vs[n][j4]) = *(const float4*)(g_V + (b*NT + nc + n)*CD + h*HD + j4);
        }
        if (tid < 64) {
            mxs[tid] = g_rmax[bh*NT + nc + tid];
            ris[tid] = g_rinv[bh*NT + nc + tid];
        }
        __syncthreads();

        // Phase A: p[n][m] for this thread's 4 m's, 8 n's
        #pragma unroll
        for (int i2 = 0; i2 < 8; i2++) {
            int n = dg + (i2 << 3);
            u64 qv2[8];
            #pragma unroll
            for (int j4 = 0; j4 < 4; j4++) {
                float4 t = *(float4*)(&qs[n][j4*4]);
                qv2[j4*2]   = pk2(t.x, t.y);
                qv2[j4*2+1] = pk2(t.z, t.w);
            }
            float m_ = mxs[n], ri = ris[n];
            float p[4];
            #pragma unroll
            for (int mm = 0; mm < 4; mm++) {
                u64 s2 = 0ull;
                #pragma unroll
                for (int jj = 0; jj < 8; jj++) s2 = ffma2(qv2[jj], kreg2[mm][jj], s2);
                float2 sf = upk2(s2);
                p[mm] = __expf(sf.x + sf.y - m_) * ri;
            }
            *(float4*)(&ps[n][mg << 2]) = make_float4(p[0], p[1], p[2], p[3]);
        }
        __syncthreads();

        // Phase B: acc[mm][dd] += p[n][mm] * v[n][dd]
        #pragma unroll 4
        for (int n = 0; n < 64; n++) {
            float4 pv = *(float4*)(&ps[n][mg << 2]);
            float4 vv = *(float4*)(&vs[n][dg << 2]);
            u64 v01 = pk2(vv.x, vv.y), v23 = pk2(vv.z, vv.w);
            float pr[4] = {pv.x, pv.y, pv.z, pv.w};
            #pragma unroll
            for (int mm = 0; mm < 4; mm++) {
                u64 pb = pk2(pr[mm], pr[mm]);
                acc2[mm][0] = ffma2(pb, v01, acc2[mm][0]);
                acc2[mm][1] = ffma2(pb, v23, acc2[mm][1]);
            }
        }
        __syncthreads();
    }

    float acc[4][4];
    #pragma unroll
    for (int mm = 0; mm < 4; mm++) {
        float2 c0 = upk2(acc2[mm][0]), c1 = upk2(acc2[mm][1]);
        acc[mm][0] = c0.x; acc[mm][1] = c0.y; acc[mm][2] = c1.x; acc[mm][3] = c1.y;
    }

    // Scrambled write: mid[b][hs=d][ws=4h+(m>>8)][c=m&255]
    const int w = (h << 2) + (m0 >> 8);
    const int cbase = (m0 & 255) + (mg << 2);
    #pragma unroll
    for (int dd = 0; dd < 4; dd++) {
        int d = (dg << 2) + dd;
        float4 o = make_float4(acc[0][dd], acc[1][dd], acc[2][dd], acc[3][dd]);
        *(float4*)(&g_mid[((b*32 + d)*32 + w)*CD + cbase]) = o;
    }
}

// ---------------------------------------------------------------------------
// Kernel 4: depthwise 3x3 PE conv on V (NHWC) + BN, added into g_mid
// ---------------------------------------------------------------------------
__global__ __launch_bounds__(256) void pe_kernel(
    const float* __restrict__ pw, const float* __restrict__ gamma,
    const float* __restrict__ beta, const float* __restrict__ mean,
    const float* __restrict__ var)
{
    const int c = threadIdx.x;
    const int bij = blockIdx.x;
    const int j = bij & 31, i = (bij >> 5) & 31, b = bij >> 10;
    float accv = 0.f;
    #pragma unroll
    for (int kh = 0; kh < 3; kh++) {
        int ii = i + kh - 1;
        if (ii < 0 || ii > 31) continue;
        #pragma unroll
        for (int kw = 0; kw < 3; kw++) {
            int jj = j + kw - 1;
            if (jj < 0 || jj > 31) continue;
            accv += g_V[(b*NT + ii*32 + jj)*CD + c] * pw[(kh*3 + kw)*CD + c];
        }
    }
    float sc = gamma[c] * rsqrtf(var[c] + EPS);
    float bi = beta[c] - mean[c] * sc;
    g_mid[bij*CD + c] += accv * sc + bi;
}

// ---------------------------------------------------------------------------
// Kernel 5: Proj GEMM [8192x256]x[256x256] + BN -> d_out
// ---------------------------------------------------------------------------
__global__ __launch_bounds__(256) void proj_kernel(
    const float* __restrict__ W, const float* __restrict__ gamma,
    const float* __restrict__ beta, const float* __restrict__ mean,
    const float* __restrict__ var, float* __restrict__ out)
{
    __shared__ float As[16][68];
    __shared__ float Bs[16][68];
    const int tid = threadIdx.x;
    const int tx = tid & 15, ty = tid >> 4;
    const int row0 = blockIdx.x * 64;
    const int col0 = blockIdx.y * 64;
    const int arow = tid >> 2, ak4 = (tid & 3) << 2;
    const int bk = tid >> 4, bc4 = (tid & 15) << 2;

    u64 acc2[4][2];
    #pragma unroll
    for (int i = 0; i < 4; i++) { acc2[i][0] = 0ull; acc2[i][1] = 0ull; }

    for (int k0 = 0; k0 < CD; k0 += 16) {
        float4 a = *(const float4*)(g_mid + (row0 + arow) * CD + k0 + ak4);
        As[ak4+0][arow] = a.x; As[ak4+1][arow] = a.y;
        As[ak4+2][arow] = a.z; As[ak4+3][arow] = a.w;
        *(float4*)(&Bs[bk][bc4]) = *(const float4*)(W + (k0 + bk) * CD + col0 + bc4);
        __syncthreads();
        #pragma unroll
        for (int kk = 0; kk < 16; kk++) {
            float4 av = *(float4*)(&As[kk][ty << 2]);
            float4 bv = *(float4*)(&Bs[kk][tx << 2]);
            u64 b01 = pk2(bv.x, bv.y), b23 = pk2(bv.z, bv.w);
            float ar[4] = {av.x, av.y, av.z, av.w};
            #pragma unroll
            for (int i = 0; i < 4; i++) {
                u64 ai = pk2(ar[i], ar[i]);
                acc2[i][0] = ffma2(ai, b01, acc2[i][0]);
                acc2[i][1] = ffma2(ai, b23, acc2[i][1]);
            }
        }
        __syncthreads();
    }

    float acc[4][4];
    #pragma unroll
    for (int i = 0; i < 4; i++) {
        float2 c0 = upk2(acc2[i][0]), c1 = upk2(acc2[i][1]);
        acc[i][0] = c0.x; acc[i][1] = c0.y; acc[i][2] = c1.x; acc[i][3] = c1.y;
    }

    #pragma unroll
    for (int j = 0; j < 4; j++) {
        int co = col0 + (tx << 2) + j;
        float sc = gamma[co] * rsqrtf(var[co] + EPS);
        float bi = beta[co] - mean[co] * sc;
        #pragma unroll
        for (int i = 0; i < 4; i++) {
            int gr = row0 + (ty << 2) + i;
            out[gr*CD + co] = acc[i][j] * sc + bi;
        }
    }
}

// ---------------------------------------------------------------------------
extern "C" void kernel_launch(void* const* d_in, const int* in_sizes, int n_in,
                              void* d_out, int out_size)
{
    const float* inputs   = (const float*)d_in[0];
    const float* qkv_w    = (const float*)d_in[1];
    const float* qkv_g    = (const float*)d_in[2];
    const float* qkv_b    = (const float*)d_in[3];
    const float* qkv_m    = (const float*)d_in[4];
    const float* qkv_v    = (const float*)d_in[5];
    const float* pe_w     = (const float*)d_in[6];
    const float* pe_g     = (const float*)d_in[7];
    const float* pe_b     = (const float*)d_in[8];
    const float* pe_m     = (const float*)d_in[9];
    const float* pe_v     = (const float*)d_in[10];
    const float* proj_w   = (const float*)d_in[11];
    const float* proj_g   = (const float*)d_in[12];
    const float* proj_b   = (const float*)d_in[13];
    const float* proj_m   = (const float*)d_in[14];
    const float* proj_v   = (const float*)d_in[15];
    float* out = (float*)d_out;

    qkv_kernel<<<dim3(128, 8), 256>>>(inputs, qkv_w, qkv_g, qkv_b, qkv_m, qkv_v);
    rowstats_kernel<<<dim3(16, 64), 256>>>();
    pv_kernel<<<dim3(8, 64), 256>>>();
    pe_kernel<<<8192, 256>>>(pe_w, pe_g, pe_b, pe_m, pe_v);
    proj_kernel<<<dim3(128, 4), 256>>>(proj_w, proj_g, proj_b, proj_m, proj_v, out);
}

// round 3
// speedup vs baseline: 1.3239x; 1.2226x over previous
#include <cuda_runtime.h>

#define NB 8
#define NH 8
#define NT 1024
#define CD 256
#define KD 16
#define HD 32
#define HQ 512
#define EPS 0.001f
// 0.25 * log2(e) folded into Q so exp(S) == ex2(S')
#define QSCALE 0.36067376022224085f

typedef unsigned long long u64;

__device__ __forceinline__ u64 pk2(float lo, float hi) {
    u64 r; asm("mov.b64 %0,{%1,%2};" : "=l"(r) : "f"(lo), "f"(hi)); return r;
}
__device__ __forceinline__ float2 upk2(u64 v) {
    float2 f; asm("mov.b64 {%0,%1},%2;" : "=f"(f.x), "=f"(f.y) : "l"(v)); return f;
}
__device__ __forceinline__ u64 ffma2(u64 a, u64 b, u64 c) {
    u64 d; asm("fma.rn.f32x2 %0,%1,%2,%3;" : "=l"(d) : "l"(a), "l"(b), "l"(c)); return d;
}
__device__ __forceinline__ float ex2f(float x) {
    float y; asm("ex2.approx.f32 %0,%1;" : "=f"(y) : "f"(x)); return y;
}

// Scratch (static device globals; no allocations allowed)
__device__ float g_Q[NB*NH*NT*KD];     // q * 0.25*log2e, [b][h][n][16]
__device__ float g_Kd[NB*NH*NT*KD];    // [b][h][n][16]
__device__ float g_V[NB*NT*CD];        // NHWC, c = h*32+d
__device__ float g_rinv[NB*NH*NT];     // 1 / sum_m exp(S[n,m])  (no-max softmax)
__device__ float g_mid[NB*NT*CD];      // attn out (scrambled layout)
__device__ float g_pe[NB*NT*CD];       // BN(dwconv(V))

// ---------------------------------------------------------------------------
// Kernel 1: QKV GEMM [8192x256]x[256x512], BN folded, routed into Q/K/V
// ---------------------------------------------------------------------------
__global__ __launch_bounds__(256) void qkv_kernel(
    const float* __restrict__ X, const float* __restrict__ W,
    const float* __restrict__ gamma, const float* __restrict__ beta,
    const float* __restrict__ mean, const float* __restrict__ var)
{
    __shared__ float As[16][68];
    __shared__ float Bs[16][68];
    const int tid = threadIdx.x;
    const int tx = tid & 15, ty = tid >> 4;
    const int row0 = blockIdx.x * 64;
    const int col0 = blockIdx.y * 64;
    const int arow = tid >> 2, ak4 = (tid & 3) << 2;
    const int bk = tid >> 4, bc4 = (tid & 15) << 2;

    u64 acc2[4][2];
    #pragma unroll
    for (int i = 0; i < 4; i++) { acc2[i][0] = 0ull; acc2[i][1] = 0ull; }

    for (int k0 = 0; k0 < CD; k0 += 16) {
        float4 a = *(const float4*)(X + (row0 + arow) * CD + k0 + ak4);
        As[ak4+0][arow] = a.x; As[ak4+1][arow] = a.y;
        As[ak4+2][arow] = a.z; As[ak4+3][arow] = a.w;
        *(float4*)(&Bs[bk][bc4]) = *(const float4*)(W + (k0 + bk) * HQ + col0 + bc4);
        __syncthreads();
        #pragma unroll
        for (int kk = 0; kk < 16; kk++) {
            float4 av = *(float4*)(&As[kk][ty << 2]);
            float4 bv = *(float4*)(&Bs[kk][tx << 2]);
            u64 b01 = pk2(bv.x, bv.y), b23 = pk2(bv.z, bv.w);
            float ar[4] = {av.x, av.y, av.z, av.w};
            #pragma unroll
            for (int i = 0; i < 4; i++) {
                u64 ai = pk2(ar[i], ar[i]);
                acc2[i][0] = ffma2(ai, b01, acc2[i][0]);
                acc2[i][1] = ffma2(ai, b23, acc2[i][1]);
            }
        }
        __syncthreads();
    }

    float acc[4][4];
    #pragma unroll
    for (int i = 0; i < 4; i++) {
        float2 c0 = upk2(acc2[i][0]), c1 = upk2(acc2[i][1]);
        acc[i][0] = c0.x; acc[i][1] = c0.y; acc[i][2] = c1.x; acc[i][3] = c1.y;
    }

    #pragma unroll
    for (int j = 0; j < 4; j++) {
        int co = col0 + (tx << 2) + j;
        float sc = gamma[co] * rsqrtf(var[co] + EPS);
        float bi = beta[co] - mean[co] * sc;
        int h = co >> 6, rr = co & 63;
        #pragma unroll
        for (int i = 0; i < 4; i++) {
            int gr = row0 + (ty << 2) + i;
            int b = gr >> 10, n = gr & 1023;
            float v = acc[i][j] * sc + bi;
            if (rr < KD)           g_Q [((b*NH + h)*NT + n)*KD + rr]       = v * QSCALE;
            else if (rr < 2*KD)    g_Kd[((b*NH + h)*NT + n)*KD + rr - KD]  = v;
            else                   g_V [(b*NT + n)*CD + h*HD + rr - 2*KD]  = v;
        }
    }
}

// ---------------------------------------------------------------------------
// Kernel 2: depthwise 3x3 PE conv on V (NHWC, float4 channels) + BN -> g_pe
// ---------------------------------------------------------------------------
__global__ __launch_bounds__(256) void pe_kernel(
    const float* __restrict__ pw, const float* __restrict__ gamma,
    const float* __restrict__ beta, const float* __restrict__ mean,
    const float* __restrict__ var)
{
    const int idx = blockIdx.x * 256 + threadIdx.x;      // (b,i,j,c4)
    const int c4 = idx & 63;
    const int j  = (idx >> 6) & 31;
    const int i  = (idx >> 11) & 31;
    const int b  = idx >> 16;
    const int c  = c4 << 2;

    float4 acc = make_float4(0.f, 0.f, 0.f, 0.f);
    #pragma unroll
    for (int kh = 0; kh < 3; kh++) {
        int ii = i + kh - 1;
        if (ii < 0 || ii > 31) continue;
        #pragma unroll
        for (int kw = 0; kw < 3; kw++) {
            int jj = j + kw - 1;
            if (jj < 0 || jj > 31) continue;
            float4 v = *(const float4*)(g_V + (b*NT + ii*32 + jj)*CD + c);
            float4 w = *(const float4*)(pw + (kh*3 + kw)*CD + c);
            acc.x += v.x * w.x; acc.y += v.y * w.y;
            acc.z += v.z * w.z; acc.w += v.w * w.w;
        }
    }
    float4 g = *(const float4*)(gamma + c);
    float4 vr = *(const float4*)(var + c);
    float4 be = *(const float4*)(beta + c);
    float4 mn = *(const float4*)(mean + c);
    float4 o;
    float s;
    s = g.x * rsqrtf(vr.x + EPS); o.x = acc.x * s + (be.x - mn.x * s);
    s = g.y * rsqrtf(vr.y + EPS); o.y = acc.y * s + (be.y - mn.y * s);
    s = g.z * rsqrtf(vr.z + EPS); o.z = acc.z * s + (be.z - mn.z * s);
    s = g.w * rsqrtf(vr.w + EPS); o.w = acc.w * s + (be.w - mn.w * s);
    *(float4*)(g_pe + ((b*NT) + i*32 + j)*CD + c) = o;
}

// ---------------------------------------------------------------------------
// Kernel 3: per-row softmax denominator: rinv[n] = 1 / sum_m exp(S[n,m])
// ---------------------------------------------------------------------------
__global__ __launch_bounds__(256) void rowstats_kernel()
{
    __shared__ float ks[128][20];
    const int bh = blockIdx.y;
    const int tid = threadIdx.x;
    const int lane = tid & 15, rg = tid >> 4;
    const int nb = blockIdx.x * 64 + rg * 4;

    u64 q2[4][8];
    #pragma unroll
    for (int r = 0; r < 4; r++)
        #pragma unroll
        for (int j4 = 0; j4 < 4; j4++) {
            float4 t = *(const float4*)(g_Q + (bh*NT + nb + r)*KD + j4*4);
            q2[r][j4*2]   = pk2(t.x, t.y);
            q2[r][j4*2+1] = pk2(t.z, t.w);
        }

    float sm[4] = {0.f, 0.f, 0.f, 0.f};

    for (int mc = 0; mc < NT; mc += 128) {
        for (int l = tid; l < 512; l += 256) {
            int m = l >> 2, j4 = (l & 3) << 2;
            *(float4*)(&ks[m][j4]) = *(const float4*)(g_Kd + (bh*NT + mc + m)*KD + j4);
        }
        __syncthreads();
        #pragma unroll
        for (int i2 = 0; i2 < 8; i2++) {
            int m = lane + (i2 << 4);
            u64 kv2[8];
            #pragma unroll
            for (int j4 = 0; j4 < 4; j4++) {
                float4 t = *(float4*)(&ks[m][j4*4]);
                kv2[j4*2]   = pk2(t.x, t.y);
                kv2[j4*2+1] = pk2(t.z, t.w);
            }
            #pragma unroll
            for (int r = 0; r < 4; r++) {
                u64 s2 = 0ull;
                #pragma unroll
                for (int jj = 0; jj < 8; jj++) s2 = ffma2(q2[r][jj], kv2[jj], s2);
                float2 sf = upk2(s2);
                sm[r] += ex2f(sf.x + sf.y);
            }
        }
        __syncthreads();
    }

    #pragma unroll
    for (int off = 8; off; off >>= 1)
        #pragma unroll
        for (int r = 0; r < 4; r++)
            sm[r] += __shfl_xor_sync(0xffffffffu, sm[r], off);

    if (lane == 0) {
        #pragma unroll
        for (int r = 0; r < 4; r++)
            g_rinv[bh*NT + nb + r] = 1.0f / sm[r];
    }
}

// ---------------------------------------------------------------------------
// Kernel 4: O[m,d] = sum_n P[n,m] * v[n,d]; rinv folded into V tile.
// ---------------------------------------------------------------------------
__global__ __launch_bounds__(256) void pv_kernel()
{
    __shared__ float qs[64][20];
    __shared__ float vs[64][32];
    __shared__ float ps[64][136];

    const int bh = blockIdx.y;
    const int b = bh >> 3, h = bh & 7;
    const int m0 = blockIdx.x * 128;
    const int tid = threadIdx.x;
    const int mg = tid >> 3;   // owns m = m0 + 4*mg + mm
    const int dg = tid & 7;    // owns d = 4*dg + dd

    u64 kreg2[4][8];
    #pragma unroll
    for (int mm = 0; mm < 4; mm++) {
        int m = m0 + (mg << 2) + mm;
        #pragma unroll
        for (int j4 = 0; j4 < 4; j4++) {
            float4 t = *(const float4*)(g_Kd + (bh*NT + m)*KD + j4*4);
            kreg2[mm][j4*2]   = pk2(t.x, t.y);
            kreg2[mm][j4*2+1] = pk2(t.z, t.w);
        }
    }

    u64 acc2[4][2];   // [mm][d-pair]
    #pragma unroll
    for (int i = 0; i < 4; i++) { acc2[i][0] = 0ull; acc2[i][1] = 0ull; }

    for (int nc = 0; nc < NT; nc += 64) {
        {
            int n = tid >> 2, j4 = (tid & 3) << 2;
            *(float4*)(&qs[n][j4]) = *(const float4*)(g_Q + (bh*NT + nc + n)*KD + j4);
        }
        for (int l = tid; l < 512; l += 256) {   // V chunk scaled by rinv[n]
            int n = l >> 3, j4 = (l & 7) << 2;
            float ri = g_rinv[bh*NT + nc + n];
            float4 v = *(const float4*)(g_V + (b*NT + nc + n)*CD + h*HD + j4);
            v.x *= ri; v.y *= ri; v.z *= ri; v.w *= ri;
            *(float4*)(&vs[n][j4]) = v;
        }
        __syncthreads();

        // Phase A: p[n][m] = exp2(S') for this thread's 4 m's, 8 n's
        #pragma unroll
        for (int i2 = 0; i2 < 8; i2++) {
            int n = dg + (i2 << 3);
            u64 qv2[8];
            #pragma unroll
            for (int j4 = 0; j4 < 4; j4++) {
                float4 t = *(float4*)(&qs[n][j4*4]);
                qv2[j4*2]   = pk2(t.x, t.y);
                qv2[j4*2+1] = pk2(t.z, t.w);
            }
            float p[4];
            #pragma unroll
            for (int mm = 0; mm < 4; mm++) {
                u64 s2 = 0ull;
                #pragma unroll
                for (int jj = 0; jj < 8; jj++) s2 = ffma2(qv2[jj], kreg2[mm][jj], s2);
                float2 sf = upk2(s2);
                p[mm] = ex2f(sf.x + sf.y);
            }
            *(float4*)(&ps[n][mg << 2]) = make_float4(p[0], p[1], p[2], p[3]);
        }
        __syncthreads();

        // Phase B: acc[mm][dd] += p[n][mm] * v'[n][dd]
        #pragma unroll 4
        for (int n = 0; n < 64; n++) {
            float4 pv = *(float4*)(&ps[n][mg << 2]);
            float4 vv = *(float4*)(&vs[n][dg << 2]);
            u64 v01 = pk2(vv.x, vv.y), v23 = pk2(vv.z, vv.w);
            float pr[4] = {pv.x, pv.y, pv.z, pv.w};
            #pragma unroll
            for (int mm = 0; mm < 4; mm++) {
                u64 pb = pk2(pr[mm], pr[mm]);
                acc2[mm][0] = ffma2(pb, v01, acc2[mm][0]);
                acc2[mm][1] = ffma2(pb, v23, acc2[mm][1]);
            }
        }
        __syncthreads();
    }

    float acc[4][4];
    #pragma unroll
    for (int mm = 0; mm < 4; mm++) {
        float2 c0 = upk2(acc2[mm][0]), c1 = upk2(acc2[mm][1]);
        acc[mm][0] = c0.x; acc[mm][1] = c0.y; acc[mm][2] = c1.x; acc[mm][3] = c1.y;
    }

    // Scrambled write: mid[b][hs=d][ws=4h+(m>>8)][c=m&255]
    const int w = (h << 2) + (m0 >> 8);
    const int cbase = (m0 & 255) + (mg << 2);
    #pragma unroll
    for (int dd = 0; dd < 4; dd++) {
        int d = (dg << 2) + dd;
        float4 o = make_float4(acc[0][dd], acc[1][dd], acc[2][dd], acc[3][dd]);
        *(float4*)(&g_mid[((b*32 + d)*32 + w)*CD + cbase]) = o;
    }
}

// ---------------------------------------------------------------------------
// Kernel 5: Proj GEMM [8192x256]x[256x256] on (g_mid + g_pe) + BN -> d_out
// ---------------------------------------------------------------------------
__global__ __launch_bounds__(256) void proj_kernel(
    const float* __restrict__ W, const float* __restrict__ gamma,
    const float* __restrict__ beta, const float* __restrict__ mean,
    const float* __restrict__ var, float* __restrict__ out)
{
    __shared__ float As[16][68];
    __shared__ float Bs[16][68];
    const int tid = threadIdx.x;
    const int tx = tid & 15, ty = tid >> 4;
    const int row0 = blockIdx.x * 64;
    const int col0 = blockIdx.y * 64;
    const int arow = tid >> 2, ak4 = (tid & 3) << 2;
    const int bk = tid >> 4, bc4 = (tid & 15) << 2;

    u64 acc2[4][2];
    #pragma unroll
    for (int i = 0; i < 4; i++) { acc2[i][0] = 0ull; acc2[i][1] = 0ull; }

    for (int k0 = 0; k0 < CD; k0 += 16) {
        const int aoff = (row0 + arow) * CD + k0 + ak4;
        float4 a = *(const float4*)(g_mid + aoff);
        float4 p = *(const float4*)(g_pe + aoff);
        a.x += p.x; a.y += p.y; a.z += p.z; a.w += p.w;
        As[ak4+0][arow] = a.x; As[ak4+1][arow] = a.y;
        As[ak4+2][arow] = a.z; As[ak4+3][arow] = a.w;
        *(float4*)(&Bs[bk][bc4]) = *(const float4*)(W + (k0 + bk) * CD + col0 + bc4);
        __syncthreads();
        #pragma unroll
        for (int kk = 0; kk < 16; kk++) {
            float4 av = *(float4*)(&As[kk][ty << 2]);
            float4 bv = *(float4*)(&Bs[kk][tx << 2]);
            u64 b01 = pk2(bv.x, bv.y), b23 = pk2(bv.z, bv.w);
            float ar[4] = {av.x, av.y, av.z, av.w};
            #pragma unroll
            for (int i = 0; i < 4; i++) {
                u64 ai = pk2(ar[i], ar[i]);
                acc2[i][0] = ffma2(ai, b01, acc2[i][0]);
                acc2[i][1] = ffma2(ai, b23, acc2[i][1]);
            }
        }
        __syncthreads();
    }

    float acc[4][4];
    #pragma unroll
    for (int i = 0; i < 4; i++) {
        float2 c0 = upk2(acc2[i][0]), c1 = upk2(acc2[i][1]);
        acc[i][0] = c0.x; acc[i][1] = c0.y; acc[i][2] = c1.x; acc[i][3] = c1.y;
    }

    #pragma unroll
    for (int j = 0; j < 4; j++) {
        int co = col0 + (tx << 2) + j;
        float sc = gamma[co] * rsqrtf(var[co] + EPS);
        float bi = beta[co] - mean[co] * sc;
        #pragma unroll
        for (int i = 0; i < 4; i++) {
            int gr = row0 + (ty << 2) + i;
            out[gr*CD + co] = acc[i][j] * sc + bi;
        }
    }
}

// ---------------------------------------------------------------------------
extern "C" void kernel_launch(void* const* d_in, const int* in_sizes, int n_in,
                              void* d_out, int out_size)
{
    const float* inputs   = (const float*)d_in[0];
    const float* qkv_w    = (const float*)d_in[1];
    const float* qkv_g    = (const float*)d_in[2];
    const float* qkv_b    = (const float*)d_in[3];
    const float* qkv_m    = (const float*)d_in[4];
    const float* qkv_v    = (const float*)d_in[5];
    const float* pe_w     = (const float*)d_in[6];
    const float* pe_g     = (const float*)d_in[7];
    const float* pe_b     = (const float*)d_in[8];
    const float* pe_m     = (const float*)d_in[9];
    const float* pe_v     = (const float*)d_in[10];
    const float* proj_w   = (const float*)d_in[11];
    const float* proj_g   = (const float*)d_in[12];
    const float* proj_b   = (const float*)d_in[13];
    const float* proj_m   = (const float*)d_in[14];
    const float* proj_v   = (const float*)d_in[15];
    float* out = (float*)d_out;

    qkv_kernel<<<dim3(128, 8), 256>>>(inputs, qkv_w, qkv_g, qkv_b, qkv_m, qkv_v);
    pe_kernel<<<2048, 256>>>(pe_w, pe_g, pe_b, pe_m, pe_v);
    rowstats_kernel<<<dim3(16, 64), 256>>>();
    pv_kernel<<<dim3(8, 64), 256>>>();
    proj_kernel<<<dim3(128, 4), 256>>>(proj_w, proj_g, proj_b, proj_m, proj_v, out);
}

// round 7
// speedup vs baseline: 1.6034x; 1.2111x over previous
#include <cuda_runtime.h>
#include <cstdint>

#define NB 8
#define NH 8
#define NT 1024
#define CD 256
#define KD 16
#define HD 32
#define HQ 512
#define EPS 0.001f
// 0.25 * log2(e) folded into Q so exp(S) == ex2(S')
#define QSCALE 0.36067376022224085f

typedef unsigned long long u64;

__device__ __forceinline__ u64 pk2(float lo, float hi) {
    u64 r; asm("mov.b64 %0,{%1,%2};" : "=l"(r) : "f"(lo), "f"(hi)); return r;
}
__device__ __forceinline__ float2 upk2(u64 v) {
    float2 f; asm("mov.b64 {%0,%1},%2;" : "=f"(f.x), "=f"(f.y) : "l"(v)); return f;
}
__device__ __forceinline__ u64 ffma2(u64 a, u64 b, u64 c) {
    u64 d; asm("fma.rn.f32x2 %0,%1,%2,%3;" : "=l"(d) : "l"(a), "l"(b), "l"(c)); return d;
}
__device__ __forceinline__ float ex2f(float x) {
    float y; asm("ex2.approx.f32 %0,%1;" : "=f"(y) : "f"(x)); return y;
}
__device__ __forceinline__ uint32_t tf32r(float x) {
    uint32_t h; asm("cvt.rna.tf32.f32 %0, %1;" : "=r"(h) : "f"(x)); return h;
}
__device__ __forceinline__ void tf32_split(float x, uint32_t& hi, uint32_t& lo) {
    uint32_t h; asm("cvt.rna.tf32.f32 %0, %1;" : "=r"(h) : "f"(x));
    float lf = x - __uint_as_float(h);
    uint32_t l; asm("cvt.rna.tf32.f32 %0, %1;" : "=r"(l) : "f"(lf));
    hi = h; lo = l;
}
// D(16x8) += A(16x8) * B(8x8), tf32 inputs, f32 accum
__device__ __forceinline__ void mma8(float* d, const uint32_t* a, const uint32_t* b) {
    asm volatile(
        "mma.sync.aligned.m16n8k8.row.col.f32.tf32.tf32.f32 "
        "{%0,%1,%2,%3},{%4,%5,%6,%7},{%8,%9},{%0,%1,%2,%3};"
        : "+f"(d[0]), "+f"(d[1]), "+f"(d[2]), "+f"(d[3])
        : "r"(a[0]), "r"(a[1]), "r"(a[2]), "r"(a[3]), "r"(b[0]), "r"(b[1]));
}

// Scratch (static device globals; no allocations allowed)
__device__ float g_Q[NB*NH*NT*KD];     // q * 0.25*log2e, [b][h][n][16]
__device__ float g_Kd[NB*NH*NT*KD];    // [b][h][n][16]
__device__ float g_V[NB*NT*CD];        // NHWC, c = h*32+d
__device__ float g_rinv[NB*NH*NT];     // 1 / sum_m exp(S[n,m])
__device__ float g_mid[NB*NT*CD];      // attn out (scrambled layout)
__device__ float g_pe[NB*NT*CD];       // BN(dwconv(V))

// ---------------------------------------------------------------------------
// Kernel 1: QKV GEMM [8192x256]x[256x512], BN folded, routed into Q/K/V
// ---------------------------------------------------------------------------
__global__ __launch_bounds__(256) void qkv_kernel(
    const float* __restrict__ X, const float* __restrict__ W,
    const float* __restrict__ gamma, const float* __restrict__ beta,
    const float* __restrict__ mean, const float* __restrict__ var)
{
    __shared__ float As[16][68];
    __shared__ float Bs[16][68];
    const int tid = threadIdx.x;
    const int tx = tid & 15, ty = tid >> 4;
    const int row0 = blockIdx.x * 64;
    const int col0 = blockIdx.y * 64;
    const int arow = tid >> 2, ak4 = (tid & 3) << 2;
    const int bk = tid >> 4, bc4 = (tid & 15) << 2;

    u64 acc2[4][2];
    #pragma unroll
    for (int i = 0; i < 4; i++) { acc2[i][0] = 0ull; acc2[i][1] = 0ull; }

    for (int k0 = 0; k0 < CD; k0 += 16) {
        float4 a = *(const float4*)(X + (row0 + arow) * CD + k0 + ak4);
        As[ak4+0][arow] = a.x; As[ak4+1][arow] = a.y;
        As[ak4+2][arow] = a.z; As[ak4+3][arow] = a.w;
        *(float4*)(&Bs[bk][bc4]) = *(const float4*)(W + (k0 + bk) * HQ + col0 + bc4);
        __syncthreads();
        #pragma unroll
        for (int kk = 0; kk < 16; kk++) {
            float4 av = *(float4*)(&As[kk][ty << 2]);
            float4 bv = *(float4*)(&Bs[kk][tx << 2]);
            u64 b01 = pk2(bv.x, bv.y), b23 = pk2(bv.z, bv.w);
            float ar[4] = {av.x, av.y, av.z, av.w};
            #pragma unroll
            for (int i = 0; i < 4; i++) {
                u64 ai = pk2(ar[i], ar[i]);
                acc2[i][0] = ffma2(ai, b01, acc2[i][0]);
                acc2[i][1] = ffma2(ai, b23, acc2[i][1]);
            }
        }
        __syncthreads();
    }

    float acc[4][4];
    #pragma unroll
    for (int i = 0; i < 4; i++) {
        float2 c0 = upk2(acc2[i][0]), c1 = upk2(acc2[i][1]);
        acc[i][0] = c0.x; acc[i][1] = c0.y; acc[i][2] = c1.x; acc[i][3] = c1.y;
    }

    #pragma unroll
    for (int j = 0; j < 4; j++) {
        int co = col0 + (tx << 2) + j;
        float sc = gamma[co] * rsqrtf(var[co] + EPS);
        float bi = beta[co] - mean[co] * sc;
        int h = co >> 6, rr = co & 63;
        #pragma unroll
        for (int i = 0; i < 4; i++) {
            int gr = row0 + (ty << 2) + i;
            int b = gr >> 10, n = gr & 1023;
            float v = acc[i][j] * sc + bi;
            if (rr < KD)           g_Q [((b*NH + h)*NT + n)*KD + rr]       = v * QSCALE;
            else if (rr < 2*KD)    g_Kd[((b*NH + h)*NT + n)*KD + rr - KD]  = v;
            else                   g_V [(b*NT + n)*CD + h*HD + rr - 2*KD]  = v;
        }
    }
}

// ---------------------------------------------------------------------------
// Kernel 2: depthwise 3x3 PE conv on V (NHWC, float4 channels) + BN -> g_pe
// ---------------------------------------------------------------------------
__global__ __launch_bounds__(256) void pe_kernel(
    const float* __restrict__ pw, const float* __restrict__ gamma,
    const float* __restrict__ beta, const float* __restrict__ mean,
    const float* __restrict__ var)
{
    const int idx = blockIdx.x * 256 + threadIdx.x;      // (b,i,j,c4)
    const int c4 = idx & 63;
    const int j  = (idx >> 6) & 31;
    const int i  = (idx >> 11) & 31;
    const int b  = idx >> 16;
    const int c  = c4 << 2;

    float4 acc = make_float4(0.f, 0.f, 0.f, 0.f);
    #pragma unroll
    for (int kh = 0; kh < 3; kh++) {
        int ii = i + kh - 1;
        if (ii < 0 || ii > 31) continue;
        #pragma unroll
        for (int kw = 0; kw < 3; kw++) {
            int jj = j + kw - 1;
            if (jj < 0 || jj > 31) continue;
            float4 v = *(const float4*)(g_V + (b*NT + ii*32 + jj)*CD + c);
            float4 w = *(const float4*)(pw + (kh*3 + kw)*CD + c);
            acc.x += v.x * w.x; acc.y += v.y * w.y;
            acc.z += v.z * w.z; acc.w += v.w * w.w;
        }
    }
    float4 g = *(const float4*)(gamma + c);
    float4 vr = *(const float4*)(var + c);
    float4 be = *(const float4*)(beta + c);
    float4 mn = *(const float4*)(mean + c);
    float4 o;
    float s;
    s = g.x * rsqrtf(vr.x + EPS); o.x = acc.x * s + (be.x - mn.x * s);
    s = g.y * rsqrtf(vr.y + EPS); o.y = acc.y * s + (be.y - mn.y * s);
    s = g.z * rsqrtf(vr.z + EPS); o.z = acc.z * s + (be.z - mn.z * s);
    s = g.w * rsqrtf(vr.w + EPS); o.w = acc.w * s + (be.w - mn.w * s);
    *(float4*)(g_pe + ((b*NT) + i*32 + j)*CD + c) = o;
}

// ---------------------------------------------------------------------------
// Kernel 3: per-row softmax denominator: rinv[n] = 1 / sum_m exp(S[n,m])
// ---------------------------------------------------------------------------
__global__ __launch_bounds__(256) void rowstats_kernel()
{
    __shared__ float ks[128][20];
    const int bh = blockIdx.y;
    const int tid = threadIdx.x;
    const int lane = tid & 15, rg = tid >> 4;
    const int nb = blockIdx.x * 64 + rg * 4;

    u64 q2[4][8];
    #pragma unroll
    for (int r = 0; r < 4; r++)
        #pragma unroll
        for (int j4 = 0; j4 < 4; j4++) {
            float4 t = *(const float4*)(g_Q + (bh*NT + nb + r)*KD + j4*4);
            q2[r][j4*2]   = pk2(t.x, t.y);
            q2[r][j4*2+1] = pk2(t.z, t.w);
        }

    float sm[4] = {0.f, 0.f, 0.f, 0.f};

    for (int mc = 0; mc < NT; mc += 128) {
        for (int l = tid; l < 512; l += 256) {
            int m = l >> 2, j4 = (l & 3) << 2;
            *(float4*)(&ks[m][j4]) = *(const float4*)(g_Kd + (bh*NT + mc + m)*KD + j4);
        }
        __syncthreads();
        #pragma unroll
        for (int i2 = 0; i2 < 8; i2++) {
            int m = lane + (i2 << 4);
            u64 kv2[8];
            #pragma unroll
            for (int j4 = 0; j4 < 4; j4++) {
                float4 t = *(float4*)(&ks[m][j4*4]);
                kv2[j4*2]   = pk2(t.x, t.y);
                kv2[j4*2+1] = pk2(t.z, t.w);
            }
            #pragma unroll
            for (int r = 0; r < 4; r++) {
                u64 sa = 0ull, sb = 0ull;
                #pragma unroll
                for (int jj = 0; jj < 4; jj++) {
                    sa = ffma2(q2[r][2*jj],   kv2[2*jj],   sa);
                    sb = ffma2(q2[r][2*jj+1], kv2[2*jj+1], sb);
                }
                float2 fa = upk2(sa), fb = upk2(sb);
                sm[r] += ex2f((fa.x + fa.y) + (fb.x + fb.y));
            }
        }
        __syncthreads();
    }

    #pragma unroll
    for (int off = 8; off; off >>= 1)
        #pragma unroll
        for (int r = 0; r < 4; r++)
            sm[r] += __shfl_xor_sync(0xffffffffu, sm[r], off);

    if (lane == 0) {
        #pragma unroll
        for (int r = 0; r < 4; r++)
            g_rinv[bh*NT + nb + r] = 1.0f / sm[r];
    }
}

// ---------------------------------------------------------------------------
// Kernel 4: pv via mma.sync tf32 (sm_103-legal HMMA path).
//   S = K(3xtf32) . Q^T(3xtf32)  -> fp32-grade scores, p = ex2(S)
//   O = P^T(tf32) . V'(tf32), V' = V * rinv; accum fp32 in registers.
//   Block: 8 warps, warp w owns m-rows [m0+16w, m0+16w+16), all 32 d.
// ---------------------------------------------------------------------------
__global__ __launch_bounds__(256) void pv_kernel()
{
    __shared__ float ps[64][132];   // P[n][m] (tf32 bits), 33792 B
    __shared__ float vsm[64][40];   // V'[n][d] (tf32 bits), 10240 B
    __shared__ float qs[64][20];    // Q chunk fp32, 5120 B   (total 49152)

    const int tid = threadIdx.x;
    const int wid = tid >> 5, lane = tid & 31;
    const int bh = blockIdx.y;
    const int b = bh >> 3, h = bh & 7;
    const int m0 = blockIdx.x * 128;
    const int r = lane >> 2;   // 0..7
    const int c = lane & 3;    // 0..3

    // K fragments (A of S-mma), 2 k-steps, hi/lo tf32 split
    uint32_t khi[2][4], klo[2][4];
    {
        const float* Kb = g_Kd + (bh*NT + m0 + wid*16)*KD;
        #pragma unroll
        for (int s = 0; s < 2; s++) {
            tf32_split(Kb[ r     *KD + s*8 + c    ], khi[s][0], klo[s][0]);
            tf32_split(Kb[(r + 8)*KD + s*8 + c    ], khi[s][1], klo[s][1]);
            tf32_split(Kb[ r     *KD + s*8 + c + 4], khi[s][2], klo[s][2]);
            tf32_split(Kb[(r + 8)*KD + s*8 + c + 4], khi[s][3], klo[s][3]);
        }
    }

    float acc[4][4];   // [d-tile][frag] accumulated across all chunks
    #pragma unroll
    for (int t = 0; t < 4; t++)
        #pragma unroll
        for (int j = 0; j < 4; j++) acc[t][j] = 0.f;

    for (int ci = 0; ci < 16; ci++) {
        const int nc = ci << 6;
        if (ci > 0) __syncthreads();   // protect qs/vsm/ps from previous chunk readers

        // stage Q chunk [64 x 16]
        {
            int n = tid >> 2, j4 = (tid & 3) << 2;
            *(float4*)(&qs[n][j4]) = *(const float4*)(g_Q + (bh*NT + nc + n)*KD + j4);
        }
        // stage V' chunk [64 n x 32 d], scaled by rinv, tf32-rounded
        {
            int n = tid & 63, dq = tid >> 6;   // dq: 4 groups x 8 d
            float ri = g_rinv[bh*NT + nc + n];
            const float* vb = g_V + (b*NT + nc + n)*CD + h*HD + dq*8;
            float4 v0 = *(const float4*)(vb);
            float4 v1 = *(const float4*)(vb + 4);
            float vv[8] = {v0.x, v0.y, v0.z, v0.w, v1.x, v1.y, v1.z, v1.w};
            #pragma unroll
            for (int dd = 0; dd < 8; dd++)
                vsm[n][dq*8 + dd] = __uint_as_float(tf32r(vv[dd] * ri));
        }
        __syncthreads();

        // Phase A: S-mma (3xtf32) per 8-n tile, then ex2 -> ps (tf32 bits)
        #pragma unroll
        for (int t = 0; t < 8; t++) {
            float d4[4] = {0.f, 0.f, 0.f, 0.f};
            #pragma unroll
            for (int s = 0; s < 2; s++) {
                float b0f = qs[t*8 + r][s*8 + c];
                float b1f = qs[t*8 + r][s*8 + c + 4];
                uint32_t bh2[2], bl2[2];
                tf32_split(b0f, bh2[0], bl2[0]);
                tf32_split(b1f, bh2[1], bl2[1]);
                mma8(d4, khi[s], bh2);
                mma8(d4, khi[s], bl2);
                mma8(d4, klo[s], bh2);
            }
            // d4[0]:(m=16w+r,   n=t8+2c)   d4[1]:(.., n+1)
            // d4[2]:(m=16w+r+8, n=t8+2c)   d4[3]:(.., n+1)
            int n0 = t*8 + 2*c;
            int mA = wid*16 + r;
            ps[n0    ][mA    ] = __uint_as_float(tf32r(ex2f(d4[0])));
            ps[n0 + 1][mA    ] = __uint_as_float(tf32r(ex2f(d4[1])));
            ps[n0    ][mA + 8] = __uint_as_float(tf32r(ex2f(d4[2])));
            ps[n0 + 1][mA + 8] = __uint_as_float(tf32r(ex2f(d4[3])));
        }
        __syncthreads();

        // Phase B: O += P^T . V'   (8 k-steps over n, 4 d-tiles)
        #pragma unroll
        for (int s = 0; s < 8; s++) {
            uint32_t a[4];
            a[0] = __float_as_uint(ps[s*8 + c    ][wid*16 + r    ]);
            a[1] = __float_as_uint(ps[s*8 + c    ][wid*16 + r + 8]);
            a[2] = __float_as_uint(ps[s*8 + c + 4][wid*16 + r    ]);
            a[3] = __float_as_uint(ps[s*8 + c + 4][wid*16 + r + 8]);
            #pragma unroll
            for (int t = 0; t < 4; t++) {
                uint32_t bb[2];
                bb[0] = __float_as_uint(vsm[s*8 + c    ][t*8 + r]);
                bb[1] = __float_as_uint(vsm[s*8 + c + 4][t*8 + r]);
                mma8(acc[t], a, bb);
            }
        }
    }

    // Output: acc[t][0]:(m=gm, d=t8+2c) [1]:(gm, d+1) [2]:(gm+8, d) [3]:(gm+8, d+1)
    // Scrambled: mid[b][d][w=4h+(m>>8)][c=m&255]
    const int gm = m0 + wid*16 + r;
    const int wq = (h << 2) + (m0 >> 8);
    const int cc0 = gm & 255;
    #pragma unroll
    for (int t = 0; t < 4; t++) {
        int d0 = t*8 + 2*c;
        g_mid[((b*32 + d0    )*32 + wq)*CD + cc0    ] = acc[t][0];
        g_mid[((b*32 + d0 + 1)*32 + wq)*CD + cc0    ] = acc[t][1];
        g_mid[((b*32 + d0    )*32 + wq)*CD + cc0 + 8] = acc[t][2];
        g_mid[((b*32 + d0 + 1)*32 + wq)*CD + cc0 + 8] = acc[t][3];
    }
}

// ---------------------------------------------------------------------------
// Kernel 5: Proj GEMM [8192x256]x[256x256] on (g_mid + g_pe) + BN -> d_out
// ---------------------------------------------------------------------------
__global__ __launch_bounds__(256) void proj_kernel(
    const float* __restrict__ W, const float* __restrict__ gamma,
    const float* __restrict__ beta, const float* __restrict__ mean,
    const float* __restrict__ var, float* __restrict__ out)
{
    __shared__ float As[16][68];
    __shared__ float Bs[16][68];
    const int tid = threadIdx.x;
    const int tx = tid & 15, ty = tid >> 4;
    const int row0 = blockIdx.x * 64;
    const int col0 = blockIdx.y * 64;
    const int arow = tid >> 2, ak4 = (tid & 3) << 2;
    const int bk = tid >> 4, bc4 = (tid & 15) << 2;

    u64 acc2[4][2];
    #pragma unroll
    for (int i = 0; i < 4; i++) { acc2[i][0] = 0ull; acc2[i][1] = 0ull; }

    for (int k0 = 0; k0 < CD; k0 += 16) {
        const int aoff = (row0 + arow) * CD + k0 + ak4;
        float4 a = *(const float4*)(g_mid + aoff);
        float4 p = *(const float4*)(g_pe + aoff);
        a.x += p.x; a.y += p.y; a.z += p.z; a.w += p.w;
        As[ak4+0][arow] = a.x; As[ak4+1][arow] = a.y;
        As[ak4+2][arow] = a.z; As[ak4+3][arow] = a.w;
        *(float4*)(&Bs[bk][bc4]) = *(const float4*)(W + (k0 + bk) * CD + col0 + bc4);
        __syncthreads();
        #pragma unroll
        for (int kk = 0; kk < 16; kk++) {
            float4 av = *(float4*)(&As[kk][ty << 2]);
            float4 bv = *(float4*)(&Bs[kk][tx << 2]);
            u64 b01 = pk2(bv.x, bv.y), b23 = pk2(bv.z, bv.w);
            float ar[4] = {av.x, av.y, av.z, av.w};
            #pragma unroll
            for (int i = 0; i < 4; i++) {
                u64 ai = pk2(ar[i], ar[i]);
                acc2[i][0] = ffma2(ai, b01, acc2[i][0]);
                acc2[i][1] = ffma2(ai, b23, acc2[i][1]);
            }
        }
        __syncthreads();
    }

    float acc[4][4];
    #pragma unroll
    for (int i = 0; i < 4; i++) {
        float2 c0 = upk2(acc2[i][0]), c1 = upk2(acc2[i][1]);
        acc[i][0] = c0.x; acc[i][1] = c0.y; acc[i][2] = c1.x; acc[i][3] = c1.y;
    }

    #pragma unroll
    for (int j = 0; j < 4; j++) {
        int co = col0 + (tx << 2) + j;
        float sc = gamma[co] * rsqrtf(var[co] + EPS);
        float bi = beta[co] - mean[co] * sc;
        #pragma unroll
        for (int i = 0; i < 4; i++) {
            int gr = row0 + (ty << 2) + i;
            out[gr*CD + co] = acc[i][j] * sc + bi;
        }
    }
}

// ---------------------------------------------------------------------------
extern "C" void kernel_launch(void* const* d_in, const int* in_sizes, int n_in,
                              void* d_out, int out_size)
{
    const float* inputs   = (const float*)d_in[0];
    const float* qkv_w    = (const float*)d_in[1];
    const float* qkv_g    = (const float*)d_in[2];
    const float* qkv_b    = (const float*)d_in[3];
    const float* qkv_m    = (const float*)d_in[4];
    const float* qkv_v    = (const float*)d_in[5];
    const float* pe_w     = (const float*)d_in[6];
    const float* pe_g     = (const float*)d_in[7];
    const float* pe_b     = (const float*)d_in[8];
    const float* pe_m     = (const float*)d_in[9];
    const float* pe_v     = (const float*)d_in[10];
    const float* proj_w   = (const float*)d_in[11];
    const float* proj_g   = (const float*)d_in[12];
    const float* proj_b   = (const float*)d_in[13];
    const float* proj_m   = (const float*)d_in[14];
    const float* proj_v   = (const float*)d_in[15];
    float* out = (float*)d_out;

    qkv_kernel<<<dim3(128, 8), 256>>>(inputs, qkv_w, qkv_g, qkv_b, qkv_m, qkv_v);
    pe_kernel<<<2048, 256>>>(pe_w, pe_g, pe_b, pe_m, pe_v);
    rowstats_kernel<<<dim3(16, 64), 256>>>();
    pv_kernel<<<dim3(8, 64), 256>>>();
    proj_kernel<<<dim3(128, 4), 256>>>(proj_w, proj_g, proj_b, proj_m, proj_v, out);
}

// round 9
// speedup vs baseline: 1.7239x; 1.0752x over previous
#include <cuda_runtime.h>
#include <cstdint>

#define NB 8
#define NH 8
#define NT 1024
#define CD 256
#define KD 16
#define HD 32
#define HQ 512
#define EPS 0.001f
// 0.25 * log2(e) folded into Q so exp(S) == ex2(S')
#define QSCALE 0.36067376022224085f

typedef unsigned long long u64;

__device__ __forceinline__ float ex2f(float x) {
    float y; asm("ex2.approx.f32 %0,%1;" : "=f"(y) : "f"(x)); return y;
}
__device__ __forceinline__ uint32_t tf32r(float x) {
    uint32_t h; asm("cvt.rna.tf32.f32 %0, %1;" : "=r"(h) : "f"(x)); return h;
}
__device__ __forceinline__ void tf32_split(float x, uint32_t& hi, uint32_t& lo) {
    uint32_t h; asm("cvt.rna.tf32.f32 %0, %1;" : "=r"(h) : "f"(x));
    float lf = x - __uint_as_float(h);
    uint32_t l; asm("cvt.rna.tf32.f32 %0, %1;" : "=r"(l) : "f"(lf));
    hi = h; lo = l;
}
// D(16x8) += A(16x8) * B(8x8), tf32 inputs, f32 accum
__device__ __forceinline__ void mma8(float* d, const uint32_t* a, const uint32_t* b) {
    asm volatile(
        "mma.sync.aligned.m16n8k8.row.col.f32.tf32.tf32.f32 "
        "{%0,%1,%2,%3},{%4,%5,%6,%7},{%8,%9},{%0,%1,%2,%3};"
        : "+f"(d[0]), "+f"(d[1]), "+f"(d[2]), "+f"(d[3])
        : "r"(a[0]), "r"(a[1]), "r"(a[2]), "r"(a[3]), "r"(b[0]), "r"(b[1]));
}

// Scratch (static device globals; no allocations allowed)
__device__ float g_Q[NB*NH*NT*KD];     // q * 0.25*log2e, [b][h][n][16]
__device__ float g_Kd[NB*NH*NT*KD];    // [b][h][n][16]
__device__ float g_V[NB*NT*CD];        // NHWC, c = h*32+d
__device__ float g_rinv[NB*NH*NT];     // 1 / sum_m exp(S[n,m])
__device__ float g_mid[NB*NT*CD];      // attn out (scrambled layout)
__device__ float g_pe[NB*NT*CD];       // BN(dwconv(V))

// ---------------------------------------------------------------------------
// Kernel 1: QKV GEMM [8192x256]x[256x512] via 3xtf32 mma, BN folded, routed.
// Block 128m x 128n, 8 warps (2m x 4n), k-chunk 16, hi/lo split at staging.
// ---------------------------------------------------------------------------
__global__ __launch_bounds__(256) void qkv_mma_kernel(
    const float* __restrict__ X, const float* __restrict__ W,
    const float* __restrict__ gamma, const float* __restrict__ beta,
    const float* __restrict__ mean, const float* __restrict__ var)
{
    __shared__ float xhi[128][20], xlo[128][20];   // A tile [m][k]
    __shared__ float whi[16][136], wlo[16][136];   // B tile [k][n]

    const int tid = threadIdx.x;
    const int wid = tid >> 5, lane = tid & 31;
    const int r = lane >> 2, c = lane & 3;
    const int wm = wid & 1, wn = wid >> 1;        // 2 m-groups x 4 n-groups
    const int row0 = blockIdx.x * 128;
    const int col0 = blockIdx.y * 128;

    float acc[4][4][4];
    #pragma unroll
    for (int i = 0; i < 4; i++)
        #pragma unroll
        for (int t = 0; t < 4; t++)
            #pragma unroll
            for (int f = 0; f < 4; f++) acc[i][t][f] = 0.f;

    for (int k0 = 0; k0 < CD; k0 += 16) {
        if (k0) __syncthreads();
        {   // X tile 128x16
            int row = tid >> 1, kb = (tid & 1) << 3;
            const float* xp = X + (row0 + row) * CD + k0 + kb;
            float4 v0 = *(const float4*)xp, v1 = *(const float4*)(xp + 4);
            float vv[8] = {v0.x, v0.y, v0.z, v0.w, v1.x, v1.y, v1.z, v1.w};
            #pragma unroll
            for (int d = 0; d < 8; d++) {
                uint32_t h, l; tf32_split(vv[d], h, l);
                xhi[row][kb + d] = __uint_as_float(h);
                xlo[row][kb + d] = __uint_as_float(l);
            }
        }
        {   // W tile 16x128
            int kk = tid >> 4, nb = (tid & 15) << 3;
            const float* wp = W + (k0 + kk) * HQ + col0 + nb;
            float4 v0 = *(const float4*)wp, v1 = *(const float4*)(wp + 4);
            float vv[8] = {v0.x, v0.y, v0.z, v0.w, v1.x, v1.y, v1.z, v1.w};
            #pragma unroll
            for (int d = 0; d < 8; d++) {
                uint32_t h, l; tf32_split(vv[d], h, l);
                whi[kk][nb + d] = __uint_as_float(h);
                wlo[kk][nb + d] = __uint_as_float(l);
            }
        }
        __syncthreads();

        #pragma unroll
        for (int s = 0; s < 2; s++) {
            uint32_t ah[4][4], al[4][4];
            #pragma unroll
            for (int i = 0; i < 4; i++) {
                int mb = wm*64 + i*16;
                ah[i][0] = __float_as_uint(xhi[mb + r    ][s*8 + c    ]);
                ah[i][1] = __float_as_uint(xhi[mb + r + 8][s*8 + c    ]);
                ah[i][2] = __float_as_uint(xhi[mb + r    ][s*8 + c + 4]);
                ah[i][3] = __float_as_uint(xhi[mb + r + 8][s*8 + c + 4]);
                al[i][0] = __float_as_uint(xlo[mb + r    ][s*8 + c    ]);
                al[i][1] = __float_as_uint(xlo[mb + r + 8][s*8 + c    ]);
                al[i][2] = __float_as_uint(xlo[mb + r    ][s*8 + c + 4]);
                al[i][3] = __float_as_uint(xlo[mb + r + 8][s*8 + c + 4]);
            }
            uint32_t bh_[4][2], bl_[4][2];
            #pragma unroll
            for (int t = 0; t < 4; t++) {
                int nb = wn*32 + t*8;
                bh_[t][0] = __float_as_uint(whi[s*8 + c    ][nb + r]);
                bh_[t][1] = __float_as_uint(whi[s*8 + c + 4][nb + r]);
                bl_[t][0] = __float_as_uint(wlo[s*8 + c    ][nb + r]);
                bl_[t][1] = __float_as_uint(wlo[s*8 + c + 4][nb + r]);
            }
            #pragma unroll
            for (int i = 0; i < 4; i++)
                #pragma unroll
                for (int t = 0; t < 4; t++) {
                    mma8(acc[i][t], ah[i], bh_[t]);
                    mma8(acc[i][t], ah[i], bl_[t]);
                    mma8(acc[i][t], al[i], bh_[t]);
                }
        }
    }

    // Epilogue: BN + route to g_Q / g_Kd / g_V
    #pragma unroll
    for (int t = 0; t < 4; t++) {
        #pragma unroll
        for (int p = 0; p < 2; p++) {
            int co = col0 + wn*32 + t*8 + 2*c + p;
            float sc = gamma[co] * rsqrtf(var[co] + EPS);
            float bi = beta[co] - mean[co] * sc;
            int h = co >> 6, rr = co & 63;
            #pragma unroll
            for (int i = 0; i < 4; i++) {
                #pragma unroll
                for (int half = 0; half < 2; half++) {
                    float v = acc[i][t][half*2 + p] * sc + bi;
                    int m = row0 + wm*64 + i*16 + r + half*8;
                    int b = m >> 10, n = m & 1023;
                    if (rr < KD)        g_Q [((b*NH + h)*NT + n)*KD + rr]      = v * QSCALE;
                    else if (rr < 2*KD) g_Kd[((b*NH + h)*NT + n)*KD + rr - KD] = v;
                    else                g_V [(b*NT + n)*CD + h*HD + rr - 2*KD] = v;
                }
            }
        }
    }
}

// ---------------------------------------------------------------------------
// Kernel 2: depthwise 3x3 PE conv on V (NHWC, float4 channels) + BN -> g_pe
// ---------------------------------------------------------------------------
__global__ __launch_bounds__(256) void pe_kernel(
    const float* __restrict__ pw, const float* __restrict__ gamma,
    const float* __restrict__ beta, const float* __restrict__ mean,
    const float* __restrict__ var)
{
    const int idx = blockIdx.x * 256 + threadIdx.x;      // (b,i,j,c4)
    const int c4 = idx & 63;
    const int j  = (idx >> 6) & 31;
    const int i  = (idx >> 11) & 31;
    const int b  = idx >> 16;
    const int c  = c4 << 2;

    float4 acc = make_float4(0.f, 0.f, 0.f, 0.f);
    #pragma unroll
    for (int kh = 0; kh < 3; kh++) {
        int ii = i + kh - 1;
        if (ii < 0 || ii > 31) continue;
        #pragma unroll
        for (int kw = 0; kw < 3; kw++) {
            int jj = j + kw - 1;
            if (jj < 0 || jj > 31) continue;
            float4 v = *(const float4*)(g_V + (b*NT + ii*32 + jj)*CD + c);
            float4 w = *(const float4*)(pw + (kh*3 + kw)*CD + c);
            acc.x += v.x * w.x; acc.y += v.y * w.y;
            acc.z += v.z * w.z; acc.w += v.w * w.w;
        }
    }
    float4 g = *(const float4*)(gamma + c);
    float4 vr = *(const float4*)(var + c);
    float4 be = *(const float4*)(beta + c);
    float4 mn = *(const float4*)(mean + c);
    float4 o;
    float s;
    s = g.x * rsqrtf(vr.x + EPS); o.x = acc.x * s + (be.x - mn.x * s);
    s = g.y * rsqrtf(vr.y + EPS); o.y = acc.y * s + (be.y - mn.y * s);
    s = g.z * rsqrtf(vr.z + EPS); o.z = acc.z * s + (be.z - mn.z * s);
    s = g.w * rsqrtf(vr.w + EPS); o.w = acc.w * s + (be.w - mn.w * s);
    *(float4*)(g_pe + ((b*NT) + i*32 + j)*CD + c) = o;
}

// ---------------------------------------------------------------------------
// Kernel 3: rinv[n] = 1 / sum_m exp(S[n,m]) via 3xtf32 mma.
// Block: (bh) x 128 n; 8 warps x 16 n. Sweep m in 64-chunks, K split at staging.
// ---------------------------------------------------------------------------
__global__ __launch_bounds__(256) void rowstats_mma_kernel()
{
    __shared__ float khi[64][20], klo[64][20];

    const int tid = threadIdx.x;
    const int wid = tid >> 5, lane = tid & 31;
    const int r = lane >> 2, c = lane & 3;
    const int bh = blockIdx.y;
    const int nb0 = blockIdx.x * 128;

    // A-frags: Q rows (constant across the m sweep), 3x split
    uint32_t qh[2][4], ql[2][4];
    {
        const float* Qb = g_Q + (bh*NT + nb0 + wid*16)*KD;
        #pragma unroll
        for (int s = 0; s < 2; s++) {
            tf32_split(Qb[ r     *KD + s*8 + c    ], qh[s][0], ql[s][0]);
            tf32_split(Qb[(r + 8)*KD + s*8 + c    ], qh[s][1], ql[s][1]);
            tf32_split(Qb[ r     *KD + s*8 + c + 4], qh[s][2], ql[s][2]);
            tf32_split(Qb[(r + 8)*KD + s*8 + c + 4], qh[s][3], ql[s][3]);
        }
    }

    float z0 = 0.f, z1 = 0.f;

    for (int mc = 0; mc < NT; mc += 64) {
        if (mc) __syncthreads();
        {   // stage K chunk 64x16, split hi/lo
            int m = tid >> 2, kb = (tid & 3) << 2;
            float4 v = *(const float4*)(g_Kd + (bh*NT + mc + m)*KD + kb);
            float vv[4] = {v.x, v.y, v.z, v.w};
            #pragma unroll
            for (int d = 0; d < 4; d++) {
                uint32_t h, l; tf32_split(vv[d], h, l);
                khi[m][kb + d] = __uint_as_float(h);
                klo[m][kb + d] = __uint_as_float(l);
            }
        }
        __syncthreads();

        #pragma unroll
        for (int t = 0; t < 8; t++) {
            float d4[4] = {0.f, 0.f, 0.f, 0.f};
            #pragma unroll
            for (int s = 0; s < 2; s++) {
                uint32_t bh_[2], bl_[2];
                bh_[0] = __float_as_uint(khi[t*8 + r][s*8 + c    ]);
                bh_[1] = __float_as_uint(khi[t*8 + r][s*8 + c + 4]);
                bl_[0] = __float_as_uint(klo[t*8 + r][s*8 + c    ]);
                bl_[1] = __float_as_uint(klo[t*8 + r][s*8 + c + 4]);
                mma8(d4, qh[s], bh_);
                mma8(d4, qh[s], bl_);
                mma8(d4, ql[s], bh_);
            }
            z0 += ex2f(d4[0]) + ex2f(d4[1]);
            z1 += ex2f(d4[2]) + ex2f(d4[3]);
        }
    }

    // reduce over the 4 c-lanes (lane = r*4 + c)
    z0 += __shfl_xor_sync(0xffffffffu, z0, 1);
    z0 += __shfl_xor_sync(0xffffffffu, z0, 2);
    z1 += __shfl_xor_sync(0xffffffffu, z1, 1);
    z1 += __shfl_xor_sync(0xffffffffu, z1, 2);
    if (c == 0) {
        g_rinv[bh*NT + nb0 + wid*16 + r    ] = 1.0f / z0;
        g_rinv[bh*NT + nb0 + wid*16 + r + 8] = 1.0f / z1;
    }
}

// ---------------------------------------------------------------------------
// Kernel 4: pv via mma.sync tf32 (validated round-7 version, unchanged).
// ---------------------------------------------------------------------------
__global__ __launch_bounds__(256) void pv_kernel()
{
    __shared__ float ps[64][132];   // P[n][m] (tf32 bits)
    __shared__ float vsm[64][40];   // V'[n][d] (tf32 bits)
    __shared__ float qs[64][20];    // Q chunk fp32

    const int tid = threadIdx.x;
    const int wid = tid >> 5, lane = tid & 31;
    const int bh = blockIdx.y;
    const int b = bh >> 3, h = bh & 7;
    const int m0 = blockIdx.x * 128;
    const int r = lane >> 2;
    const int c = lane & 3;

    uint32_t khi[2][4], klo[2][4];
    {
        const float* Kb = g_Kd + (bh*NT + m0 + wid*16)*KD;
        #pragma unroll
        for (int s = 0; s < 2; s++) {
            tf32_split(Kb[ r     *KD + s*8 + c    ], khi[s][0], klo[s][0]);
            tf32_split(Kb[(r + 8)*KD + s*8 + c    ], khi[s][1], klo[s][1]);
            tf32_split(Kb[ r     *KD + s*8 + c + 4], khi[s][2], klo[s][2]);
            tf32_split(Kb[(r + 8)*KD + s*8 + c + 4], khi[s][3], klo[s][3]);
        }
    }

    float acc[4][4];
    #pragma unroll
    for (int t = 0; t < 4; t++)
        #pragma unroll
        for (int j = 0; j < 4; j++) acc[t][j] = 0.f;

    for (int ci = 0; ci < 16; ci++) {
        const int nc = ci << 6;
        if (ci > 0) __syncthreads();

        {
            int n = tid >> 2, j4 = (tid & 3) << 2;
            *(float4*)(&qs[n][j4]) = *(const float4*)(g_Q + (bh*NT + nc + n)*KD + j4);
        }
        {
            int n = tid & 63, dq = tid >> 6;
            float ri = g_rinv[bh*NT + nc + n];
            const float* vb = g_V + (b*NT + nc + n)*CD + h*HD + dq*8;
            float4 v0 = *(const float4*)(vb);
            float4 v1 = *(const float4*)(vb + 4);
            float vv[8] = {v0.x, v0.y, v0.z, v0.w, v1.x, v1.y, v1.z, v1.w};
            #pragma unroll
            for (int dd = 0; dd < 8; dd++)
                vsm[n][dq*8 + dd] = __uint_as_float(tf32r(vv[dd] * ri));
        }
        __syncthreads();

        #pragma unroll
        for (int t = 0; t < 8; t++) {
            float d4[4] = {0.f, 0.f, 0.f, 0.f};
            #pragma unroll
            for (int s = 0; s < 2; s++) {
                float b0f = qs[t*8 + r][s*8 + c];
                float b1f = qs[t*8 + r][s*8 + c + 4];
                uint32_t bh2[2], bl2[2];
                tf32_split(b0f, bh2[0], bl2[0]);
                tf32_split(b1f, bh2[1], bl2[1]);
                mma8(d4, khi[s], bh2);
                mma8(d4, khi[s], bl2);
                mma8(d4, klo[s], bh2);
            }
            int n0 = t*8 + 2*c;
            int mA = wid*16 + r;
            ps[n0    ][mA    ] = __uint_as_float(tf32r(ex2f(d4[0])));
            ps[n0 + 1][mA    ] = __uint_as_float(tf32r(ex2f(d4[1])));
            ps[n0    ][mA + 8] = __uint_as_float(tf32r(ex2f(d4[2])));
            ps[n0 + 1][mA + 8] = __uint_as_float(tf32r(ex2f(d4[3])));
        }
        __syncthreads();

        #pragma unroll
        for (int s = 0; s < 8; s++) {
            uint32_t a[4];
            a[0] = __float_as_uint(ps[s*8 + c    ][wid*16 + r    ]);
            a[1] = __float_as_uint(ps[s*8 + c    ][wid*16 + r + 8]);
            a[2] = __float_as_uint(ps[s*8 + c + 4][wid*16 + r    ]);
            a[3] = __float_as_uint(ps[s*8 + c + 4][wid*16 + r + 8]);
            #pragma unroll
            for (int t = 0; t < 4; t++) {
                uint32_t bb[2];
                bb[0] = __float_as_uint(vsm[s*8 + c    ][t*8 + r]);
                bb[1] = __float_as_uint(vsm[s*8 + c + 4][t*8 + r]);
                mma8(acc[t], a, bb);
            }
        }
    }

    const int gm = m0 + wid*16 + r;
    const int wq = (h << 2) + (m0 >> 8);
    const int cc0 = gm & 255;
    #pragma unroll
    for (int t = 0; t < 4; t++) {
        int d0 = t*8 + 2*c;
        g_mid[((b*32 + d0    )*32 + wq)*CD + cc0    ] = acc[t][0];
        g_mid[((b*32 + d0 + 1)*32 + wq)*CD + cc0    ] = acc[t][1];
        g_mid[((b*32 + d0    )*32 + wq)*CD + cc0 + 8] = acc[t][2];
        g_mid[((b*32 + d0 + 1)*32 + wq)*CD + cc0 + 8] = acc[t][3];
    }
}

// ---------------------------------------------------------------------------
// Kernel 5: Proj GEMM [8192x256]x[256x256] on (mid+pe) via 3xtf32 mma + BN.
// ---------------------------------------------------------------------------
__global__ __launch_bounds__(256) void proj_mma_kernel(
    const float* __restrict__ W, const float* __restrict__ gamma,
    const float* __restrict__ beta, const float* __restrict__ mean,
    const float* __restrict__ var, float* __restrict__ out)
{
    __shared__ float xhi[128][20], xlo[128][20];
    __shared__ float whi[16][136], wlo[16][136];

    const int tid = threadIdx.x;
    const int wid = tid >> 5, lane = tid & 31;
    const int r = lane >> 2, c = lane & 3;
    const int wm = wid & 1, wn = wid >> 1;
    const int row0 = blockIdx.x * 128;
    const int col0 = blockIdx.y * 128;

    float acc[4][4][4];
    #pragma unroll
    for (int i = 0; i < 4; i++)
        #pragma unroll
        for (int t = 0; t < 4; t++)
            #pragma unroll
            for (int f = 0; f < 4; f++) acc[i][t][f] = 0.f;

    for (int k0 = 0; k0 < CD; k0 += 16) {
        if (k0) __syncthreads();
        {   // A tile = mid + pe
            int row = tid >> 1, kb = (tid & 1) << 3;
            const int off = (row0 + row) * CD + k0 + kb;
            float4 v0 = *(const float4*)(g_mid + off);
            float4 v1 = *(const float4*)(g_mid + off + 4);
            float4 p0 = *(const float4*)(g_pe + off);
            float4 p1 = *(const float4*)(g_pe + off + 4);
            float vv[8] = {v0.x + p0.x, v0.y + p0.y, v0.z + p0.z, v0.w + p0.w,
                           v1.x + p1.x, v1.y + p1.y, v1.z + p1.z, v1.w + p1.w};
            #pragma unroll
            for (int d = 0; d < 8; d++) {
                uint32_t h, l; tf32_split(vv[d], h, l);
                xhi[row][kb + d] = __uint_as_float(h);
                xlo[row][kb + d] = __uint_as_float(l);
            }
        }
        {
            int kk = tid >> 4, nb = (tid & 15) << 3;
            const float* wp = W + (k0 + kk) * CD + col0 + nb;
            float4 v0 = *(const float4*)wp, v1 = *(const float4*)(wp + 4);
            float vv[8] = {v0.x, v0.y, v0.z, v0.w, v1.x, v1.y, v1.z, v1.w};
            #pragma unroll
            for (int d = 0; d < 8; d++) {
                uint32_t h, l; tf32_split(vv[d], h, l);
                whi[kk][nb + d] = __uint_as_float(h);
                wlo[kk][nb + d] = __uint_as_float(l);
            }
        }
        __syncthreads();

        #pragma unroll
        for (int s = 0; s < 2; s++) {
            uint32_t ah[4][4], al[4][4];
            #pragma unroll
            for (int i = 0; i < 4; i++) {
                int mb = wm*64 + i*16;
                ah[i][0] = __float_as_uint(xhi[mb + r    ][s*8 + c    ]);
                ah[i][1] = __float_as_uint(xhi[mb + r + 8][s*8 + c    ]);
                ah[i][2] = __float_as_uint(xhi[mb + r    ][s*8 + c + 4]);
                ah[i][3] = __float_as_uint(xhi[mb + r + 8][s*8 + c + 4]);
                al[i][0] = __float_as_uint(xlo[mb + r    ][s*8 + c    ]);
                al[i][1] = __float_as_uint(xlo[mb + r + 8][s*8 + c    ]);
                al[i][2] = __float_as_uint(xlo[mb + r    ][s*8 + c + 4]);
                al[i][3] = __float_as_uint(xlo[mb + r + 8][s*8 + c + 4]);
            }
            uint32_t bh_[4][2], bl_[4][2];
            #pragma unroll
            for (int t = 0; t < 4; t++) {
                int nb = wn*32 + t*8;
                bh_[t][0] = __float_as_uint(whi[s*8 + c    ][nb + r]);
                bh_[t][1] = __float_as_uint(whi[s*8 + c + 4][nb + r]);
                bl_[t][0] = __float_as_uint(wlo[s*8 + c    ][nb + r]);
                bl_[t][1] = __float_as_uint(wlo[s*8 + c + 4][nb + r]);
            }
            #pragma unroll
            for (int i = 0; i < 4; i++)
                #pragma unroll
                for (int t = 0; t < 4; t++) {
                    mma8(acc[i][t], ah[i], bh_[t]);
                    mma8(acc[i][t], ah[i], bl_[t]);
                    mma8(acc[i][t], al[i], bh_[t]);
                }
        }
    }

    #pragma unroll
    for (int t = 0; t < 4; t++) {
        #pragma unroll
        for (int p = 0; p < 2; p++) {
            int co = col0 + wn*32 + t*8 + 2*c + p;
            float sc = gamma[co] * rsqrtf(var[co] + EPS);
            float bi = beta[co] - mean[co] * sc;
            #pragma unroll
            for (int i = 0; i < 4; i++) {
                #pragma unroll
                for (int half = 0; half < 2; half++) {
                    float v = acc[i][t][half*2 + p] * sc + bi;
                    int m = row0 + wm*64 + i*16 + r + half*8;
                    out[m*CD + co] = v;
                }
            }
        }
    }
}

// ---------------------------------------------------------------------------
extern "C" void kernel_launch(void* const* d_in, const int* in_sizes, int n_in,
                              void* d_out, int out_size)
{
    const float* inputs   = (const float*)d_in[0];
    const float* qkv_w    = (const float*)d_in[1];
    const float* qkv_g    = (const float*)d_in[2];
    const float* qkv_b    = (const float*)d_in[3];
    const float* qkv_m    = (const float*)d_in[4];
    const float* qkv_v    = (const float*)d_in[5];
    const float* pe_w     = (const float*)d_in[6];
    const float* pe_g     = (const float*)d_in[7];
    const float* pe_b     = (const float*)d_in[8];
    const float* pe_m     = (const float*)d_in[9];
    const float* pe_v     = (const float*)d_in[10];
    const float* proj_w   = (const float*)d_in[11];
    const float* proj_g   = (const float*)d_in[12];
    const float* proj_b   = (const float*)d_in[13];
    const float* proj_m   = (const float*)d_in[14];
    const float* proj_v   = (const float*)d_in[15];
    float* out = (float*)d_out;

    qkv_mma_kernel<<<dim3(64, 4), 256>>>(inputs, qkv_w, qkv_g, qkv_b, qkv_m, qkv_v);
    pe_kernel<<<2048, 256>>>(pe_w, pe_g, pe_b, pe_m, pe_v);
    rowstats_mma_kernel<<<dim3(8, 64), 256>>>();
    pv_kernel<<<dim3(8, 64), 256>>>();
    proj_mma_kernel<<<dim3(64, 2), 256>>>(proj_w, proj_g, proj_b, proj_m, proj_v, out);
}

// round 12
// speedup vs baseline: 1.8053x; 1.0472x over previous
#include <cuda_runtime.h>
#include <cstdint>

#define NB 8
#define NH 8
#define NT 1024
#define CD 256
#define KD 16
#define HD 32
#define HQ 512
#define EPS 0.001f
// 0.25 * log2(e) folded into Q so exp(S) == ex2(S')
#define QSCALE 0.36067376022224085f

typedef unsigned long long u64;

__device__ __forceinline__ float ex2f(float x) {
    float y; asm("ex2.approx.f32 %0,%1;" : "=f"(y) : "f"(x)); return y;
}
__device__ __forceinline__ uint32_t tf32r(float x) {
    uint32_t h; asm("cvt.rna.tf32.f32 %0, %1;" : "=r"(h) : "f"(x)); return h;
}
__device__ __forceinline__ void tf32_split(float x, uint32_t& hi, uint32_t& lo) {
    uint32_t h; asm("cvt.rna.tf32.f32 %0, %1;" : "=r"(h) : "f"(x));
    float lf = x - __uint_as_float(h);
    uint32_t l; asm("cvt.rna.tf32.f32 %0, %1;" : "=r"(l) : "f"(lf));
    hi = h; lo = l;
}
// D(16x8) += A(16x8) * B(8x8), tf32 inputs, f32 accum
__device__ __forceinline__ void mma8(float* d, const uint32_t* a, const uint32_t* b) {
    asm volatile(
        "mma.sync.aligned.m16n8k8.row.col.f32.tf32.tf32.f32 "
        "{%0,%1,%2,%3},{%4,%5,%6,%7},{%8,%9},{%0,%1,%2,%3};"
        : "+f"(d[0]), "+f"(d[1]), "+f"(d[2]), "+f"(d[3])
        : "r"(a[0]), "r"(a[1]), "r"(a[2]), "r"(a[3]), "r"(b[0]), "r"(b[1]));
}

// Scratch (static device globals; no allocations allowed)
__device__ float g_Q[NB*NH*NT*KD];     // q * 0.25*log2e, [b][h][n][16]
__device__ float g_Kd[NB*NH*NT*KD];    // [b][h][n][16]
__device__ float g_V[NB*NT*CD];        // NHWC, c = h*32+d
__device__ float g_rinv[NB*NH*NT];     // 1 / sum_m exp(S[n,m])
__device__ float g_mid[NB*NT*CD];      // attn out (scrambled layout)
__device__ float g_pe[NB*NT*CD];       // BN(dwconv(V))

// ---------------------------------------------------------------------------
// Kernel 1: QKV GEMM [8192x256]x[256x512] via 3xtf32 mma, BN folded, routed.
// ---------------------------------------------------------------------------
__global__ __launch_bounds__(256) void qkv_mma_kernel(
    const float* __restrict__ X, const float* __restrict__ W,
    const float* __restrict__ gamma, const float* __restrict__ beta,
    const float* __restrict__ mean, const float* __restrict__ var)
{
    __shared__ float xhi[128][20], xlo[128][20];   // A tile [m][k]
    __shared__ float whi[16][136], wlo[16][136];   // B tile [k][n]

    const int tid = threadIdx.x;
    const int wid = tid >> 5, lane = tid & 31;
    const int r = lane >> 2, c = lane & 3;
    const int wm = wid & 1, wn = wid >> 1;        // 2 m-groups x 4 n-groups
    const int row0 = blockIdx.x * 128;
    const int col0 = blockIdx.y * 128;

    float acc[4][4][4];
    #pragma unroll
    for (int i = 0; i < 4; i++)
        #pragma unroll
        for (int t = 0; t < 4; t++)
            #pragma unroll
            for (int f = 0; f < 4; f++) acc[i][t][f] = 0.f;

    for (int k0 = 0; k0 < CD; k0 += 16) {
        if (k0) __syncthreads();
        {   // X tile 128x16
            int row = tid >> 1, kb = (tid & 1) << 3;
            const float* xp = X + (row0 + row) * CD + k0 + kb;
            float4 v0 = *(const float4*)xp, v1 = *(const float4*)(xp + 4);
            float vv[8] = {v0.x, v0.y, v0.z, v0.w, v1.x, v1.y, v1.z, v1.w};
            #pragma unroll
            for (int d = 0; d < 8; d++) {
                uint32_t h, l; tf32_split(vv[d], h, l);
                xhi[row][kb + d] = __uint_as_float(h);
                xlo[row][kb + d] = __uint_as_float(l);
            }
        }
        {   // W tile 16x128
            int kk = tid >> 4, nb = (tid & 15) << 3;
            const float* wp = W + (k0 + kk) * HQ + col0 + nb;
            float4 v0 = *(const float4*)wp, v1 = *(const float4*)(wp + 4);
            float vv[8] = {v0.x, v0.y, v0.z, v0.w, v1.x, v1.y, v1.z, v1.w};
            #pragma unroll
            for (int d = 0; d < 8; d++) {
                uint32_t h, l; tf32_split(vv[d], h, l);
                whi[kk][nb + d] = __uint_as_float(h);
                wlo[kk][nb + d] = __uint_as_float(l);
            }
        }
        __syncthreads();

        #pragma unroll
        for (int s = 0; s < 2; s++) {
            uint32_t ah[4][4], al[4][4];
            #pragma unroll
            for (int i = 0; i < 4; i++) {
                int mb = wm*64 + i*16;
                ah[i][0] = __float_as_uint(xhi[mb + r    ][s*8 + c    ]);
                ah[i][1] = __float_as_uint(xhi[mb + r + 8][s*8 + c    ]);
                ah[i][2] = __float_as_uint(xhi[mb + r    ][s*8 + c + 4]);
                ah[i][3] = __float_as_uint(xhi[mb + r + 8][s*8 + c + 4]);
                al[i][0] = __float_as_uint(xlo[mb + r    ][s*8 + c    ]);
                al[i][1] = __float_as_uint(xlo[mb + r + 8][s*8 + c    ]);
                al[i][2] = __float_as_uint(xlo[mb + r    ][s*8 + c + 4]);
                al[i][3] = __float_as_uint(xlo[mb + r + 8][s*8 + c + 4]);
            }
            uint32_t bh_[4][2], bl_[4][2];
            #pragma unroll
            for (int t = 0; t < 4; t++) {
                int nb = wn*32 + t*8;
                bh_[t][0] = __float_as_uint(whi[s*8 + c    ][nb + r]);
                bh_[t][1] = __float_as_uint(whi[s*8 + c + 4][nb + r]);
                bl_[t][0] = __float_as_uint(wlo[s*8 + c    ][nb + r]);
                bl_[t][1] = __float_as_uint(wlo[s*8 + c + 4][nb + r]);
            }
            #pragma unroll
            for (int i = 0; i < 4; i++)
                #pragma unroll
                for (int t = 0; t < 4; t++) {
                    mma8(acc[i][t], ah[i], bh_[t]);
                    mma8(acc[i][t], ah[i], bl_[t]);
                    mma8(acc[i][t], al[i], bh_[t]);
                }
        }
    }

    // Epilogue: BN + route to g_Q / g_Kd / g_V
    #pragma unroll
    for (int t = 0; t < 4; t++) {
        #pragma unroll
        for (int p = 0; p < 2; p++) {
            int co = col0 + wn*32 + t*8 + 2*c + p;
            float sc = gamma[co] * rsqrtf(var[co] + EPS);
            float bi = beta[co] - mean[co] * sc;
            int h = co >> 6, rr = co & 63;
            #pragma unroll
            for (int i = 0; i < 4; i++) {
                #pragma unroll
                for (int half = 0; half < 2; half++) {
                    float v = acc[i][t][half*2 + p] * sc + bi;
                    int m = row0 + wm*64 + i*16 + r + half*8;
                    int b = m >> 10, n = m & 1023;
                    if (rr < KD)        g_Q [((b*NH + h)*NT + n)*KD + rr]      = v * QSCALE;
                    else if (rr < 2*KD) g_Kd[((b*NH + h)*NT + n)*KD + rr - KD] = v;
                    else                g_V [(b*NT + n)*CD + h*HD + rr - 2*KD] = v;
                }
            }
        }
    }
}

// ---------------------------------------------------------------------------
// Kernel 2: depthwise 3x3 PE conv on V (NHWC, float4 channels) + BN -> g_pe
// ---------------------------------------------------------------------------
__global__ __launch_bounds__(256) void pe_kernel(
    const float* __restrict__ pw, const float* __restrict__ gamma,
    const float* __restrict__ beta, const float* __restrict__ mean,
    const float* __restrict__ var)
{
    const int idx = blockIdx.x * 256 + threadIdx.x;      // (b,i,j,c4)
    const int c4 = idx & 63;
    const int j  = (idx >> 6) & 31;
    const int i  = (idx >> 11) & 31;
    const int b  = idx >> 16;
    const int c  = c4 << 2;

    float4 acc = make_float4(0.f, 0.f, 0.f, 0.f);
    #pragma unroll
    for (int kh = 0; kh < 3; kh++) {
        int ii = i + kh - 1;
        if (ii < 0 || ii > 31) continue;
        #pragma unroll
        for (int kw = 0; kw < 3; kw++) {
            int jj = j + kw - 1;
            if (jj < 0 || jj > 31) continue;
            float4 v = *(const float4*)(g_V + (b*NT + ii*32 + jj)*CD + c);
            float4 w = *(const float4*)(pw + (kh*3 + kw)*CD + c);
            acc.x += v.x * w.x; acc.y += v.y * w.y;
            acc.z += v.z * w.z; acc.w += v.w * w.w;
        }
    }
    float4 g = *(const float4*)(gamma + c);
    float4 vr = *(const float4*)(var + c);
    float4 be = *(const float4*)(beta + c);
    float4 mn = *(const float4*)(mean + c);
    float4 o;
    float s;
    s = g.x * rsqrtf(vr.x + EPS); o.x = acc.x * s + (be.x - mn.x * s);
    s = g.y * rsqrtf(vr.y + EPS); o.y = acc.y * s + (be.y - mn.y * s);
    s = g.z * rsqrtf(vr.z + EPS); o.z = acc.z * s + (be.z - mn.z * s);
    s = g.w * rsqrtf(vr.w + EPS); o.w = acc.w * s + (be.w - mn.w * s);
    *(float4*)(g_pe + ((b*NT) + i*32 + j)*CD + c) = o;
}

// ---------------------------------------------------------------------------
// Kernel 3: rinv[n] = 1 / sum_m exp(S[n,m]) via 3xtf32 mma.
// ---------------------------------------------------------------------------
__global__ __launch_bounds__(256) void rowstats_mma_kernel()
{
    __shared__ float khi[64][20], klo[64][20];

    const int tid = threadIdx.x;
    const int wid = tid >> 5, lane = tid & 31;
    const int r = lane >> 2, c = lane & 3;
    const int bh = blockIdx.y;
    const int nb0 = blockIdx.x * 128;

    uint32_t qh[2][4], ql[2][4];
    {
        const float* Qb = g_Q + (bh*NT + nb0 + wid*16)*KD;
        #pragma unroll
        for (int s = 0; s < 2; s++) {
            tf32_split(Qb[ r     *KD + s*8 + c    ], qh[s][0], ql[s][0]);
            tf32_split(Qb[(r + 8)*KD + s*8 + c    ], qh[s][1], ql[s][1]);
            tf32_split(Qb[ r     *KD + s*8 + c + 4], qh[s][2], ql[s][2]);
            tf32_split(Qb[(r + 8)*KD + s*8 + c + 4], qh[s][3], ql[s][3]);
        }
    }

    float z0 = 0.f, z1 = 0.f;

    for (int mc = 0; mc < NT; mc += 64) {
        if (mc) __syncthreads();
        {
            int m = tid >> 2, kb = (tid & 3) << 2;
            float4 v = *(const float4*)(g_Kd + (bh*NT + mc + m)*KD + kb);
            float vv[4] = {v.x, v.y, v.z, v.w};
            #pragma unroll
            for (int d = 0; d < 4; d++) {
                uint32_t h, l; tf32_split(vv[d], h, l);
                khi[m][kb + d] = __uint_as_float(h);
                klo[m][kb + d] = __uint_as_float(l);
            }
        }
        __syncthreads();

        #pragma unroll
        for (int t = 0; t < 8; t++) {
            float d4[4] = {0.f, 0.f, 0.f, 0.f};
            #pragma unroll
            for (int s = 0; s < 2; s++) {
                uint32_t bh_[2], bl_[2];
                bh_[0] = __float_as_uint(khi[t*8 + r][s*8 + c    ]);
                bh_[1] = __float_as_uint(khi[t*8 + r][s*8 + c + 4]);
                bl_[0] = __float_as_uint(klo[t*8 + r][s*8 + c    ]);
                bl_[1] = __float_as_uint(klo[t*8 + r][s*8 + c + 4]);
                mma8(d4, qh[s], bh_);
                mma8(d4, qh[s], bl_);
                mma8(d4, ql[s], bh_);
            }
            z0 += ex2f(d4[0]) + ex2f(d4[1]);
            z1 += ex2f(d4[2]) + ex2f(d4[3]);
        }
    }

    z0 += __shfl_xor_sync(0xffffffffu, z0, 1);
    z0 += __shfl_xor_sync(0xffffffffu, z0, 2);
    z1 += __shfl_xor_sync(0xffffffffu, z1, 1);
    z1 += __shfl_xor_sync(0xffffffffu, z1, 2);
    if (c == 0) {
        g_rinv[bh*NT + nb0 + wid*16 + r    ] = 1.0f / z0;
        g_rinv[bh*NT + nb0 + wid*16 + r + 8] = 1.0f / z1;
    }
}

// ---------------------------------------------------------------------------
// Kernel 4: pv, fused via warp-shuffle fragment transpose (no ps smem tile).
//   Per chunk: stage Q (pre-split hi/lo) + V' (d-major, conflict-free);
//   per 8-n tile: S-mma(3xtf32) -> ex2 -> shfl D-frag->A-frag -> 4 O-mmas.
//   Double-buffered staging, ONE __syncthreads per chunk.
// ---------------------------------------------------------------------------
__global__ __launch_bounds__(256) void pv_kernel()
{
    __shared__ float qhi[2][64][20];   // Q hi, fp32-bit tf32   (10240 B)
    __shared__ float qlo[2][64][20];   // Q lo                  (10240 B)
    __shared__ float vsm[2][32][68];   // V' d-major, tf32 bits (17408 B)

    const int tid = threadIdx.x;
    const int wid = tid >> 5, lane = tid & 31;
    const int bh = blockIdx.y;
    const int b = bh >> 3, h = bh & 7;
    const int m0 = blockIdx.x * 128;
    const int r = lane >> 2;
    const int c = lane & 3;
    const int srcA = (lane & ~3) | (c >> 1);
    const int srcB = srcA + 2;
    const bool odd = (c & 1);

    // K fragments (persistent), 3x split
    uint32_t khi_[2][4], klo_[2][4];
    {
        const float* Kb = g_Kd + (bh*NT + m0 + wid*16)*KD;
        #pragma unroll
        for (int s = 0; s < 2; s++) {
            tf32_split(Kb[ r     *KD + s*8 + c    ], khi_[s][0], klo_[s][0]);
            tf32_split(Kb[(r + 8)*KD + s*8 + c    ], khi_[s][1], klo_[s][1]);
            tf32_split(Kb[ r     *KD + s*8 + c + 4], khi_[s][2], klo_[s][2]);
            tf32_split(Kb[(r + 8)*KD + s*8 + c + 4], khi_[s][3], klo_[s][3]);
        }
    }

    float acc[4][4];
    #pragma unroll
    for (int t = 0; t < 4; t++)
        #pragma unroll
        for (int j = 0; j < 4; j++) acc[t][j] = 0.f;

    const int qn = tid >> 2, qj = (tid & 3) << 2;   // Q staging: 4 vals/thread
    const int vn = tid & 63, vdq = tid >> 6;        // V staging: 8 d/thread

    for (int ci = 0; ci < 16; ci++) {
        const int nc = ci << 6;
        const int buf = ci & 1;

        {   // stage Q chunk [64 x 16], pre-split
            float4 q = *(const float4*)(g_Q + (bh*NT + nc + qn)*KD + qj);
            float qq[4] = {q.x, q.y, q.z, q.w};
            #pragma unroll
            for (int d = 0; d < 4; d++) {
                uint32_t hh, ll; tf32_split(qq[d], hh, ll);
                qhi[buf][qn][qj + d] = __uint_as_float(hh);
                qlo[buf][qn][qj + d] = __uint_as_float(ll);
            }
        }
        {   // stage V' chunk d-major [32 d][64 n], scaled by rinv (conflict-free)
            float ri = g_rinv[bh*NT + nc + vn];
            const float* vb = g_V + (b*NT + nc + vn)*CD + h*HD + vdq*8;
            float4 v0 = *(const float4*)(vb);
            float4 v1 = *(const float4*)(vb + 4);
            float vv[8] = {v0.x, v0.y, v0.z, v0.w, v1.x, v1.y, v1.z, v1.w};
            #pragma unroll
            for (int dd = 0; dd < 8; dd++)
                vsm[buf][vdq*8 + dd][vn] = __uint_as_float(tf32r(vv[dd] * ri));
        }
        __syncthreads();

        #pragma unroll
        for (int t = 0; t < 8; t++) {
            // S-mma: D[m-tile][n = t*8..t*8+8)
            float d4[4] = {0.f, 0.f, 0.f, 0.f};
            #pragma unroll
            for (int s = 0; s < 2; s++) {
                uint32_t bhq[2], blq[2];
                bhq[0] = __float_as_uint(qhi[buf][t*8 + r][s*8 + c    ]);
                bhq[1] = __float_as_uint(qhi[buf][t*8 + r][s*8 + c + 4]);
                blq[0] = __float_as_uint(qlo[buf][t*8 + r][s*8 + c    ]);
                blq[1] = __float_as_uint(qlo[buf][t*8 + r][s*8 + c + 4]);
                mma8(d4, khi_[s], bhq);
                mma8(d4, khi_[s], blq);
                mma8(d4, klo_[s], bhq);
            }
            float p0 = ex2f(d4[0]), p1 = ex2f(d4[1]);
            float p2 = ex2f(d4[2]), p3 = ex2f(d4[3]);

            // D-frag -> A-frag transpose via shuffles
            float x0 = __shfl_sync(0xffffffffu, p0, srcA);
            float x1 = __shfl_sync(0xffffffffu, p1, srcA);
            float x2 = __shfl_sync(0xffffffffu, p2, srcA);
            float x3 = __shfl_sync(0xffffffffu, p3, srcA);
            float y0 = __shfl_sync(0xffffffffu, p0, srcB);
            float y1 = __shfl_sync(0xffffffffu, p1, srcB);
            float y2 = __shfl_sync(0xffffffffu, p2, srcB);
            float y3 = __shfl_sync(0xffffffffu, p3, srcB);
            uint32_t a[4];
            a[0] = tf32r(odd ? x1 : x0);
            a[1] = tf32r(odd ? x3 : x2);
            a[2] = tf32r(odd ? y1 : y0);
            a[3] = tf32r(odd ? y3 : y2);

            // O-mma: k-block = this n tile
            #pragma unroll
            for (int dt = 0; dt < 4; dt++) {
                uint32_t bb[2];
                bb[0] = __float_as_uint(vsm[buf][dt*8 + r][t*8 + c    ]);
                bb[1] = __float_as_uint(vsm[buf][dt*8 + r][t*8 + c + 4]);
                mma8(acc[dt], a, bb);
            }
        }
    }

    // Output: acc[t][0]:(m=gm, d=t8+2c) [1]:(gm, d+1) [2]:(gm+8, d) [3]:(gm+8, d+1)
    // Scrambled: mid[b][d][w=4h+(m>>8)][c=m&255]
    const int gm = m0 + wid*16 + r;
    const int wq = (h << 2) + (m0 >> 8);
    const int cc0 = gm & 255;
    #pragma unroll
    for (int t = 0; t < 4; t++) {
        int d0 = t*8 + 2*c;
        g_mid[((b*32 + d0    )*32 + wq)*CD + cc0    ] = acc[t][0];
        g_mid[((b*32 + d0 + 1)*32 + wq)*CD + cc0    ] = acc[t][1];
        g_mid[((b*32 + d0    )*32 + wq)*CD + cc0 + 8] = acc[t][2];
        g_mid[((b*32 + d0 + 1)*32 + wq)*CD + cc0 + 8] = acc[t][3];
    }
}

// ---------------------------------------------------------------------------
// Kernel 5: Proj GEMM [8192x256]x[256x256] on (mid+pe) via 3xtf32 mma + BN.
// ---------------------------------------------------------------------------
__global__ __launch_bounds__(256) void proj_mma_kernel(
    const float* __restrict__ W, const float* __restrict__ gamma,
    const float* __restrict__ beta, const float* __restrict__ mean,
    const float* __restrict__ var, float* __restrict__ out)
{
    __shared__ float xhi[128][20], xlo[128][20];
    __shared__ float whi[16][136], wlo[16][136];

    const int tid = threadIdx.x;
    const int wid = tid >> 5, lane = tid & 31;
    const int r = lane >> 2, c = lane & 3;
    const int wm = wid & 1, wn = wid >> 1;
    const int row0 = blockIdx.x * 128;
    const int col0 = blockIdx.y * 128;

    float acc[4][4][4];
    #pragma unroll
    for (int i = 0; i < 4; i++)
        #pragma unroll
        for (int t = 0; t < 4; t++)
            #pragma unroll
            for (int f = 0; f < 4; f++) acc[i][t][f] = 0.f;

    for (int k0 = 0; k0 < CD; k0 += 16) {
        if (k0) __syncthreads();
        {   // A tile = mid + pe
            int row = tid >> 1, kb = (tid & 1) << 3;
            const int off = (row0 + row) * CD + k0 + kb;
            float4 v0 = *(const float4*)(g_mid + off);
            float4 v1 = *(const float4*)(g_mid + off + 4);
            float4 p0 = *(const float4*)(g_pe + off);
            float4 p1 = *(const float4*)(g_pe + off + 4);
            float vv[8] = {v0.x + p0.x, v0.y + p0.y, v0.z + p0.z, v0.w + p0.w,
                           v1.x + p1.x, v1.y + p1.y, v1.z + p1.z, v1.w + p1.w};
            #pragma unroll
            for (int d = 0; d < 8; d++) {
                uint32_t h, l; tf32_split(vv[d], h, l);
                xhi[row][kb + d] = __uint_as_float(h);
                xlo[row][kb + d] = __uint_as_float(l);
            }
        }
        {
            int kk = tid >> 4, nb = (tid & 15) << 3;
            const float* wp = W + (k0 + kk) * CD + col0 + nb;
            float4 v0 = *(const float4*)wp, v1 = *(const float4*)(wp + 4);
            float vv[8] = {v0.x, v0.y, v0.z, v0.w, v1.x, v1.y, v1.z, v1.w};
            #pragma unroll
            for (int d = 0; d < 8; d++) {
                uint32_t h, l; tf32_split(vv[d], h, l);
                whi[kk][nb + d] = __uint_as_float(h);
                wlo[kk][nb + d] = __uint_as_float(l);
            }
        }
        __syncthreads();

        #pragma unroll
        for (int s = 0; s < 2; s++) {
            uint32_t ah[4][4], al[4][4];
            #pragma unroll
            for (int i = 0; i < 4; i++) {
                int mb = wm*64 + i*16;
                ah[i][0] = __float_as_uint(xhi[mb + r    ][s*8 + c    ]);
                ah[i][1] = __float_as_uint(xhi[mb + r + 8][s*8 + c    ]);
                ah[i][2] = __float_as_uint(xhi[mb + r    ][s*8 + c + 4]);
                ah[i][3] = __float_as_uint(xhi[mb + r + 8][s*8 + c + 4]);
                al[i][0] = __float_as_uint(xlo[mb + r    ][s*8 + c    ]);
                al[i][1] = __float_as_uint(xlo[mb + r + 8][s*8 + c    ]);
                al[i][2] = __float_as_uint(xlo[mb + r    ][s*8 + c + 4]);
                al[i][3] = __float_as_uint(xlo[mb + r + 8][s*8 + c + 4]);
            }
            uint32_t bh_[4][2], bl_[4][2];
            #pragma unroll
            for (int t = 0; t < 4; t++) {
                int nb = wn*32 + t*8;
                bh_[t][0] = __float_as_uint(whi[s*8 + c    ][nb + r]);
                bh_[t][1] = __float_as_uint(whi[s*8 + c + 4][nb + r]);
                bl_[t][0] = __float_as_uint(wlo[s*8 + c    ][nb + r]);
                bl_[t][1] = __float_as_uint(wlo[s*8 + c + 4][nb + r]);
            }
            #pragma unroll
            for (int i = 0; i < 4; i++)
                #pragma unroll
                for (int t = 0; t < 4; t++) {
                    mma8(acc[i][t], ah[i], bh_[t]);
                    mma8(acc[i][t], ah[i], bl_[t]);
                    mma8(acc[i][t], al[i], bh_[t]);
                }
        }
    }

    #pragma unroll
    for (int t = 0; t < 4; t++) {
        #pragma unroll
        for (int p = 0; p < 2; p++) {
            int co = col0 + wn*32 + t*8 + 2*c + p;
            float sc = gamma[co] * rsqrtf(var[co] + EPS);
            float bi = beta[co] - mean[co] * sc;
            #pragma unroll
            for (int i = 0; i < 4; i++) {
                #pragma unroll
                for (int half = 0; half < 2; half++) {
                    float v = acc[i][t][half*2 + p] * sc + bi;
                    int m = row0 + wm*64 + i*16 + r + half*8;
                    out[m*CD + co] = v;
                }
            }
        }
    }
}

// ---------------------------------------------------------------------------
extern "C" void kernel_launch(void* const* d_in, const int* in_sizes, int n_in,
                              void* d_out, int out_size)
{
    const float* inputs   = (const float*)d_in[0];
    const float* qkv_w    = (const float*)d_in[1];
    const float* qkv_g    = (const float*)d_in[2];
    const float* qkv_b    = (const float*)d_in[3];
    const float* qkv_m    = (const float*)d_in[4];
    const float* qkv_v    = (const float*)d_in[5];
    const float* pe_w     = (const float*)d_in[6];
    const float* pe_g     = (const float*)d_in[7];
    const float* pe_b     = (const float*)d_in[8];
    const float* pe_m     = (const float*)d_in[9];
    const float* pe_v     = (const float*)d_in[10];
    const float* proj_w   = (const float*)d_in[11];
    const float* proj_g   = (const float*)d_in[12];
    const float* proj_b   = (const float*)d_in[13];
    const float* proj_m   = (const float*)d_in[14];
    const float* proj_v   = (const float*)d_in[15];
    float* out = (float*)d_out;

    qkv_mma_kernel<<<dim3(64, 4), 256>>>(inputs, qkv_w, qkv_g, qkv_b, qkv_m, qkv_v);
    pe_kernel<<<2048, 256>>>(pe_w, pe_g, pe_b, pe_m, pe_v);
    rowstats_mma_kernel<<<dim3(8, 64), 256>>>();
    pv_kernel<<<dim3(8, 64), 256>>>();
    proj_mma_kernel<<<dim3(64, 2), 256>>>(proj_w, proj_g, proj_b, proj_m, proj_v, out);
}

// round 13
// speedup vs baseline: 1.9942x; 1.1046x over previous
#include <cuda_runtime.h>
#include <cstdint>

#define NB 8
#define NH 8
#define NT 1024
#define CD 256
#define KD 16
#define HD 32
#define HQ 512
#define EPS 0.001f
// 0.25 * log2(e) folded into Q so exp(S) == ex2(S')
#define QSCALE 0.36067376022224085f

typedef unsigned long long u64;

__device__ __forceinline__ float ex2f(float x) {
    float y; asm("ex2.approx.f32 %0,%1;" : "=f"(y) : "f"(x)); return y;
}
__device__ __forceinline__ uint32_t tf32r(float x) {
    uint32_t h; asm("cvt.rna.tf32.f32 %0, %1;" : "=r"(h) : "f"(x)); return h;
}
__device__ __forceinline__ void tf32_split(float x, uint32_t& hi, uint32_t& lo) {
    uint32_t h; asm("cvt.rna.tf32.f32 %0, %1;" : "=r"(h) : "f"(x));
    float lf = x - __uint_as_float(h);
    uint32_t l; asm("cvt.rna.tf32.f32 %0, %1;" : "=r"(l) : "f"(lf));
    hi = h; lo = l;
}
// D(16x8) += A(16x8) * B(8x8), tf32 inputs, f32 accum
__device__ __forceinline__ void mma8(float* d, const uint32_t* a, const uint32_t* b) {
    asm volatile(
        "mma.sync.aligned.m16n8k8.row.col.f32.tf32.tf32.f32 "
        "{%0,%1,%2,%3},{%4,%5,%6,%7},{%8,%9},{%0,%1,%2,%3};"
        : "+f"(d[0]), "+f"(d[1]), "+f"(d[2]), "+f"(d[3])
        : "r"(a[0]), "r"(a[1]), "r"(a[2]), "r"(a[3]), "r"(b[0]), "r"(b[1]));
}

// Scratch (static device globals; no allocations allowed)
__device__ float g_Q[NB*NH*NT*KD];     // q * 0.25*log2e, [b][h][n][16]
__device__ float g_Kd[NB*NH*NT*KD];    // [b][h][n][16]
__device__ float g_V[NB*NT*CD];        // NHWC, c = h*32+d
__device__ float g_rinv[NB*NH*NT];     // 1 / sum_m exp(S[n,m])
__device__ float g_mid[NB*NT*CD];      // attn out (scrambled layout)
__device__ float g_pe[NB*NT*CD];       // BN(dwconv(V))

// ---------------------------------------------------------------------------
// Kernel 1: QKV GEMM [8192x256]x[256x512] via 3xtf32 mma, BN folded, routed.
// ---------------------------------------------------------------------------
__global__ __launch_bounds__(256) void qkv_mma_kernel(
    const float* __restrict__ X, const float* __restrict__ W,
    const float* __restrict__ gamma, const float* __restrict__ beta,
    const float* __restrict__ mean, const float* __restrict__ var)
{
    __shared__ float xhi[128][20], xlo[128][20];   // A tile [m][k]
    __shared__ float whi[16][136], wlo[16][136];   // B tile [k][n]

    const int tid = threadIdx.x;
    const int wid = tid >> 5, lane = tid & 31;
    const int r = lane >> 2, c = lane & 3;
    const int wm = wid & 1, wn = wid >> 1;        // 2 m-groups x 4 n-groups
    const int row0 = blockIdx.x * 128;
    const int col0 = blockIdx.y * 128;

    float acc[4][4][4];
    #pragma unroll
    for (int i = 0; i < 4; i++)
        #pragma unroll
        for (int t = 0; t < 4; t++)
            #pragma unroll
            for (int f = 0; f < 4; f++) acc[i][t][f] = 0.f;

    for (int k0 = 0; k0 < CD; k0 += 16) {
        if (k0) __syncthreads();
        {   // X tile 128x16
            int row = tid >> 1, kb = (tid & 1) << 3;
            const float* xp = X + (row0 + row) * CD + k0 + kb;
            float4 v0 = *(const float4*)xp, v1 = *(const float4*)(xp + 4);
            float vv[8] = {v0.x, v0.y, v0.z, v0.w, v1.x, v1.y, v1.z, v1.w};
            #pragma unroll
            for (int d = 0; d < 8; d++) {
                uint32_t h, l; tf32_split(vv[d], h, l);
                xhi[row][kb + d] = __uint_as_float(h);
                xlo[row][kb + d] = __uint_as_float(l);
            }
        }
        {   // W tile 16x128
            int kk = tid >> 4, nb = (tid & 15) << 3;
            const float* wp = W + (k0 + kk) * HQ + col0 + nb;
            float4 v0 = *(const float4*)wp, v1 = *(const float4*)(wp + 4);
            float vv[8] = {v0.x, v0.y, v0.z, v0.w, v1.x, v1.y, v1.z, v1.w};
            #pragma unroll
            for (int d = 0; d < 8; d++) {
                uint32_t h, l; tf32_split(vv[d], h, l);
                whi[kk][nb + d] = __uint_as_float(h);
                wlo[kk][nb + d] = __uint_as_float(l);
            }
        }
        __syncthreads();

        #pragma unroll
        for (int s = 0; s < 2; s++) {
            uint32_t ah[4][4], al[4][4];
            #pragma unroll
            for (int i = 0; i < 4; i++) {
                int mb = wm*64 + i*16;
                ah[i][0] = __float_as_uint(xhi[mb + r    ][s*8 + c    ]);
                ah[i][1] = __float_as_uint(xhi[mb + r + 8][s*8 + c    ]);
                ah[i][2] = __float_as_uint(xhi[mb + r    ][s*8 + c + 4]);
                ah[i][3] = __float_as_uint(xhi[mb + r + 8][s*8 + c + 4]);
                al[i][0] = __float_as_uint(xlo[mb + r    ][s*8 + c    ]);
                al[i][1] = __float_as_uint(xlo[mb + r + 8][s*8 + c    ]);
                al[i][2] = __float_as_uint(xlo[mb + r    ][s*8 + c + 4]);
                al[i][3] = __float_as_uint(xlo[mb + r + 8][s*8 + c + 4]);
            }
            uint32_t bh_[4][2], bl_[4][2];
            #pragma unroll
            for (int t = 0; t < 4; t++) {
                int nb = wn*32 + t*8;
                bh_[t][0] = __float_as_uint(whi[s*8 + c    ][nb + r]);
                bh_[t][1] = __float_as_uint(whi[s*8 + c + 4][nb + r]);
                bl_[t][0] = __float_as_uint(wlo[s*8 + c    ][nb + r]);
                bl_[t][1] = __float_as_uint(wlo[s*8 + c + 4][nb + r]);
            }
            #pragma unroll
            for (int i = 0; i < 4; i++)
                #pragma unroll
                for (int t = 0; t < 4; t++) {
                    mma8(acc[i][t], ah[i], bh_[t]);
                    mma8(acc[i][t], ah[i], bl_[t]);
                    mma8(acc[i][t], al[i], bh_[t]);
                }
        }
    }

    // Epilogue: BN + route to g_Q / g_Kd / g_V
    #pragma unroll
    for (int t = 0; t < 4; t++) {
        #pragma unroll
        for (int p = 0; p < 2; p++) {
            int co = col0 + wn*32 + t*8 + 2*c + p;
            float sc = gamma[co] * rsqrtf(var[co] + EPS);
            float bi = beta[co] - mean[co] * sc;
            int h = co >> 6, rr = co & 63;
            #pragma unroll
            for (int i = 0; i < 4; i++) {
                #pragma unroll
                for (int half = 0; half < 2; half++) {
                    float v = acc[i][t][half*2 + p] * sc + bi;
                    int m = row0 + wm*64 + i*16 + r + half*8;
                    int b = m >> 10, n = m & 1023;
                    if (rr < KD)        g_Q [((b*NH + h)*NT + n)*KD + rr]      = v * QSCALE;
                    else if (rr < 2*KD) g_Kd[((b*NH + h)*NT + n)*KD + rr - KD] = v;
                    else                g_V [(b*NT + n)*CD + h*HD + rr - 2*KD] = v;
                }
            }
        }
    }
}

// ---------------------------------------------------------------------------
// Kernel 2: depthwise 3x3 PE conv on V (NHWC, float4 channels) + BN -> g_pe
// ---------------------------------------------------------------------------
__global__ __launch_bounds__(256) void pe_kernel(
    const float* __restrict__ pw, const float* __restrict__ gamma,
    const float* __restrict__ beta, const float* __restrict__ mean,
    const float* __restrict__ var)
{
    const int idx = blockIdx.x * 256 + threadIdx.x;      // (b,i,j,c4)
    const int c4 = idx & 63;
    const int j  = (idx >> 6) & 31;
    const int i  = (idx >> 11) & 31;
    const int b  = idx >> 16;
    const int c  = c4 << 2;

    float4 acc = make_float4(0.f, 0.f, 0.f, 0.f);
    #pragma unroll
    for (int kh = 0; kh < 3; kh++) {
        int ii = i + kh - 1;
        if (ii < 0 || ii > 31) continue;
        #pragma unroll
        for (int kw = 0; kw < 3; kw++) {
            int jj = j + kw - 1;
            if (jj < 0 || jj > 31) continue;
            float4 v = *(const float4*)(g_V + (b*NT + ii*32 + jj)*CD + c);
            float4 w = *(const float4*)(pw + (kh*3 + kw)*CD + c);
            acc.x += v.x * w.x; acc.y += v.y * w.y;
            acc.z += v.z * w.z; acc.w += v.w * w.w;
        }
    }
    float4 g = *(const float4*)(gamma + c);
    float4 vr = *(const float4*)(var + c);
    float4 be = *(const float4*)(beta + c);
    float4 mn = *(const float4*)(mean + c);
    float4 o;
    float s;
    s = g.x * rsqrtf(vr.x + EPS); o.x = acc.x * s + (be.x - mn.x * s);
    s = g.y * rsqrtf(vr.y + EPS); o.y = acc.y * s + (be.y - mn.y * s);
    s = g.z * rsqrtf(vr.z + EPS); o.z = acc.z * s + (be.z - mn.z * s);
    s = g.w * rsqrtf(vr.w + EPS); o.w = acc.w * s + (be.w - mn.w * s);
    *(float4*)(g_pe + ((b*NT) + i*32 + j)*CD + c) = o;
}

// ---------------------------------------------------------------------------
// Kernel 3: rinv[n] = 1 / sum_m exp(S[n,m]) via 3xtf32 mma.
// Each warp owns TWO 16-n groups (32 n); K B-frags loaded once serve both.
// Block covers 256 n; grid (4, 64).
// ---------------------------------------------------------------------------
__global__ __launch_bounds__(256) void rowstats_mma_kernel()
{
    __shared__ float khi[64][20], klo[64][20];

    const int tid = threadIdx.x;
    const int wid = tid >> 5, lane = tid & 31;
    const int r = lane >> 2, c = lane & 3;
    const int bh = blockIdx.y;
    const int nb0 = blockIdx.x * 256;

    // A-frags: Q rows for 2 n-groups, 3x split
    uint32_t qh[2][2][4], ql[2][2][4];
    #pragma unroll
    for (int u = 0; u < 2; u++) {
        const float* Qb = g_Q + (bh*NT + nb0 + wid*32 + u*16)*KD;
        #pragma unroll
        for (int s = 0; s < 2; s++) {
            tf32_split(Qb[ r     *KD + s*8 + c    ], qh[u][s][0], ql[u][s][0]);
            tf32_split(Qb[(r + 8)*KD + s*8 + c    ], qh[u][s][1], ql[u][s][1]);
            tf32_split(Qb[ r     *KD + s*8 + c + 4], qh[u][s][2], ql[u][s][2]);
            tf32_split(Qb[(r + 8)*KD + s*8 + c + 4], qh[u][s][3], ql[u][s][3]);
        }
    }

    float z[2][2] = {{0.f, 0.f}, {0.f, 0.f}};

    for (int mc = 0; mc < NT; mc += 64) {
        if (mc) __syncthreads();
        {   // stage K chunk 64x16, split hi/lo
            int m = tid >> 2, kb = (tid & 3) << 2;
            float4 v = *(const float4*)(g_Kd + (bh*NT + mc + m)*KD + kb);
            float vv[4] = {v.x, v.y, v.z, v.w};
            #pragma unroll
            for (int d = 0; d < 4; d++) {
                uint32_t h, l; tf32_split(vv[d], h, l);
                khi[m][kb + d] = __uint_as_float(h);
                klo[m][kb + d] = __uint_as_float(l);
            }
        }
        __syncthreads();

        #pragma unroll
        for (int t = 0; t < 8; t++) {
            float d4[2][4];
            #pragma unroll
            for (int u = 0; u < 2; u++)
                #pragma unroll
                for (int f = 0; f < 4; f++) d4[u][f] = 0.f;
            #pragma unroll
            for (int s = 0; s < 2; s++) {
                uint32_t bh_[2], bl_[2];
                bh_[0] = __float_as_uint(khi[t*8 + r][s*8 + c    ]);
                bh_[1] = __float_as_uint(khi[t*8 + r][s*8 + c + 4]);
                bl_[0] = __float_as_uint(klo[t*8 + r][s*8 + c    ]);
                bl_[1] = __float_as_uint(klo[t*8 + r][s*8 + c + 4]);
                #pragma unroll
                for (int u = 0; u < 2; u++) {
                    mma8(d4[u], qh[u][s], bh_);
                    mma8(d4[u], qh[u][s], bl_);
                    mma8(d4[u], ql[u][s], bh_);
                }
            }
            #pragma unroll
            for (int u = 0; u < 2; u++) {
                z[u][0] += ex2f(d4[u][0]) + ex2f(d4[u][1]);
                z[u][1] += ex2f(d4[u][2]) + ex2f(d4[u][3]);
            }
        }
    }

    #pragma unroll
    for (int u = 0; u < 2; u++) {
        float z0 = z[u][0], z1 = z[u][1];
        z0 += __shfl_xor_sync(0xffffffffu, z0, 1);
        z0 += __shfl_xor_sync(0xffffffffu, z0, 2);
        z1 += __shfl_xor_sync(0xffffffffu, z1, 1);
        z1 += __shfl_xor_sync(0xffffffffu, z1, 2);
        if (c == 0) {
            g_rinv[bh*NT + nb0 + wid*32 + u*16 + r    ] = 1.0f / z0;
            g_rinv[bh*NT + nb0 + wid*32 + u*16 + r + 8] = 1.0f / z1;
        }
    }
}

// ---------------------------------------------------------------------------
// Kernel 4: pv via shuffle-transpose, TWO m-tiles per warp (32 m).
//   Q B-frags and V B-frags loaded once per tile-step, reused for both
//   K A-fragment tiles -> 0.8 LDS per mma. Block covers 256 m; grid (4, 64).
// ---------------------------------------------------------------------------
__global__ __launch_bounds__(256) void pv_kernel()
{
    __shared__ float qhi[2][64][20];   // Q hi, tf32 bits
    __shared__ float qlo[2][64][20];   // Q lo
    __shared__ float vsm[2][32][68];   // V' d-major, tf32 bits

    const int tid = threadIdx.x;
    const int wid = tid >> 5, lane = tid & 31;
    const int bh = blockIdx.y;
    const int b = bh >> 3, h = bh & 7;
    const int m0 = blockIdx.x * 256;
    const int r = lane >> 2;
    const int c = lane & 3;
    const int srcA = (lane & ~3) | (c >> 1);
    const int srcB = srcA + 2;
    const bool odd = (c & 1);

    // K fragments for 2 m-tiles (persistent), 3x split
    uint32_t khi_[2][2][4], klo_[2][2][4];
    #pragma unroll
    for (int u = 0; u < 2; u++) {
        const float* Kb = g_Kd + (bh*NT + m0 + wid*32 + u*16)*KD;
        #pragma unroll
        for (int s = 0; s < 2; s++) {
            tf32_split(Kb[ r     *KD + s*8 + c    ], khi_[u][s][0], klo_[u][s][0]);
            tf32_split(Kb[(r + 8)*KD + s*8 + c    ], khi_[u][s][1], klo_[u][s][1]);
            tf32_split(Kb[ r     *KD + s*8 + c + 4], khi_[u][s][2], klo_[u][s][2]);
            tf32_split(Kb[(r + 8)*KD + s*8 + c + 4], khi_[u][s][3], klo_[u][s][3]);
        }
    }

    float acc[2][4][4];
    #pragma unroll
    for (int u = 0; u < 2; u++)
        #pragma unroll
        for (int t = 0; t < 4; t++)
            #pragma unroll
            for (int j = 0; j < 4; j++) acc[u][t][j] = 0.f;

    const int qn = tid >> 2, qj = (tid & 3) << 2;   // Q staging: 4 vals/thread
    const int vn = tid & 63, vdq = tid >> 6;        // V staging: 8 d/thread

    for (int ci = 0; ci < 16; ci++) {
        const int nc = ci << 6;
        const int buf = ci & 1;

        {   // stage Q chunk [64 x 16], pre-split
            float4 q = *(const float4*)(g_Q + (bh*NT + nc + qn)*KD + qj);
            float qq[4] = {q.x, q.y, q.z, q.w};
            #pragma unroll
            for (int d = 0; d < 4; d++) {
                uint32_t hh, ll; tf32_split(qq[d], hh, ll);
                qhi[buf][qn][qj + d] = __uint_as_float(hh);
                qlo[buf][qn][qj + d] = __uint_as_float(ll);
            }
        }
        {   // stage V' chunk d-major [32 d][64 n], scaled by rinv (conflict-free)
            float ri = g_rinv[bh*NT + nc + vn];
            const float* vb = g_V + (b*NT + nc + vn)*CD + h*HD + vdq*8;
            float4 v0 = *(const float4*)(vb);
            float4 v1 = *(const float4*)(vb + 4);
            float vv[8] = {v0.x, v0.y, v0.z, v0.w, v1.x, v1.y, v1.z, v1.w};
            #pragma unroll
            for (int dd = 0; dd < 8; dd++)
                vsm[buf][vdq*8 + dd][vn] = __uint_as_float(tf32r(vv[dd] * ri));
        }
        __syncthreads();

        #pragma unroll
        for (int t = 0; t < 8; t++) {
            // S-mma for both m-tiles; Q B-frags loaded once per s
            float d4[2][4];
            #pragma unroll
            for (int u = 0; u < 2; u++)
                #pragma unroll
                for (int f = 0; f < 4; f++) d4[u][f] = 0.f;
            #pragma unroll
            for (int s = 0; s < 2; s++) {
                uint32_t bhq[2], blq[2];
                bhq[0] = __float_as_uint(qhi[buf][t*8 + r][s*8 + c    ]);
                bhq[1] = __float_as_uint(qhi[buf][t*8 + r][s*8 + c + 4]);
                blq[0] = __float_as_uint(qlo[buf][t*8 + r][s*8 + c    ]);
                blq[1] = __float_as_uint(qlo[buf][t*8 + r][s*8 + c + 4]);
                #pragma unroll
                for (int u = 0; u < 2; u++) {
                    mma8(d4[u], khi_[u][s], bhq);
                    mma8(d4[u], khi_[u][s], blq);
                    mma8(d4[u], klo_[u][s], bhq);
                }
            }

            // V B-frags loaded once, reused by both m-tiles
            uint32_t bb[4][2];
            #pragma unroll
            for (int dt = 0; dt < 4; dt++) {
                bb[dt][0] = __float_as_uint(vsm[buf][dt*8 + r][t*8 + c    ]);
                bb[dt][1] = __float_as_uint(vsm[buf][dt*8 + r][t*8 + c + 4]);
            }

            #pragma unroll
            for (int u = 0; u < 2; u++) {
                float p0 = ex2f(d4[u][0]), p1 = ex2f(d4[u][1]);
                float p2 = ex2f(d4[u][2]), p3 = ex2f(d4[u][3]);

                // D-frag -> A-frag transpose via shuffles
                float x0 = __shfl_sync(0xffffffffu, p0, srcA);
                float x1 = __shfl_sync(0xffffffffu, p1, srcA);
                float x2 = __shfl_sync(0xffffffffu, p2, srcA);
                float x3 = __shfl_sync(0xffffffffu, p3, srcA);
                float y0 = __shfl_sync(0xffffffffu, p0, srcB);
                float y1 = __shfl_sync(0xffffffffu, p1, srcB);
                float y2 = __shfl_sync(0xffffffffu, p2, srcB);
                float y3 = __shfl_sync(0xffffffffu, p3, srcB);
                uint32_t a[4];
                a[0] = tf32r(odd ? x1 : x0);
                a[1] = tf32r(odd ? x3 : x2);
                a[2] = tf32r(odd ? y1 : y0);
                a[3] = tf32r(odd ? y3 : y2);

                #pragma unroll
                for (int dt = 0; dt < 4; dt++)
                    mma8(acc[u][dt], a, bb[dt]);
            }
        }
    }

    // Output: acc[u][t][0]:(m=gm, d=t8+2c) [1]:(gm, d+1) [2]:(gm+8, d) [3]:(gm+8, d+1)
    // Scrambled: mid[b][d][w=4h+(m>>8)][c=m&255]
    #pragma unroll
    for (int u = 0; u < 2; u++) {
        const int gm = m0 + wid*32 + u*16 + r;
        const int wq = (h << 2) + (gm >> 8);
        const int cc0 = gm & 255;
        #pragma unroll
        for (int t = 0; t < 4; t++) {
            int d0 = t*8 + 2*c;
            g_mid[((b*32 + d0    )*32 + wq)*CD + cc0    ] = acc[u][t][0];
            g_mid[((b*32 + d0 + 1)*32 + wq)*CD + cc0    ] = acc[u][t][1];
            g_mid[((b*32 + d0    )*32 + wq)*CD + cc0 + 8] = acc[u][t][2];
            g_mid[((b*32 + d0 + 1)*32 + wq)*CD + cc0 + 8] = acc[u][t][3];
        }
    }
}

// ---------------------------------------------------------------------------
// Kernel 5: Proj GEMM [8192x256]x[256x256] on (mid+pe) via 3xtf32 mma + BN.
// ---------------------------------------------------------------------------
__global__ __launch_bounds__(256) void proj_mma_kernel(
    const float* __restrict__ W, const float* __restrict__ gamma,
    const float* __restrict__ beta, const float* __restrict__ mean,
    const float* __restrict__ var, float* __restrict__ out)
{
    __shared__ float xhi[128][20], xlo[128][20];
    __shared__ float whi[16][136], wlo[16][136];

    const int tid = threadIdx.x;
    const int wid = tid >> 5, lane = tid & 31;
    const int r = lane >> 2, c = lane & 3;
    const int wm = wid & 1, wn = wid >> 1;
    const int row0 = blockIdx.x * 128;
    const int col0 = blockIdx.y * 128;

    float acc[4][4][4];
    #pragma unroll
    for (int i = 0; i < 4; i++)
        #pragma unroll
        for (int t = 0; t < 4; t++)
            #pragma unroll
            for (int f = 0; f < 4; f++) acc[i][t][f] = 0.f;

    for (int k0 = 0; k0 < CD; k0 += 16) {
        if (k0) __syncthreads();
        {   // A tile = mid + pe
            int row = tid >> 1, kb = (tid & 1) << 3;
            const int off = (row0 + row) * CD + k0 + kb;
            float4 v0 = *(const float4*)(g_mid + off);
            float4 v1 = *(const float4*)(g_mid + off + 4);
            float4 p0 = *(const float4*)(g_pe + off);
            float4 p1 = *(const float4*)(g_pe + off + 4);
            float vv[8] = {v0.x + p0.x, v0.y + p0.y, v0.z + p0.z, v0.w + p0.w,
                           v1.x + p1.x, v1.y + p1.y, v1.z + p1.z, v1.w + p1.w};
            #pragma unroll
            for (int d = 0; d < 8; d++) {
                uint32_t h, l; tf32_split(vv[d], h, l);
                xhi[row][kb + d] = __uint_as_float(h);
                xlo[row][kb + d] = __uint_as_float(l);
            }
        }
        {
            int kk = tid >> 4, nb = (tid & 15) << 3;
            const float* wp = W + (k0 + kk) * CD + col0 + nb;
            float4 v0 = *(const float4*)wp, v1 = *(const float4*)(wp + 4);
            float vv[8] = {v0.x, v0.y, v0.z, v0.w, v1.x, v1.y, v1.z, v1.w};
            #pragma unroll
            for (int d = 0; d < 8; d++) {
                uint32_t h, l; tf32_split(vv[d], h, l);
                whi[kk][nb + d] = __uint_as_float(h);
                wlo[kk][nb + d] = __uint_as_float(l);
            }
        }
        __syncthreads();

        #pragma unroll
        for (int s = 0; s < 2; s++) {
            uint32_t ah[4][4], al[4][4];
            #pragma unroll
            for (int i = 0; i < 4; i++) {
                int mb = wm*64 + i*16;
                ah[i][0] = __float_as_uint(xhi[mb + r    ][s*8 + c    ]);
                ah[i][1] = __float_as_uint(xhi[mb + r + 8][s*8 + c    ]);
                ah[i][2] = __float_as_uint(xhi[mb + r    ][s*8 + c + 4]);
                ah[i][3] = __float_as_uint(xhi[mb + r + 8][s*8 + c + 4]);
                al[i][0] = __float_as_uint(xlo[mb + r    ][s*8 + c    ]);
                al[i][1] = __float_as_uint(xlo[mb + r + 8][s*8 + c    ]);
                al[i][2] = __float_as_uint(xlo[mb + r    ][s*8 + c + 4]);
                al[i][3] = __float_as_uint(xlo[mb + r + 8][s*8 + c + 4]);
            }
            uint32_t bh_[4][2], bl_[4][2];
            #pragma unroll
            for (int t = 0; t < 4; t++) {
                int nb = wn*32 + t*8;
                bh_[t][0] = __float_as_uint(whi[s*8 + c    ][nb + r]);
                bh_[t][1] = __float_as_uint(whi[s*8 + c + 4][nb + r]);
                bl_[t][0] = __float_as_uint(wlo[s*8 + c    ][nb + r]);
                bl_[t][1] = __float_as_uint(wlo[s*8 + c + 4][nb + r]);
            }
            #pragma unroll
            for (int i = 0; i < 4; i++)
                #pragma unroll
                for (int t = 0; t < 4; t++) {
                    mma8(acc[i][t], ah[i], bh_[t]);
                    mma8(acc[i][t], ah[i], bl_[t]);
                    mma8(acc[i][t], al[i], bh_[t]);
                }
        }
    }

    #pragma unroll
    for (int t = 0; t < 4; t++) {
        #pragma unroll
        for (int p = 0; p < 2; p++) {
            int co = col0 + wn*32 + t*8 + 2*c + p;
            float sc = gamma[co] * rsqrtf(var[co] + EPS);
            float bi = beta[co] - mean[co] * sc;
            #pragma unroll
            for (int i = 0; i < 4; i++) {
                #pragma unroll
                for (int half = 0; half < 2; half++) {
                    float v = acc[i][t][half*2 + p] * sc + bi;
                    int m = row0 + wm*64 + i*16 + r + half*8;
                    out[m*CD + co] = v;
                }
            }
        }
    }
}

// ---------------------------------------------------------------------------
extern "C" void kernel_launch(void* const* d_in, const int* in_sizes, int n_in,
                              void* d_out, int out_size)
{
    const float* inputs   = (const float*)d_in[0];
    const float* qkv_w    = (const float*)d_in[1];
    const float* qkv_g    = (const float*)d_in[2];
    const float* qkv_b    = (const float*)d_in[3];
    const float* qkv_m    = (const float*)d_in[4];
    const float* qkv_v    = (const float*)d_in[5];
    const float* pe_w     = (const float*)d_in[6];
    const float* pe_g     = (const float*)d_in[7];
    const float* pe_b     = (const float*)d_in[8];
    const float* pe_m     = (const float*)d_in[9];
    const float* pe_v     = (const float*)d_in[10];
    const float* proj_w   = (const float*)d_in[11];
    const float* proj_g   = (const float*)d_in[12];
    const float* proj_b   = (const float*)d_in[13];
    const float* proj_m   = (const float*)d_in[14];
    const float* proj_v   = (const float*)d_in[15];
    float* out = (float*)d_out;

    qkv_mma_kernel<<<dim3(64, 4), 256>>>(inputs, qkv_w, qkv_g, qkv_b, qkv_m, qkv_v);
    pe_kernel<<<2048, 256>>>(pe_w, pe_g, pe_b, pe_m, pe_v);
    rowstats_mma_kernel<<<dim3(4, 64), 256>>>();
    pv_kernel<<<dim3(4, 64), 256>>>();
    proj_mma_kernel<<<dim3(64, 2), 256>>>(proj_w, proj_g, proj_b, proj_m, proj_v, out);
}

// round 15
// speedup vs baseline: 2.1435x; 1.0749x over previous
#include <cuda_runtime.h>
#include <cstdint>

#define NB 8
#define NH 8
#define NT 1024
#define CD 256
#define KD 16
#define HD 32
#define HQ 512
#define EPS 0.001f
// 0.25 * log2(e) folded into Q so exp(S) == ex2(S')
#define QSCALE 0.36067376022224085f

typedef unsigned long long u64;

__device__ __forceinline__ float ex2f(float x) {
    float y; asm("ex2.approx.f32 %0,%1;" : "=f"(y) : "f"(x)); return y;
}
__device__ __forceinline__ uint32_t tf32r(float x) {
    uint32_t h; asm("cvt.rna.tf32.f32 %0, %1;" : "=r"(h) : "f"(x)); return h;
}
__device__ __forceinline__ void tf32_split(float x, uint32_t& hi, uint32_t& lo) {
    uint32_t h; asm("cvt.rna.tf32.f32 %0, %1;" : "=r"(h) : "f"(x));
    float lf = x - __uint_as_float(h);
    uint32_t l; asm("cvt.rna.tf32.f32 %0, %1;" : "=r"(l) : "f"(lf));
    hi = h; lo = l;
}
// D(16x8) += A(16x8) * B(8x8), tf32 inputs, f32 accum
__device__ __forceinline__ void mma8(float* d, const uint32_t* a, const uint32_t* b) {
    asm volatile(
        "mma.sync.aligned.m16n8k8.row.col.f32.tf32.tf32.f32 "
        "{%0,%1,%2,%3},{%4,%5,%6,%7},{%8,%9},{%0,%1,%2,%3};"
        : "+f"(d[0]), "+f"(d[1]), "+f"(d[2]), "+f"(d[3])
        : "r"(a[0]), "r"(a[1]), "r"(a[2]), "r"(a[3]), "r"(b[0]), "r"(b[1]));
}

// Scratch (static device globals; no allocations allowed)
__device__ float g_Q[NB*NH*NT*KD];     // q * 0.25*log2e, [b][h][n][16]
__device__ float g_Kd[NB*NH*NT*KD];    // [b][h][n][16]
__device__ float g_V[NB*NT*CD];        // NHWC, c = h*32+d
__device__ float g_rinv[NB*NH*NT];     // 1 / sum_m exp(S[n,m])
__device__ float g_mid[NB*NT*CD];      // attn out (scrambled layout)
__device__ float g_pe[NB*NT*CD];       // BN(dwconv(V))

// ---------------------------------------------------------------------------
// Kernel 1: QKV GEMM [8192x256]x[256x512] via 3xtf32 mma, BN folded, routed.
// ---------------------------------------------------------------------------
__global__ __launch_bounds__(256) void qkv_mma_kernel(
    const float* __restrict__ X, const float* __restrict__ W,
    const float* __restrict__ gamma, const float* __restrict__ beta,
    const float* __restrict__ mean, const float* __restrict__ var)
{
    __shared__ float xhi[128][20], xlo[128][20];   // A tile [m][k]
    __shared__ float whi[16][136], wlo[16][136];   // B tile [k][n]

    const int tid = threadIdx.x;
    const int wid = tid >> 5, lane = tid & 31;
    const int r = lane >> 2, c = lane & 3;
    const int wm = wid & 1, wn = wid >> 1;        // 2 m-groups x 4 n-groups
    const int row0 = blockIdx.x * 128;
    const int col0 = blockIdx.y * 128;

    float acc[4][4][4];
    #pragma unroll
    for (int i = 0; i < 4; i++)
        #pragma unroll
        for (int t = 0; t < 4; t++)
            #pragma unroll
            for (int f = 0; f < 4; f++) acc[i][t][f] = 0.f;

    for (int k0 = 0; k0 < CD; k0 += 16) {
        if (k0) __syncthreads();
        {   // X tile 128x16
            int row = tid >> 1, kb = (tid & 1) << 3;
            const float* xp = X + (row0 + row) * CD + k0 + kb;
            float4 v0 = *(const float4*)xp, v1 = *(const float4*)(xp + 4);
            float vv[8] = {v0.x, v0.y, v0.z, v0.w, v1.x, v1.y, v1.z, v1.w};
            #pragma unroll
            for (int d = 0; d < 8; d++) {
                uint32_t h, l; tf32_split(vv[d], h, l);
                xhi[row][kb + d] = __uint_as_float(h);
                xlo[row][kb + d] = __uint_as_float(l);
            }
        }
        {   // W tile 16x128
            int kk = tid >> 4, nb = (tid & 15) << 3;
            const float* wp = W + (k0 + kk) * HQ + col0 + nb;
            float4 v0 = *(const float4*)wp, v1 = *(const float4*)(wp + 4);
            float vv[8] = {v0.x, v0.y, v0.z, v0.w, v1.x, v1.y, v1.z, v1.w};
            #pragma unroll
            for (int d = 0; d < 8; d++) {
                uint32_t h, l; tf32_split(vv[d], h, l);
                whi[kk][nb + d] = __uint_as_float(h);
                wlo[kk][nb + d] = __uint_as_float(l);
            }
        }
        __syncthreads();

        #pragma unroll
        for (int s = 0; s < 2; s++) {
            uint32_t ah[4][4], al[4][4];
            #pragma unroll
            for (int i = 0; i < 4; i++) {
                int mb = wm*64 + i*16;
                ah[i][0] = __float_as_uint(xhi[mb + r    ][s*8 + c    ]);
                ah[i][1] = __float_as_uint(xhi[mb + r + 8][s*8 + c    ]);
                ah[i][2] = __float_as_uint(xhi[mb + r    ][s*8 + c + 4]);
                ah[i][3] = __float_as_uint(xhi[mb + r + 8][s*8 + c + 4]);
                al[i][0] = __float_as_uint(xlo[mb + r    ][s*8 + c    ]);
                al[i][1] = __float_as_uint(xlo[mb + r + 8][s*8 + c    ]);
                al[i][2] = __float_as_uint(xlo[mb + r    ][s*8 + c + 4]);
                al[i][3] = __float_as_uint(xlo[mb + r + 8][s*8 + c + 4]);
            }
            uint32_t bh_[4][2], bl_[4][2];
            #pragma unroll
            for (int t = 0; t < 4; t++) {
                int nb = wn*32 + t*8;
                bh_[t][0] = __float_as_uint(whi[s*8 + c    ][nb + r]);
                bh_[t][1] = __float_as_uint(whi[s*8 + c + 4][nb + r]);
                bl_[t][0] = __float_as_uint(wlo[s*8 + c    ][nb + r]);
                bl_[t][1] = __float_as_uint(wlo[s*8 + c + 4][nb + r]);
            }
            #pragma unroll
            for (int i = 0; i < 4; i++)
                #pragma unroll
                for (int t = 0; t < 4; t++) {
                    mma8(acc[i][t], ah[i], bh_[t]);
                    mma8(acc[i][t], ah[i], bl_[t]);
                    mma8(acc[i][t], al[i], bh_[t]);
                }
        }
    }

    // Epilogue: BN + route to g_Q / g_Kd / g_V
    #pragma unroll
    for (int t = 0; t < 4; t++) {
        #pragma unroll
        for (int p = 0; p < 2; p++) {
            int co = col0 + wn*32 + t*8 + 2*c + p;
            float sc = gamma[co] * rsqrtf(var[co] + EPS);
            float bi = beta[co] - mean[co] * sc;
            int h = co >> 6, rr = co & 63;
            #pragma unroll
            for (int i = 0; i < 4; i++) {
                #pragma unroll
                for (int half = 0; half < 2; half++) {
                    float v = acc[i][t][half*2 + p] * sc + bi;
                    int m = row0 + wm*64 + i*16 + r + half*8;
                    int b = m >> 10, n = m & 1023;
                    if (rr < KD)        g_Q [((b*NH + h)*NT + n)*KD + rr]      = v * QSCALE;
                    else if (rr < 2*KD) g_Kd[((b*NH + h)*NT + n)*KD + rr - KD] = v;
                    else                g_V [(b*NT + n)*CD + h*HD + rr - 2*KD] = v;
                }
            }
        }
    }
}

// ---------------------------------------------------------------------------
// Kernel 2: depthwise 3x3 PE conv on V (NHWC, float4 channels) + BN -> g_pe
// Split into two half-grid launches (blk0 offset) so the ncu capture slot
// (4th launch) lands on rowstats this round.
// ---------------------------------------------------------------------------
__global__ __launch_bounds__(256) void pe_kernel(
    const float* __restrict__ pw, const float* __restrict__ gamma,
    const float* __restrict__ beta, const float* __restrict__ mean,
    const float* __restrict__ var, int blk0)
{
    const int idx = (blk0 + blockIdx.x) * 256 + threadIdx.x;   // (b,i,j,c4)
    const int c4 = idx & 63;
    const int j  = (idx >> 6) & 31;
    const int i  = (idx >> 11) & 31;
    const int b  = idx >> 16;
    const int c  = c4 << 2;

    float4 acc = make_float4(0.f, 0.f, 0.f, 0.f);
    #pragma unroll
    for (int kh = 0; kh < 3; kh++) {
        int ii = i + kh - 1;
        if (ii < 0 || ii > 31) continue;
        #pragma unroll
        for (int kw = 0; kw < 3; kw++) {
            int jj = j + kw - 1;
            if (jj < 0 || jj > 31) continue;
            float4 v = *(const float4*)(g_V + (b*NT + ii*32 + jj)*CD + c);
            float4 w = *(const float4*)(pw + (kh*3 + kw)*CD + c);
            acc.x += v.x * w.x; acc.y += v.y * w.y;
            acc.z += v.z * w.z; acc.w += v.w * w.w;
        }
    }
    float4 g = *(const float4*)(gamma + c);
    float4 vr = *(const float4*)(var + c);
    float4 be = *(const float4*)(beta + c);
    float4 mn = *(const float4*)(mean + c);
    float4 o;
    float s;
    s = g.x * rsqrtf(vr.x + EPS); o.x = acc.x * s + (be.x - mn.x * s);
    s = g.y * rsqrtf(vr.y + EPS); o.y = acc.y * s + (be.y - mn.y * s);
    s = g.z * rsqrtf(vr.z + EPS); o.z = acc.z * s + (be.z - mn.z * s);
    s = g.w * rsqrtf(vr.w + EPS); o.w = acc.w * s + (be.w - mn.w * s);
    *(float4*)(g_pe + ((b*NT) + i*32 + j)*CD + c) = o;
}

// ---------------------------------------------------------------------------
// Kernel 3: rinv[n] = 1 / sum_m exp(S[n,m]) via SINGLE-tf32 mma.
// Z averages independent per-term tf32 errors down by sqrt(N_eff) -> safe.
// Each warp owns TWO 16-n groups (32 n); K B-frags loaded once serve both.
// ---------------------------------------------------------------------------
__global__ __launch_bounds__(256) void rowstats_mma_kernel()
{
    __shared__ float khi[64][20];

    const int tid = threadIdx.x;
    const int wid = tid >> 5, lane = tid & 31;
    const int r = lane >> 2, c = lane & 3;
    const int bh = blockIdx.y;
    const int nb0 = blockIdx.x * 256;

    // A-frags: Q rows for 2 n-groups, single tf32
    uint32_t qh[2][2][4];
    #pragma unroll
    for (int u = 0; u < 2; u++) {
        const float* Qb = g_Q + (bh*NT + nb0 + wid*32 + u*16)*KD;
        #pragma unroll
        for (int s = 0; s < 2; s++) {
            qh[u][s][0] = tf32r(Qb[ r     *KD + s*8 + c    ]);
            qh[u][s][1] = tf32r(Qb[(r + 8)*KD + s*8 + c    ]);
            qh[u][s][2] = tf32r(Qb[ r     *KD + s*8 + c + 4]);
            qh[u][s][3] = tf32r(Qb[(r + 8)*KD + s*8 + c + 4]);
        }
    }

    float z[2][2] = {{0.f, 0.f}, {0.f, 0.f}};

    for (int mc = 0; mc < NT; mc += 64) {
        if (mc) __syncthreads();
        {   // stage K chunk 64x16, single tf32
            int m = tid >> 2, kb = (tid & 3) << 2;
            float4 v = *(const float4*)(g_Kd + (bh*NT + mc + m)*KD + kb);
            khi[m][kb + 0] = __uint_as_float(tf32r(v.x));
            khi[m][kb + 1] = __uint_as_float(tf32r(v.y));
            khi[m][kb + 2] = __uint_as_float(tf32r(v.z));
            khi[m][kb + 3] = __uint_as_float(tf32r(v.w));
        }
        __syncthreads();

        #pragma unroll
        for (int t = 0; t < 8; t++) {
            float d4[2][4];
            #pragma unroll
            for (int u = 0; u < 2; u++)
                #pragma unroll
                for (int f = 0; f < 4; f++) d4[u][f] = 0.f;
            #pragma unroll
            for (int s = 0; s < 2; s++) {
                uint32_t bh_[2];
                bh_[0] = __float_as_uint(khi[t*8 + r][s*8 + c    ]);
                bh_[1] = __float_as_uint(khi[t*8 + r][s*8 + c + 4]);
                #pragma unroll
                for (int u = 0; u < 2; u++)
                    mma8(d4[u], qh[u][s], bh_);
            }
            #pragma unroll
            for (int u = 0; u < 2; u++) {
                z[u][0] += ex2f(d4[u][0]) + ex2f(d4[u][1]);
                z[u][1] += ex2f(d4[u][2]) + ex2f(d4[u][3]);
            }
        }
    }

    #pragma unroll
    for (int u = 0; u < 2; u++) {
        float z0 = z[u][0], z1 = z[u][1];
        z0 += __shfl_xor_sync(0xffffffffu, z0, 1);
        z0 += __shfl_xor_sync(0xffffffffu, z0, 2);
        z1 += __shfl_xor_sync(0xffffffffu, z1, 1);
        z1 += __shfl_xor_sync(0xffffffffu, z1, 2);
        if (c == 0) {
            g_rinv[bh*NT + nb0 + wid*32 + u*16 + r    ] = 1.0f / z0;
            g_rinv[bh*NT + nb0 + wid*32 + u*16 + r + 8] = 1.0f / z1;
        }
    }
}

// ---------------------------------------------------------------------------
// Kernel 4: pv via shuffle-transpose, TWO m-tiles per warp (unchanged R13).
// ---------------------------------------------------------------------------
__global__ __launch_bounds__(256) void pv_kernel()
{
    __shared__ float qhi[2][64][20];   // Q hi, tf32 bits
    __shared__ float qlo[2][64][20];   // Q lo
    __shared__ float vsm[2][32][68];   // V' d-major, tf32 bits

    const int tid = threadIdx.x;
    const int wid = tid >> 5, lane = tid & 31;
    const int bh = blockIdx.y;
    const int b = bh >> 3, h = bh & 7;
    const int m0 = blockIdx.x * 256;
    const int r = lane >> 2;
    const int c = lane & 3;
    const int srcA = (lane & ~3) | (c >> 1);
    const int srcB = srcA + 2;
    const bool odd = (c & 1);

    // K fragments for 2 m-tiles (persistent), 3x split
    uint32_t khi_[2][2][4], klo_[2][2][4];
    #pragma unroll
    for (int u = 0; u < 2; u++) {
        const float* Kb = g_Kd + (bh*NT + m0 + wid*32 + u*16)*KD;
        #pragma unroll
        for (int s = 0; s < 2; s++) {
            tf32_split(Kb[ r     *KD + s*8 + c    ], khi_[u][s][0], klo_[u][s][0]);
            tf32_split(Kb[(r + 8)*KD + s*8 + c    ], khi_[u][s][1], klo_[u][s][1]);
            tf32_split(Kb[ r     *KD + s*8 + c + 4], khi_[u][s][2], klo_[u][s][2]);
            tf32_split(Kb[(r + 8)*KD + s*8 + c + 4], khi_[u][s][3], klo_[u][s][3]);
        }
    }

    float acc[2][4][4];
    #pragma unroll
    for (int u = 0; u < 2; u++)
        #pragma unroll
        for (int t = 0; t < 4; t++)
            #pragma unroll
            for (int j = 0; j < 4; j++) acc[u][t][j] = 0.f;

    const int qn = tid >> 2, qj = (tid & 3) << 2;   // Q staging: 4 vals/thread
    const int vn = tid & 63, vdq = tid >> 6;        // V staging: 8 d/thread

    for (int ci = 0; ci < 16; ci++) {
        const int nc = ci << 6;
        const int buf = ci & 1;

        {   // stage Q chunk [64 x 16], pre-split
            float4 q = *(const float4*)(g_Q + (bh*NT + nc + qn)*KD + qj);
            float qq[4] = {q.x, q.y, q.z, q.w};
            #pragma unroll
            for (int d = 0; d < 4; d++) {
                uint32_t hh, ll; tf32_split(qq[d], hh, ll);
                qhi[buf][qn][qj + d] = __uint_as_float(hh);
                qlo[buf][qn][qj + d] = __uint_as_float(ll);
            }
        }
        {   // stage V' chunk d-major [32 d][64 n], scaled by rinv (conflict-free)
            float ri = g_rinv[bh*NT + nc + vn];
            const float* vb = g_V + (b*NT + nc + vn)*CD + h*HD + vdq*8;
            float4 v0 = *(const float4*)(vb);
            float4 v1 = *(const float4*)(vb + 4);
            float vv[8] = {v0.x, v0.y, v0.z, v0.w, v1.x, v1.y, v1.z, v1.w};
            #pragma unroll
            for (int dd = 0; dd < 8; dd++)
                vsm[buf][vdq*8 + dd][vn] = __uint_as_float(tf32r(vv[dd] * ri));
        }
        __syncthreads();

        #pragma unroll
        for (int t = 0; t < 8; t++) {
            // S-mma for both m-tiles; Q B-frags loaded once per s
            float d4[2][4];
            #pragma unroll
            for (int u = 0; u < 2; u++)
                #pragma unroll
                for (int f = 0; f < 4; f++) d4[u][f] = 0.f;
            #pragma unroll
            for (int s = 0; s < 2; s++) {
                uint32_t bhq[2], blq[2];
                bhq[0] = __float_as_uint(qhi[buf][t*8 + r][s*8 + c    ]);
                bhq[1] = __float_as_uint(qhi[buf][t*8 + r][s*8 + c + 4]);
                blq[0] = __float_as_uint(qlo[buf][t*8 + r][s*8 + c    ]);
                blq[1] = __float_as_uint(qlo[buf][t*8 + r][s*8 + c + 4]);
                #pragma unroll
                for (int u = 0; u < 2; u++) {
                    mma8(d4[u], khi_[u][s], bhq);
                    mma8(d4[u], khi_[u][s], blq);
                    mma8(d4[u], klo_[u][s], bhq);
                }
            }

            // V B-frags loaded once, reused by both m-tiles
            uint32_t bb[4][2];
            #pragma unroll
            for (int dt = 0; dt < 4; dt++) {
                bb[dt][0] = __float_as_uint(vsm[buf][dt*8 + r][t*8 + c    ]);
                bb[dt][1] = __float_as_uint(vsm[buf][dt*8 + r][t*8 + c + 4]);
            }

            #pragma unroll
            for (int u = 0; u < 2; u++) {
                float p0 = ex2f(d4[u][0]), p1 = ex2f(d4[u][1]);
                float p2 = ex2f(d4[u][2]), p3 = ex2f(d4[u][3]);

                // D-frag -> A-frag transpose via shuffles
                float x0 = __shfl_sync(0xffffffffu, p0, srcA);
                float x1 = __shfl_sync(0xffffffffu, p1, srcA);
                float x2 = __shfl_sync(0xffffffffu, p2, srcA);
                float x3 = __shfl_sync(0xffffffffu, p3, srcA);
                float y0 = __shfl_sync(0xffffffffu, p0, srcB);
                float y1 = __shfl_sync(0xffffffffu, p1, srcB);
                float y2 = __shfl_sync(0xffffffffu, p2, srcB);
                float y3 = __shfl_sync(0xffffffffu, p3, srcB);
                uint32_t a[4];
                a[0] = tf32r(odd ? x1 : x0);
                a[1] = tf32r(odd ? x3 : x2);
                a[2] = tf32r(odd ? y1 : y0);
                a[3] = tf32r(odd ? y3 : y2);

                #pragma unroll
                for (int dt = 0; dt < 4; dt++)
                    mma8(acc[u][dt], a, bb[dt]);
            }
        }
    }

    // Output: acc[u][t][0]:(m=gm, d=t8+2c) [1]:(gm, d+1) [2]:(gm+8, d) [3]:(gm+8, d+1)
    // Scrambled: mid[b][d][w=4h+(m>>8)][c=m&255]
    #pragma unroll
    for (int u = 0; u < 2; u++) {
        const int gm = m0 + wid*32 + u*16 + r;
        const int wq = (h << 2) + (gm >> 8);
        const int cc0 = gm & 255;
        #pragma unroll
        for (int t = 0; t < 4; t++) {
            int d0 = t*8 + 2*c;
            g_mid[((b*32 + d0    )*32 + wq)*CD + cc0    ] = acc[u][t][0];
            g_mid[((b*32 + d0 + 1)*32 + wq)*CD + cc0    ] = acc[u][t][1];
            g_mid[((b*32 + d0    )*32 + wq)*CD + cc0 + 8] = acc[u][t][2];
            g_mid[((b*32 + d0 + 1)*32 + wq)*CD + cc0 + 8] = acc[u][t][3];
        }
    }
}

// ---------------------------------------------------------------------------
// Kernel 5: Proj GEMM [8192x256]x[256x256] on (mid+pe) via 3xtf32 mma + BN.
// ---------------------------------------------------------------------------
__global__ __launch_bounds__(256) void proj_mma_kernel(
    const float* __restrict__ W, const float* __restrict__ gamma,
    const float* __restrict__ beta, const float* __restrict__ mean,
    const float* __restrict__ var, float* __restrict__ out)
{
    __shared__ float xhi[128][20], xlo[128][20];
    __shared__ float whi[16][136], wlo[16][136];

    const int tid = threadIdx.x;
    const int wid = tid >> 5, lane = tid & 31;
    const int r = lane >> 2, c = lane & 3;
    const int wm = wid & 1, wn = wid >> 1;
    const int row0 = blockIdx.x * 128;
    const int col0 = blockIdx.y * 128;

    float acc[4][4][4];
    #pragma unroll
    for (int i = 0; i < 4; i++)
        #pragma unroll
        for (int t = 0; t < 4; t++)
            #pragma unroll
            for (int f = 0; f < 4; f++) acc[i][t][f] = 0.f;

    for (int k0 = 0; k0 < CD; k0 += 16) {
        if (k0) __syncthreads();
        {   // A tile = mid + pe
            int row = tid >> 1, kb = (tid & 1) << 3;
            const int off = (row0 + row) * CD + k0 + kb;
            float4 v0 = *(const float4*)(g_mid + off);
            float4 v1 = *(const float4*)(g_mid + off + 4);
            float4 p0 = *(const float4*)(g_pe + off);
            float4 p1 = *(const float4*)(g_pe + off + 4);
            float vv[8] = {v0.x + p0.x, v0.y + p0.y, v0.z + p0.z, v0.w + p0.w,
                           v1.x + p1.x, v1.y + p1.y, v1.z + p1.z, v1.w + p1.w};
            #pragma unroll
            for (int d = 0; d < 8; d++) {
                uint32_t h, l; tf32_split(vv[d], h, l);
                xhi[row][kb + d] = __uint_as_float(h);
                xlo[row][kb + d] = __uint_as_float(l);
            }
        }
        {
            int kk = tid >> 4, nb = (tid & 15) << 3;
            const float* wp = W + (k0 + kk) * CD + col0 + nb;
            float4 v0 = *(const float4*)wp, v1 = *(const float4*)(wp + 4);
            float vv[8] = {v0.x, v0.y, v0.z, v0.w, v1.x, v1.y, v1.z, v1.w};
            #pragma unroll
            for (int d = 0; d < 8; d++) {
                uint32_t h, l; tf32_split(vv[d], h, l);
                whi[kk][nb + d] = __uint_as_float(h);
                wlo[kk][nb + d] = __uint_as_float(l);
            }
        }
        __syncthreads();

        #pragma unroll
        for (int s = 0; s < 2; s++) {
            uint32_t ah[4][4], al[4][4];
            #pragma unroll
            for (int i = 0; i < 4; i++) {
                int mb = wm*64 + i*16;
                ah[i][0] = __float_as_uint(xhi[mb + r    ][s*8 + c    ]);
                ah[i][1] = __float_as_uint(xhi[mb + r + 8][s*8 + c    ]);
                ah[i][2] = __float_as_uint(xhi[mb + r    ][s*8 + c + 4]);
                ah[i][3] = __float_as_uint(xhi[mb + r + 8][s*8 + c + 4]);
                al[i][0] = __float_as_uint(xlo[mb + r    ][s*8 + c    ]);
                al[i][1] = __float_as_uint(xlo[mb + r + 8][s*8 + c    ]);
                al[i][2] = __float_as_uint(xlo[mb + r    ][s*8 + c + 4]);
                al[i][3] = __float_as_uint(xlo[mb + r + 8][s*8 + c + 4]);
            }
            uint32_t bh_[4][2], bl_[4][2];
            #pragma unroll
            for (int t = 0; t < 4; t++) {
                int nb = wn*32 + t*8;
                bh_[t][0] = __float_as_uint(whi[s*8 + c    ][nb + r]);
                bh_[t][1] = __float_as_uint(whi[s*8 + c + 4][nb + r]);
                bl_[t][0] = __float_as_uint(wlo[s*8 + c    ][nb + r]);
                bl_[t][1] = __float_as_uint(wlo[s*8 + c + 4][nb + r]);
            }
            #pragma unroll
            for (int i = 0; i < 4; i++)
                #pragma unroll
                for (int t = 0; t < 4; t++) {
                    mma8(acc[i][t], ah[i], bh_[t]);
                    mma8(acc[i][t], ah[i], bl_[t]);
                    mma8(acc[i][t], al[i], bh_[t]);
                }
        }
    }

    #pragma unroll
    for (int t = 0; t < 4; t++) {
        #pragma unroll
        for (int p = 0; p < 2; p++) {
            int co = col0 + wn*32 + t*8 + 2*c + p;
            float sc = gamma[co] * rsqrtf(var[co] + EPS);
            float bi = beta[co] - mean[co] * sc;
            #pragma unroll
            for (int i = 0; i < 4; i++) {
                #pragma unroll
                for (int half = 0; half < 2; half++) {
                    float v = acc[i][t][half*2 + p] * sc + bi;
                    int m = row0 + wm*64 + i*16 + r + half*8;
                    out[m*CD + co] = v;
                }
            }
        }
    }
}

// ---------------------------------------------------------------------------
extern "C" void kernel_launch(void* const* d_in, const int* in_sizes, int n_in,
                              void* d_out, int out_size)
{
    const float* inputs   = (const float*)d_in[0];
    const float* qkv_w    = (const float*)d_in[1];
    const float* qkv_g    = (const float*)d_in[2];
    const float* qkv_b    = (const float*)d_in[3];
    const float* qkv_m    = (const float*)d_in[4];
    const float* qkv_v    = (const float*)d_in[5];
    const float* pe_w     = (const float*)d_in[6];
    const float* pe_g     = (const float*)d_in[7];
    const float* pe_b     = (const float*)d_in[8];
    const float* pe_m     = (const float*)d_in[9];
    const float* pe_v     = (const float*)d_in[10];
    const float* proj_w   = (const float*)d_in[11];
    const float* proj_g   = (const float*)d_in[12];
    const float* proj_b   = (const float*)d_in[13];
    const float* proj_m   = (const float*)d_in[14];
    const float* proj_v   = (const float*)d_in[15];
    float* out = (float*)d_out;

    qkv_mma_kernel<<<dim3(64, 4), 256>>>(inputs, qkv_w, qkv_g, qkv_b, qkv_m, qkv_v);
    pe_kernel<<<1024, 256>>>(pe_w, pe_g, pe_b, pe_m, pe_v, 0);
    pe_kernel<<<1024, 256>>>(pe_w, pe_g, pe_b, pe_m, pe_v, 1024);
    rowstats_mma_kernel<<<dim3(4, 64), 256>>>();
    pv_kernel<<<dim3(4, 64), 256>>>();
    proj_mma_kernel<<<dim3(64, 2), 256>>>(proj_w, proj_g, proj_b, proj_m, proj_v, out);
}

// round 16
// speedup vs baseline: 2.6878x; 1.2539x over previous
#include <cuda_runtime.h>
#include <cstdint>

#define NB 8
#define NH 8
#define NT 1024
#define CD 256
#define KD 16
#define HD 32
#define HQ 512
#define EPS 0.001f
// 0.25 * log2(e) folded into Q so exp(S) == ex2(S')
#define QSCALE 0.36067376022224085f

typedef unsigned long long u64;

__device__ __forceinline__ float ex2f(float x) {
    float y; asm("ex2.approx.f32 %0,%1;" : "=f"(y) : "f"(x)); return y;
}
__device__ __forceinline__ uint32_t tf32r(float x) {
    uint32_t h; asm("cvt.rna.tf32.f32 %0, %1;" : "=r"(h) : "f"(x)); return h;
}
__device__ __forceinline__ void tf32_split(float x, uint32_t& hi, uint32_t& lo) {
    uint32_t h; asm("cvt.rna.tf32.f32 %0, %1;" : "=r"(h) : "f"(x));
    float lf = x - __uint_as_float(h);
    uint32_t l; asm("cvt.rna.tf32.f32 %0, %1;" : "=r"(l) : "f"(lf));
    hi = h; lo = l;
}
// D(16x8) += A(16x8) * B(8x8), tf32 inputs, f32 accum
__device__ __forceinline__ void mma8(float* d, const uint32_t* a, const uint32_t* b) {
    asm volatile(
        "mma.sync.aligned.m16n8k8.row.col.f32.tf32.tf32.f32 "
        "{%0,%1,%2,%3},{%4,%5,%6,%7},{%8,%9},{%0,%1,%2,%3};"
        : "+f"(d[0]), "+f"(d[1]), "+f"(d[2]), "+f"(d[3])
        : "r"(a[0]), "r"(a[1]), "r"(a[2]), "r"(a[3]), "r"(b[0]), "r"(b[1]));
}

// Scratch (static device globals; no allocations allowed)
__device__ float g_Q[NB*NH*NT*KD];     // q * 0.25*log2e, [b][h][n][16]
__device__ float g_Kd[NB*NH*NT*KD];    // [b][h][n][16]
__device__ float g_V[NB*NT*CD];        // NHWC, c = h*32+d
__device__ float g_rinv[NB*NH*NT];     // 1 / sum_m exp(S[n,m])
__device__ float g_mid[NB*NT*CD];      // attn out (scrambled layout)
__device__ float g_pe[NB*NT*CD];       // BN(dwconv(V))

// ---------------------------------------------------------------------------
// Kernel 1: QKV GEMM [8192x256]x[256x512] via SINGLE-tf32 mma, BN, routed.
// Input-side rounding (~2.4e-4 rel) averages through downstream contractions.
// ---------------------------------------------------------------------------
__global__ __launch_bounds__(256) void qkv_mma_kernel(
    const float* __restrict__ X, const float* __restrict__ W,
    const float* __restrict__ gamma, const float* __restrict__ beta,
    const float* __restrict__ mean, const float* __restrict__ var)
{
    __shared__ float xs[128][20];    // A tile [m][k], tf32 bits
    __shared__ float ws[16][136];    // B tile [k][n], tf32 bits

    const int tid = threadIdx.x;
    const int wid = tid >> 5, lane = tid & 31;
    const int r = lane >> 2, c = lane & 3;
    const int wm = wid & 1, wn = wid >> 1;        // 2 m-groups x 4 n-groups
    const int row0 = blockIdx.x * 128;
    const int col0 = blockIdx.y * 128;

    float acc[4][4][4];
    #pragma unroll
    for (int i = 0; i < 4; i++)
        #pragma unroll
        for (int t = 0; t < 4; t++)
            #pragma unroll
            for (int f = 0; f < 4; f++) acc[i][t][f] = 0.f;

    for (int k0 = 0; k0 < CD; k0 += 16) {
        if (k0) __syncthreads();
        {   // X tile 128x16, single tf32
            int row = tid >> 1, kb = (tid & 1) << 3;
            const float* xp = X + (row0 + row) * CD + k0 + kb;
            float4 v0 = *(const float4*)xp, v1 = *(const float4*)(xp + 4);
            float vv[8] = {v0.x, v0.y, v0.z, v0.w, v1.x, v1.y, v1.z, v1.w};
            #pragma unroll
            for (int d = 0; d < 8; d++)
                xs[row][kb + d] = __uint_as_float(tf32r(vv[d]));
        }
        {   // W tile 16x128, single tf32
            int kk = tid >> 4, nb = (tid & 15) << 3;
            const float* wp = W + (k0 + kk) * HQ + col0 + nb;
            float4 v0 = *(const float4*)wp, v1 = *(const float4*)(wp + 4);
            float vv[8] = {v0.x, v0.y, v0.z, v0.w, v1.x, v1.y, v1.z, v1.w};
            #pragma unroll
            for (int d = 0; d < 8; d++)
                ws[kk][nb + d] = __uint_as_float(tf32r(vv[d]));
        }
        __syncthreads();

        #pragma unroll
        for (int s = 0; s < 2; s++) {
            uint32_t ah[4][4];
            #pragma unroll
            for (int i = 0; i < 4; i++) {
                int mb = wm*64 + i*16;
                ah[i][0] = __float_as_uint(xs[mb + r    ][s*8 + c    ]);
                ah[i][1] = __float_as_uint(xs[mb + r + 8][s*8 + c    ]);
                ah[i][2] = __float_as_uint(xs[mb + r    ][s*8 + c + 4]);
                ah[i][3] = __float_as_uint(xs[mb + r + 8][s*8 + c + 4]);
            }
            uint32_t bh_[4][2];
            #pragma unroll
            for (int t = 0; t < 4; t++) {
                int nb = wn*32 + t*8;
                bh_[t][0] = __float_as_uint(ws[s*8 + c    ][nb + r]);
                bh_[t][1] = __float_as_uint(ws[s*8 + c + 4][nb + r]);
            }
            #pragma unroll
            for (int i = 0; i < 4; i++)
                #pragma unroll
                for (int t = 0; t < 4; t++)
                    mma8(acc[i][t], ah[i], bh_[t]);
        }
    }

    // Epilogue: BN + route to g_Q / g_Kd / g_V
    #pragma unroll
    for (int t = 0; t < 4; t++) {
        #pragma unroll
        for (int p = 0; p < 2; p++) {
            int co = col0 + wn*32 + t*8 + 2*c + p;
            float sc = gamma[co] * rsqrtf(var[co] + EPS);
            float bi = beta[co] - mean[co] * sc;
            int h = co >> 6, rr = co & 63;
            #pragma unroll
            for (int i = 0; i < 4; i++) {
                #pragma unroll
                for (int half = 0; half < 2; half++) {
                    float v = acc[i][t][half*2 + p] * sc + bi;
                    int m = row0 + wm*64 + i*16 + r + half*8;
                    int b = m >> 10, n = m & 1023;
                    if (rr < KD)        g_Q [((b*NH + h)*NT + n)*KD + rr]      = v * QSCALE;
                    else if (rr < 2*KD) g_Kd[((b*NH + h)*NT + n)*KD + rr - KD] = v;
                    else                g_V [(b*NT + n)*CD + h*HD + rr - 2*KD] = v;
                }
            }
        }
    }
}

// ---------------------------------------------------------------------------
// Kernel 2: depthwise 3x3 PE conv on V (NHWC, float4 channels) + BN -> g_pe
// (two half-grid launches keep rowstats in the ncu capture slot)
// ---------------------------------------------------------------------------
__global__ __launch_bounds__(256) void pe_kernel(
    const float* __restrict__ pw, const float* __restrict__ gamma,
    const float* __restrict__ beta, const float* __restrict__ mean,
    const float* __restrict__ var, int blk0)
{
    const int idx = (blk0 + blockIdx.x) * 256 + threadIdx.x;   // (b,i,j,c4)
    const int c4 = idx & 63;
    const int j  = (idx >> 6) & 31;
    const int i  = (idx >> 11) & 31;
    const int b  = idx >> 16;
    const int c  = c4 << 2;

    float4 acc = make_float4(0.f, 0.f, 0.f, 0.f);
    #pragma unroll
    for (int kh = 0; kh < 3; kh++) {
        int ii = i + kh - 1;
        if (ii < 0 || ii > 31) continue;
        #pragma unroll
        for (int kw = 0; kw < 3; kw++) {
            int jj = j + kw - 1;
            if (jj < 0 || jj > 31) continue;
            float4 v = *(const float4*)(g_V + (b*NT + ii*32 + jj)*CD + c);
            float4 w = *(const float4*)(pw + (kh*3 + kw)*CD + c);
            acc.x += v.x * w.x; acc.y += v.y * w.y;
            acc.z += v.z * w.z; acc.w += v.w * w.w;
        }
    }
    float4 g = *(const float4*)(gamma + c);
    float4 vr = *(const float4*)(var + c);
    float4 be = *(const float4*)(beta + c);
    float4 mn = *(const float4*)(mean + c);
    float4 o;
    float s;
    s = g.x * rsqrtf(vr.x + EPS); o.x = acc.x * s + (be.x - mn.x * s);
    s = g.y * rsqrtf(vr.y + EPS); o.y = acc.y * s + (be.y - mn.y * s);
    s = g.z * rsqrtf(vr.z + EPS); o.z = acc.z * s + (be.z - mn.z * s);
    s = g.w * rsqrtf(vr.w + EPS); o.w = acc.w * s + (be.w - mn.w * s);
    *(float4*)(g_pe + ((b*NT) + i*32 + j)*CD + c) = o;
}

// ---------------------------------------------------------------------------
// Kernel 3: rinv[n] = 1 / sum_m exp(S[n,m]) via single-tf32 mma.
// 128-n blocks (grid 8x64 = 512) -> ~3.5 CTAs/SM, fixing occ=21%.
// ---------------------------------------------------------------------------
__global__ __launch_bounds__(256) void rowstats_mma_kernel()
{
    __shared__ float khi[64][20];

    const int tid = threadIdx.x;
    const int wid = tid >> 5, lane = tid & 31;
    const int r = lane >> 2, c = lane & 3;
    const int bh = blockIdx.y;
    const int nb0 = blockIdx.x * 128;

    // A-frags: Q rows, single tf32
    uint32_t qh[2][4];
    {
        const float* Qb = g_Q + (bh*NT + nb0 + wid*16)*KD;
        #pragma unroll
        for (int s = 0; s < 2; s++) {
            qh[s][0] = tf32r(Qb[ r     *KD + s*8 + c    ]);
            qh[s][1] = tf32r(Qb[(r + 8)*KD + s*8 + c    ]);
            qh[s][2] = tf32r(Qb[ r     *KD + s*8 + c + 4]);
            qh[s][3] = tf32r(Qb[(r + 8)*KD + s*8 + c + 4]);
        }
    }

    float z0 = 0.f, z1 = 0.f;

    for (int mc = 0; mc < NT; mc += 64) {
        if (mc) __syncthreads();
        {   // stage K chunk 64x16, single tf32
            int m = tid >> 2, kb = (tid & 3) << 2;
            float4 v = *(const float4*)(g_Kd + (bh*NT + mc + m)*KD + kb);
            khi[m][kb + 0] = __uint_as_float(tf32r(v.x));
            khi[m][kb + 1] = __uint_as_float(tf32r(v.y));
            khi[m][kb + 2] = __uint_as_float(tf32r(v.z));
            khi[m][kb + 3] = __uint_as_float(tf32r(v.w));
        }
        __syncthreads();

        #pragma unroll
        for (int t = 0; t < 8; t++) {
            float d4[4] = {0.f, 0.f, 0.f, 0.f};
            #pragma unroll
            for (int s = 0; s < 2; s++) {
                uint32_t bh_[2];
                bh_[0] = __float_as_uint(khi[t*8 + r][s*8 + c    ]);
                bh_[1] = __float_as_uint(khi[t*8 + r][s*8 + c + 4]);
                mma8(d4, qh[s], bh_);
            }
            z0 += ex2f(d4[0]) + ex2f(d4[1]);
            z1 += ex2f(d4[2]) + ex2f(d4[3]);
        }
    }

    z0 += __shfl_xor_sync(0xffffffffu, z0, 1);
    z0 += __shfl_xor_sync(0xffffffffu, z0, 2);
    z1 += __shfl_xor_sync(0xffffffffu, z1, 1);
    z1 += __shfl_xor_sync(0xffffffffu, z1, 2);
    if (c == 0) {
        g_rinv[bh*NT + nb0 + wid*16 + r    ] = 1.0f / z0;
        g_rinv[bh*NT + nb0 + wid*16 + r + 8] = 1.0f / z1;
    }
}

// ---------------------------------------------------------------------------
// Kernel 4: pv via shuffle-transpose, TWO m-tiles per warp (unchanged R13).
// ---------------------------------------------------------------------------
__global__ __launch_bounds__(256) void pv_kernel()
{
    __shared__ float qhi[2][64][20];   // Q hi, tf32 bits
    __shared__ float qlo[2][64][20];   // Q lo
    __shared__ float vsm[2][32][68];   // V' d-major, tf32 bits

    const int tid = threadIdx.x;
    const int wid = tid >> 5, lane = tid & 31;
    const int bh = blockIdx.y;
    const int b = bh >> 3, h = bh & 7;
    const int m0 = blockIdx.x * 256;
    const int r = lane >> 2;
    const int c = lane & 3;
    const int srcA = (lane & ~3) | (c >> 1);
    const int srcB = srcA + 2;
    const bool odd = (c & 1);

    // K fragments for 2 m-tiles (persistent), 3x split
    uint32_t khi_[2][2][4], klo_[2][2][4];
    #pragma unroll
    for (int u = 0; u < 2; u++) {
        const float* Kb = g_Kd + (bh*NT + m0 + wid*32 + u*16)*KD;
        #pragma unroll
        for (int s = 0; s < 2; s++) {
            tf32_split(Kb[ r     *KD + s*8 + c    ], khi_[u][s][0], klo_[u][s][0]);
            tf32_split(Kb[(r + 8)*KD + s*8 + c    ], khi_[u][s][1], klo_[u][s][1]);
            tf32_split(Kb[ r     *KD + s*8 + c + 4], khi_[u][s][2], klo_[u][s][2]);
            tf32_split(Kb[(r + 8)*KD + s*8 + c + 4], khi_[u][s][3], klo_[u][s][3]);
        }
    }

    float acc[2][4][4];
    #pragma unroll
    for (int u = 0; u < 2; u++)
        #pragma unroll
        for (int t = 0; t < 4; t++)
            #pragma unroll
            for (int j = 0; j < 4; j++) acc[u][t][j] = 0.f;

    const int qn = tid >> 2, qj = (tid & 3) << 2;   // Q staging: 4 vals/thread
    const int vn = tid & 63, vdq = tid >> 6;        // V staging: 8 d/thread

    for (int ci = 0; ci < 16; ci++) {
        const int nc = ci << 6;
        const int buf = ci & 1;

        {   // stage Q chunk [64 x 16], pre-split
            float4 q = *(const float4*)(g_Q + (bh*NT + nc + qn)*KD + qj);
            float qq[4] = {q.x, q.y, q.z, q.w};
            #pragma unroll
            for (int d = 0; d < 4; d++) {
                uint32_t hh, ll; tf32_split(qq[d], hh, ll);
                qhi[buf][qn][qj + d] = __uint_as_float(hh);
                qlo[buf][qn][qj + d] = __uint_as_float(ll);
            }
        }
        {   // stage V' chunk d-major [32 d][64 n], scaled by rinv (conflict-free)
            float ri = g_rinv[bh*NT + nc + vn];
            const float* vb = g_V + (b*NT + nc + vn)*CD + h*HD + vdq*8;
            float4 v0 = *(const float4*)(vb);
            float4 v1 = *(const float4*)(vb + 4);
            float vv[8] = {v0.x, v0.y, v0.z, v0.w, v1.x, v1.y, v1.z, v1.w};
            #pragma unroll
            for (int dd = 0; dd < 8; dd++)
                vsm[buf][vdq*8 + dd][vn] = __uint_as_float(tf32r(vv[dd] * ri));
        }
        __syncthreads();

        #pragma unroll
        for (int t = 0; t < 8; t++) {
            // S-mma for both m-tiles; Q B-frags loaded once per s
            float d4[2][4];
            #pragma unroll
            for (int u = 0; u < 2; u++)
                #pragma unroll
                for (int f = 0; f < 4; f++) d4[u][f] = 0.f;
            #pragma unroll
            for (int s = 0; s < 2; s++) {
                uint32_t bhq[2], blq[2];
                bhq[0] = __float_as_uint(qhi[buf][t*8 + r][s*8 + c    ]);
                bhq[1] = __float_as_uint(qhi[buf][t*8 + r][s*8 + c + 4]);
                blq[0] = __float_as_uint(qlo[buf][t*8 + r][s*8 + c    ]);
                blq[1] = __float_as_uint(qlo[buf][t*8 + r][s*8 + c + 4]);
                #pragma unroll
                for (int u = 0; u < 2; u++) {
                    mma8(d4[u], khi_[u][s], bhq);
                    mma8(d4[u], khi_[u][s], blq);
                    mma8(d4[u], klo_[u][s], bhq);
                }
            }

            // V B-frags loaded once, reused by both m-tiles
            uint32_t bb[4][2];
            #pragma unroll
            for (int dt = 0; dt < 4; dt++) {
                bb[dt][0] = __float_as_uint(vsm[buf][dt*8 + r][t*8 + c    ]);
                bb[dt][1] = __float_as_uint(vsm[buf][dt*8 + r][t*8 + c + 4]);
            }

            #pragma unroll
            for (int u = 0; u < 2; u++) {
                float p0 = ex2f(d4[u][0]), p1 = ex2f(d4[u][1]);
                float p2 = ex2f(d4[u][2]), p3 = ex2f(d4[u][3]);

                // D-frag -> A-frag transpose via shuffles
                float x0 = __shfl_sync(0xffffffffu, p0, srcA);
                float x1 = __shfl_sync(0xffffffffu, p1, srcA);
                float x2 = __shfl_sync(0xffffffffu, p2, srcA);
                float x3 = __shfl_sync(0xffffffffu, p3, srcA);
                float y0 = __shfl_sync(0xffffffffu, p0, srcB);
                float y1 = __shfl_sync(0xffffffffu, p1, srcB);
                float y2 = __shfl_sync(0xffffffffu, p2, srcB);
                float y3 = __shfl_sync(0xffffffffu, p3, srcB);
                uint32_t a[4];
                a[0] = tf32r(odd ? x1 : x0);
                a[1] = tf32r(odd ? x3 : x2);
                a[2] = tf32r(odd ? y1 : y0);
                a[3] = tf32r(odd ? y3 : y2);

                #pragma unroll
                for (int dt = 0; dt < 4; dt++)
                    mma8(acc[u][dt], a, bb[dt]);
            }
        }
    }

    // Output: acc[u][t][0]:(m=gm, d=t8+2c) [1]:(gm, d+1) [2]:(gm+8, d) [3]:(gm+8, d+1)
    // Scrambled: mid[b][d][w=4h+(m>>8)][c=m&255]
    #pragma unroll
    for (int u = 0; u < 2; u++) {
        const int gm = m0 + wid*32 + u*16 + r;
        const int wq = (h << 2) + (gm >> 8);
        const int cc0 = gm & 255;
        #pragma unroll
        for (int t = 0; t < 4; t++) {
            int d0 = t*8 + 2*c;
            g_mid[((b*32 + d0    )*32 + wq)*CD + cc0    ] = acc[u][t][0];
            g_mid[((b*32 + d0 + 1)*32 + wq)*CD + cc0    ] = acc[u][t][1];
            g_mid[((b*32 + d0    )*32 + wq)*CD + cc0 + 8] = acc[u][t][2];
            g_mid[((b*32 + d0 + 1)*32 + wq)*CD + cc0 + 8] = acc[u][t][3];
        }
    }
}

// ---------------------------------------------------------------------------
// Kernel 5: Proj GEMM [8192x256]x[256x256] on (mid+pe), A single-tf32,
// W hi/lo split (2 mma per tile-step) + BN -> d_out.
// ---------------------------------------------------------------------------
__global__ __launch_bounds__(256) void proj_mma_kernel(
    const float* __restrict__ W, const float* __restrict__ gamma,
    const float* __restrict__ beta, const float* __restrict__ mean,
    const float* __restrict__ var, float* __restrict__ out)
{
    __shared__ float xs[128][20];
    __shared__ float whi[16][136], wlo[16][136];

    const int tid = threadIdx.x;
    const int wid = tid >> 5, lane = tid & 31;
    const int r = lane >> 2, c = lane & 3;
    const int wm = wid & 1, wn = wid >> 1;
    const int row0 = blockIdx.x * 128;
    const int col0 = blockIdx.y * 128;

    float acc[4][4][4];
    #pragma unroll
    for (int i = 0; i < 4; i++)
        #pragma unroll
        for (int t = 0; t < 4; t++)
            #pragma unroll
            for (int f = 0; f < 4; f++) acc[i][t][f] = 0.f;

    for (int k0 = 0; k0 < CD; k0 += 16) {
        if (k0) __syncthreads();
        {   // A tile = mid + pe, single tf32
            int row = tid >> 1, kb = (tid & 1) << 3;
            const int off = (row0 + row) * CD + k0 + kb;
            float4 v0 = *(const float4*)(g_mid + off);
            float4 v1 = *(const float4*)(g_mid + off + 4);
            float4 p0 = *(const float4*)(g_pe + off);
            float4 p1 = *(const float4*)(g_pe + off + 4);
            float vv[8] = {v0.x + p0.x, v0.y + p0.y, v0.z + p0.z, v0.w + p0.w,
                           v1.x + p1.x, v1.y + p1.y, v1.z + p1.z, v1.w + p1.w};
            #pragma unroll
            for (int d = 0; d < 8; d++)
                xs[row][kb + d] = __uint_as_float(tf32r(vv[d]));
        }
        {   // W tile, hi/lo split (weight side exact)
            int kk = tid >> 4, nb = (tid & 15) << 3;
            const float* wp = W + (k0 + kk) * CD + col0 + nb;
            float4 v0 = *(const float4*)wp, v1 = *(const float4*)(wp + 4);
            float vv[8] = {v0.x, v0.y, v0.z, v0.w, v1.x, v1.y, v1.z, v1.w};
            #pragma unroll
            for (int d = 0; d < 8; d++) {
                uint32_t h, l; tf32_split(vv[d], h, l);
                whi[kk][nb + d] = __uint_as_float(h);
                wlo[kk][nb + d] = __uint_as_float(l);
            }
        }
        __syncthreads();

        #pragma unroll
        for (int s = 0; s < 2; s++) {
            uint32_t ah[4][4];
            #pragma unroll
            for (int i = 0; i < 4; i++) {
                int mb = wm*64 + i*16;
                ah[i][0] = __float_as_uint(xs[mb + r    ][s*8 + c    ]);
                ah[i][1] = __float_as_uint(xs[mb + r + 8][s*8 + c    ]);
                ah[i][2] = __float_as_uint(xs[mb + r    ][s*8 + c + 4]);
                ah[i][3] = __float_as_uint(xs[mb + r + 8][s*8 + c + 4]);
            }
            uint32_t bh_[4][2], bl_[4][2];
            #pragma unroll
            for (int t = 0; t < 4; t++) {
                int nb = wn*32 + t*8;
                bh_[t][0] = __float_as_uint(whi[s*8 + c    ][nb + r]);
                bh_[t][1] = __float_as_uint(whi[s*8 + c + 4][nb + r]);
                bl_[t][0] = __float_as_uint(wlo[s*8 + c    ][nb + r]);
                bl_[t][1] = __float_as_uint(wlo[s*8 + c + 4][nb + r]);
            }
            #pragma unroll
            for (int i = 0; i < 4; i++)
                #pragma unroll
                for (int t = 0; t < 4; t++) {
                    mma8(acc[i][t], ah[i], bh_[t]);
                    mma8(acc[i][t], ah[i], bl_[t]);
                }
        }
    }

    #pragma unroll
    for (int t = 0; t < 4; t++) {
        #pragma unroll
        for (int p = 0; p < 2; p++) {
            int co = col0 + wn*32 + t*8 + 2*c + p;
            float sc = gamma[co] * rsqrtf(var[co] + EPS);
            float bi = beta[co] - mean[co] * sc;
            #pragma unroll
            for (int i = 0; i < 4; i++) {
                #pragma unroll
                for (int half = 0; half < 2; half++) {
                    float v = acc[i][t][half*2 + p] * sc + bi;
                    int m = row0 + wm*64 + i*16 + r + half*8;
                    out[m*CD + co] = v;
                }
            }
        }
    }
}

// ---------------------------------------------------------------------------
extern "C" void kernel_launch(void* const* d_in, const int* in_sizes, int n_in,
                              void* d_out, int out_size)
{
    const float* inputs   = (const float*)d_in[0];
    const float* qkv_w    = (const float*)d_in[1];
    const float* qkv_g    = (const float*)d_in[2];
    const float* qkv_b    = (const float*)d_in[3];
    const float* qkv_m    = (const float*)d_in[4];
    const float* qkv_v    = (const float*)d_in[5];
    const float* pe_w     = (const float*)d_in[6];
    const float* pe_g     = (const float*)d_in[7];
    const float* pe_b     = (const float*)d_in[8];
    const float* pe_m     = (const float*)d_in[9];
    const float* pe_v     = (const float*)d_in[10];
    const float* proj_w   = (const float*)d_in[11];
    const float* proj_g   = (const float*)d_in[12];
    const float* proj_b   = (const float*)d_in[13];
    const float* proj_m   = (const float*)d_in[14];
    const float* proj_v   = (const float*)d_in[15];
    float* out = (float*)d_out;

    qkv_mma_kernel<<<dim3(64, 4), 256>>>(inputs, qkv_w, qkv_g, qkv_b, qkv_m, qkv_v);
    pe_kernel<<<1024, 256>>>(pe_w, pe_g, pe_b, pe_m, pe_v, 0);
    pe_kernel<<<1024, 256>>>(pe_w, pe_g, pe_b, pe_m, pe_v, 1024);
    rowstats_mma_kernel<<<dim3(8, 64), 256>>>();
    pv_kernel<<<dim3(4, 64), 256>>>();
    proj_mma_kernel<<<dim3(64, 2), 256>>>(proj_w, proj_g, proj_b, proj_m, proj_v, out);
}